// round 6
// baseline (speedup 1.0000x reference)
#include <cuda_runtime.h>
#include <cuda_bf16.h>
#include <math.h>
#include <stdint.h>
#include <stddef.h>

#define DHID 768
#define NB   64
#define NLP  1024
#define NLQ  128

// ---------------- scratch (__device__ globals; allocation-free rule) --------
__device__ float g_qbias[NB * NLQ];
// int8 2-digit quantized inputs for projection GEMM
__device__ __align__(16) int8_t g_P1[(size_t)NB * NLP * DHID];
__device__ __align__(16) int8_t g_P0[(size_t)NB * NLP * DHID];
__device__ float g_sP[NB * NLP];
__device__ __align__(16) int8_t g_Q1i[(size_t)NB * NLQ * DHID];
__device__ __align__(16) int8_t g_Q0i[(size_t)NB * NLQ * DHID];
__device__ float g_sQ[NB * NLQ];
__device__ __align__(16) int8_t g_W1[DHID * DHID];   // W^T digits [n][k]
__device__ __align__(16) int8_t g_W0[DHID * DHID];
__device__ float g_sW[DHID];
// bf16 hi/lo tensors consumed by the attention kernel
__device__ __align__(16) __nv_bfloat16 g_Qh[(size_t)NB * NLQ * DHID];
__device__ __align__(16) __nv_bfloat16 g_Ql[(size_t)NB * NLQ * DHID];
__device__ __align__(16) __nv_bfloat16 g_Wph[(size_t)NB * NLP * DHID];
__device__ __align__(16) __nv_bfloat16 g_Wpl[(size_t)NB * NLP * DHID];
__device__ __align__(16) __nv_bfloat16 g_Wqh[(size_t)NB * NLQ * DHID];
__device__ __align__(16) __nv_bfloat16 g_Wql[(size_t)NB * NLQ * DHID];

// ---------------- small asm helpers ----------------------------------------
__device__ __forceinline__ uint32_t smem_u32(const void* p) {
    uint32_t a;
    asm("{ .reg .u64 t; cvta.to.shared.u64 t, %1; cvt.u32.u64 %0, t; }" : "=r"(a) : "l"(p));
    return a;
}
__device__ __forceinline__ void cp16(uint32_t dst, const void* src) {
    asm volatile("cp.async.cg.shared.global [%0], [%1], 16;" :: "r"(dst), "l"(src));
}
#define CP_COMMIT() asm volatile("cp.async.commit_group;" ::: "memory")
#define CP_WAIT1()  asm volatile("cp.async.wait_group 1;" ::: "memory")
#define CP_WAIT0()  asm volatile("cp.async.wait_group 0;" ::: "memory")

__device__ __forceinline__ void ldsm4(uint32_t& r0, uint32_t& r1, uint32_t& r2,
                                      uint32_t& r3, uint32_t a) {
    asm volatile("ldmatrix.sync.aligned.m8n8.x4.shared.b16 {%0,%1,%2,%3}, [%4];"
                 : "=r"(r0), "=r"(r1), "=r"(r2), "=r"(r3) : "r"(a));
}
__device__ __forceinline__ void ldsm4t(uint32_t& r0, uint32_t& r1, uint32_t& r2,
                                       uint32_t& r3, uint32_t a) {
    asm volatile("ldmatrix.sync.aligned.m8n8.x4.trans.shared.b16 {%0,%1,%2,%3}, [%4];"
                 : "=r"(r0), "=r"(r1), "=r"(r2), "=r"(r3) : "r"(a));
}
__device__ __forceinline__ void mma16816(float* c, uint32_t a0, uint32_t a1,
                                         uint32_t a2, uint32_t a3,
                                         uint32_t b0, uint32_t b1) {
    asm volatile("mma.sync.aligned.m16n8k16.row.col.f32.bf16.bf16.f32 "
                 "{%0,%1,%2,%3}, {%4,%5,%6,%7}, {%8,%9}, {%0,%1,%2,%3};"
                 : "+f"(c[0]), "+f"(c[1]), "+f"(c[2]), "+f"(c[3])
                 : "r"(a0), "r"(a1), "r"(a2), "r"(a3), "r"(b0), "r"(b1));
}
__device__ __forceinline__ void mma_s8(int* c, uint32_t a0, uint32_t a1,
                                       uint32_t a2, uint32_t a3,
                                       uint32_t b0, uint32_t b1) {
    asm volatile("mma.sync.aligned.m16n8k32.row.col.s32.s8.s8.s32 "
                 "{%0,%1,%2,%3}, {%4,%5,%6,%7}, {%8,%9}, {%0,%1,%2,%3};"
                 : "+r"(c[0]), "+r"(c[1]), "+r"(c[2]), "+r"(c[3])
                 : "r"(a0), "r"(a1), "r"(a2), "r"(a3), "r"(b0), "r"(b1));
}
__device__ __forceinline__ void split2(float v, __nv_bfloat16& h, __nv_bfloat16& l) {
    h = __float2bfloat16(v);
    l = __float2bfloat16(v - __bfloat162float(h));
}
__device__ __forceinline__ void q2(float x, float inv, int8_t& d1, int8_t& d0) {
    float X = x * inv;
    float d1f = rintf(X * 0.00390625f);          // /256
    int r = __float2int_rn(fmaf(-256.0f, d1f, X));
    if (r > 127) r = 127;
    d1 = (int8_t)(int)d1f;
    d0 = (int8_t)r;
}

// ---------------- mask prep (dtype-sniffing) --------------------------------
__global__ void mask_prep_kernel(const unsigned char* __restrict__ qm, int n) {
    __shared__ int mode;
    if (threadIdx.x == 0) mode = 0;
    __syncthreads();
    for (int i = threadIdx.x; i < n; i += blockDim.x) {
        int r = i & 3;
        unsigned char c = qm[i];
        if (r != 0 && c != 0) {
            if (r == 3 && c == 0x3F) atomicMax(&mode, 2);
            else                     atomicMax(&mode, 1);
        }
    }
    __syncthreads();
    int m = mode;
    for (int i = threadIdx.x; i < n; i += blockDim.x) {
        int v;
        if (m == 2)      v = (((const float*)(const void*)qm)[i] != 0.0f);
        else if (m == 1) v = (qm[i] != 0);
        else             v = (((const int*)(const void*)qm)[i] != 0);
        g_qbias[i] = v ? -1e30f : 0.0f;
    }
}

// ---------------- fp32 -> (hi,lo) bf16 split (question only) ----------------
__global__ void split_kernel(const float4* __restrict__ x,
                             __nv_bfloat162* __restrict__ h,
                             __nv_bfloat162* __restrict__ l, int n4) {
    int i = blockIdx.x * blockDim.x + threadIdx.x;
    if (i >= n4) return;
    float4 v = x[i];
    __nv_bfloat16 h0, h1, h2, h3, l0, l1, l2, l3;
    split2(v.x, h0, l0); split2(v.y, h1, l1);
    split2(v.z, h2, l2); split2(v.w, h3, l3);
    h[i * 2]     = __nv_bfloat162(h0, h1);
    h[i * 2 + 1] = __nv_bfloat162(h2, h3);
    l[i * 2]     = __nv_bfloat162(l0, l1);
    l[i * 2 + 1] = __nv_bfloat162(l2, l3);
}

// ---------------- per-row int8 2-digit quantization -------------------------
// One block (192 threads) per row of 768; each thread handles 4 elements.
__global__ __launch_bounds__(192)
void quant_rows_kernel(const float* __restrict__ X,
                       int8_t* __restrict__ D1, int8_t* __restrict__ D0,
                       float* __restrict__ S) {
    __shared__ float red[6];
    size_t row = blockIdx.x;
    const float* x = X + row * DHID;
    int t = threadIdx.x;
    float4 v = *(const float4*)(x + t * 4);
    float m = fmaxf(fmaxf(fabsf(v.x), fabsf(v.y)), fmaxf(fabsf(v.z), fabsf(v.w)));
#pragma unroll
    for (int o = 16; o; o >>= 1) m = fmaxf(m, __shfl_xor_sync(0xFFFFFFFFu, m, o));
    if ((t & 31) == 0) red[t >> 5] = m;
    __syncthreads();
    float rm = red[0];
#pragma unroll
    for (int i = 1; i < 6; ++i) rm = fmaxf(rm, red[i]);
    rm = fmaxf(rm, 1e-20f);
    float inv = 32512.0f / rm;
    if (t == 0) S[row] = rm * (1.0f / 32512.0f);
    char4 c1, c0;
    int8_t a, b;
    q2(v.x, inv, a, b); c1.x = a; c0.x = b;
    q2(v.y, inv, a, b); c1.y = a; c0.y = b;
    q2(v.z, inv, a, b); c1.z = a; c0.z = b;
    q2(v.w, inv, a, b); c1.w = a; c0.w = b;
    *(char4*)(D1 + row * DHID + t * 4) = c1;
    *(char4*)(D0 + row * DHID + t * 4) = c0;
}

// ---------------- W column quantization: W[k][n] -> digits of W^T[n][k] -----
__global__ __launch_bounds__(256)
void wquant_kernel(const float* __restrict__ W,
                   int8_t* __restrict__ D1, int8_t* __restrict__ D0,
                   float* __restrict__ S) {
    __shared__ float red[8];
    int n = blockIdx.x;
    int t = threadIdx.x;
    float x0 = W[(size_t)t * DHID + n];
    float x1 = W[(size_t)(t + 256) * DHID + n];
    float x2 = W[(size_t)(t + 512) * DHID + n];
    float m = fmaxf(fmaxf(fabsf(x0), fabsf(x1)), fabsf(x2));
#pragma unroll
    for (int o = 16; o; o >>= 1) m = fmaxf(m, __shfl_xor_sync(0xFFFFFFFFu, m, o));
    if ((t & 31) == 0) red[t >> 5] = m;
    __syncthreads();
    float rm = red[0];
#pragma unroll
    for (int i = 1; i < 8; ++i) rm = fmaxf(rm, red[i]);
    rm = fmaxf(rm, 1e-20f);
    float inv = 32512.0f / rm;
    if (t == 0) S[n] = rm * (1.0f / 32512.0f);
    int8_t a, b;
    q2(x0, inv, a, b); D1[(size_t)n * DHID + t]       = a; D0[(size_t)n * DHID + t]       = b;
    q2(x1, inv, a, b); D1[(size_t)n * DHID + t + 256] = a; D0[(size_t)n * DHID + t + 256] = b;
    q2(x2, inv, a, b); D1[(size_t)n * DHID + t + 512] = a; D0[(size_t)n * DHID + t + 512] = b;
}

// ---------------- int8 2-digit projection GEMM ------------------------------
// C = relu(A @ W^T + b) with A,W in 2-digit int8; exact s32/s64 combine.
// CTA tile 128m x 64n, 8 warps (warp 64x16), k-chunks of 64, 3-stage pipeline.
#define I8_GPB    80
#define I8_A1     0
#define I8_A0     10240
#define I8_B1     20480
#define I8_B0     25600
#define I8_STAGE  30720
#define I8_NCH    12
#define I8_SMEM   (3 * I8_STAGE + 512)
#define YP        ((NB * NLP) / 128)          // 512 P row-blocks

__device__ __forceinline__ void load_stage_i8(uint32_t dst, int kc, int tid,
                                              const int8_t* __restrict__ A1,
                                              const int8_t* __restrict__ A0,
                                              const int8_t* __restrict__ B1,
                                              const int8_t* __restrict__ B0) {
#pragma unroll
    for (int i = 0; i < 2; ++i) {
        int idx = tid + i * 256;          // 0..511
        int row = idx >> 2;               // 0..127
        int c   = idx & 3;
        uint32_t d = dst + (uint32_t)(row * I8_GPB + c * 16);
        size_t so = (size_t)row * DHID + kc + c * 16;
        cp16(d + I8_A1, A1 + so);
        cp16(d + I8_A0, A0 + so);
    }
    {
        int row = tid >> 2;               // 0..63
        int c   = tid & 3;
        uint32_t d = dst + (uint32_t)(row * I8_GPB + c * 16);
        size_t so = (size_t)row * DHID + kc + c * 16;
        cp16(d + I8_B1, B1 + so);
        cp16(d + I8_B0, B0 + so);
    }
}

__device__ __forceinline__ float comb3(int a2, int a1, int a0) {
    long long t = ((long long)a2 << 16) + ((long long)a1 << 8) + (long long)a0;
    return (float)t;
}

__global__ __launch_bounds__(256)
void gemm_i8_kernel(const int8_t* __restrict__ P1, const int8_t* __restrict__ P0,
                    const float* __restrict__ sP,
                    const int8_t* __restrict__ Q1, const int8_t* __restrict__ Q0,
                    const float* __restrict__ sQ,
                    const int8_t* __restrict__ W1, const int8_t* __restrict__ W0,
                    const float* __restrict__ sW,
                    const float* __restrict__ bias,
                    __nv_bfloat16* __restrict__ Ph_out, __nv_bfloat16* __restrict__ Pl_out,
                    __nv_bfloat16* __restrict__ Qh_out, __nv_bfloat16* __restrict__ Ql_out) {
    extern __shared__ char smem[];
    uint32_t sb = smem_u32(smem);
    float* bias_s = (float*)(smem + 3 * I8_STAGE);

    const int tid  = threadIdx.x;
    const int w    = tid >> 5;
    const int lane = tid & 31;
    const int wm   = w >> 2;              // 0..1  (m 64-half)
    const int wn   = w & 3;               // 0..3  (n 16-strip)
    const int yb   = blockIdx.y;
    const bool isQ = (yb >= YP);
    const size_t mBase = (size_t)(isQ ? yb - YP : yb) * 128;
    const int    nBase = blockIdx.x * 64;

    if (tid < 64) bias_s[tid] = bias[nBase + tid];

    const int8_t* A1 = (isQ ? Q1 : P1) + mBase * DHID;
    const int8_t* A0 = (isQ ? Q0 : P0) + mBase * DHID;
    const float*  sA = (isQ ? sQ : sP) + mBase;
    const int8_t* B1 = W1 + (size_t)nBase * DHID;
    const int8_t* B0 = W0 + (size_t)nBase * DHID;
    __nv_bfloat16* Ch = isQ ? Qh_out : Ph_out;
    __nv_bfloat16* Cl = isQ ? Ql_out : Pl_out;

    const int j  = lane >> 3;
    const int rj = lane & 7;
    uint32_t aoff[4];
#pragma unroll
    for (int mi = 0; mi < 4; ++mi)
        aoff[mi] = (uint32_t)((wm * 64 + mi * 16 + (j & 1) * 8 + rj) * I8_GPB + (j >> 1) * 16);
    const uint32_t boff = (uint32_t)((wn * 16 + (j >> 1) * 8 + rj) * I8_GPB + (j & 1) * 16);

    int acc2[4][2][4], acc1[4][2][4], acc0[4][2][4];
#pragma unroll
    for (int mi = 0; mi < 4; ++mi)
#pragma unroll
        for (int ni = 0; ni < 2; ++ni)
#pragma unroll
            for (int r = 0; r < 4; ++r) {
                acc2[mi][ni][r] = 0; acc1[mi][ni][r] = 0; acc0[mi][ni][r] = 0;
            }

    load_stage_i8(sb + 0 * I8_STAGE, 0, tid, A1, A0, B1, B0);
    CP_COMMIT();
    load_stage_i8(sb + 1 * I8_STAGE, 64, tid, A1, A0, B1, B0);
    CP_COMMIT();

    for (int t = 0; t < I8_NCH; ++t) {
        if (t + 1 < I8_NCH) CP_WAIT1(); else CP_WAIT0();
        __syncthreads();
        if (t + 2 < I8_NCH) {
            load_stage_i8(sb + (uint32_t)((t + 2) % 3) * I8_STAGE, (t + 2) * 64, tid,
                          A1, A0, B1, B0);
            CP_COMMIT();
        }
        uint32_t st = sb + (uint32_t)(t % 3) * I8_STAGE;
#pragma unroll
        for (int ks = 0; ks < 2; ++ks) {
            uint32_t k2 = (uint32_t)ks * 32;
            uint32_t a1[4][4], a0[4][4];
#pragma unroll
            for (int mi = 0; mi < 4; ++mi)
                ldsm4(a1[mi][0], a1[mi][1], a1[mi][2], a1[mi][3], st + I8_A1 + aoff[mi] + k2);
#pragma unroll
            for (int mi = 0; mi < 4; ++mi)
                ldsm4(a0[mi][0], a0[mi][1], a0[mi][2], a0[mi][3], st + I8_A0 + aoff[mi] + k2);
            uint32_t b1[2][2], b0[2][2];
            {
                uint32_t r0, r1, r2, r3;
                ldsm4(r0, r1, r2, r3, st + I8_B1 + boff + k2);
                b1[0][0] = r0; b1[0][1] = r1; b1[1][0] = r2; b1[1][1] = r3;
                ldsm4(r0, r1, r2, r3, st + I8_B0 + boff + k2);
                b0[0][0] = r0; b0[0][1] = r1; b0[1][0] = r2; b0[1][1] = r3;
            }
#pragma unroll
            for (int mi = 0; mi < 4; ++mi)
#pragma unroll
                for (int ni = 0; ni < 2; ++ni) {
                    mma_s8(acc2[mi][ni], a1[mi][0], a1[mi][1], a1[mi][2], a1[mi][3],
                           b1[ni][0], b1[ni][1]);
                    mma_s8(acc1[mi][ni], a1[mi][0], a1[mi][1], a1[mi][2], a1[mi][3],
                           b0[ni][0], b0[ni][1]);
                    mma_s8(acc1[mi][ni], a0[mi][0], a0[mi][1], a0[mi][2], a0[mi][3],
                           b1[ni][0], b1[ni][1]);
                    mma_s8(acc0[mi][ni], a0[mi][0], a0[mi][1], a0[mi][2], a0[mi][3],
                           b0[ni][0], b0[ni][1]);
                }
        }
    }

    // epilogue: exact int64 combine, scale, bias+relu, split hi/lo bf16
    const int rGrp = lane >> 2;
    const int cGrp = (lane & 3) * 2;
#pragma unroll
    for (int mi = 0; mi < 4; ++mi) {
        int r0 = wm * 64 + mi * 16 + rGrp;
        float sa0 = sA[r0], sa1 = sA[r0 + 8];
        size_t gr0 = mBase + r0;
#pragma unroll
        for (int ni = 0; ni < 2; ++ni) {
            int c0 = wn * 16 + ni * 8 + cGrp;
            float sb0 = sW[nBase + c0], sb1 = sW[nBase + c0 + 1];
            float bb0 = bias_s[c0], bb1 = bias_s[c0 + 1];
            float v0 = fmaxf(comb3(acc2[mi][ni][0], acc1[mi][ni][0], acc0[mi][ni][0]) * sa0 * sb0 + bb0, 0.0f);
            float v1 = fmaxf(comb3(acc2[mi][ni][1], acc1[mi][ni][1], acc0[mi][ni][1]) * sa0 * sb1 + bb1, 0.0f);
            float v2 = fmaxf(comb3(acc2[mi][ni][2], acc1[mi][ni][2], acc0[mi][ni][2]) * sa1 * sb0 + bb0, 0.0f);
            float v3 = fmaxf(comb3(acc2[mi][ni][3], acc1[mi][ni][3], acc0[mi][ni][3]) * sa1 * sb1 + bb1, 0.0f);
            __nv_bfloat16 h0, h1, h2, h3, l0, l1, l2, l3;
            split2(v0, h0, l0); split2(v1, h1, l1);
            split2(v2, h2, l2); split2(v3, h3, l3);
            size_t o0 = gr0 * DHID + nBase + c0;
            size_t o1 = (gr0 + 8) * DHID + nBase + c0;
            *(__nv_bfloat162*)(Ch + o0) = __nv_bfloat162(h0, h1);
            *(__nv_bfloat162*)(Cl + o0) = __nv_bfloat162(l0, l1);
            *(__nv_bfloat162*)(Ch + o1) = __nv_bfloat162(h2, h3);
            *(__nv_bfloat162*)(Cl + o1) = __nv_bfloat162(l2, l3);
        }
    }
}

// ---------------- common bf16 tiling constants (attention) ------------------
#define GP_B      80
#define ARR_B     (128 * GP_B)
#define O_AH      0
#define O_AL      (1 * ARR_B)
#define O_BH      (2 * ARR_B)
#define O_BL      (3 * ARR_B)
#define STAGE_B   (4 * ARR_B)         // 40960
#define NCHUNK    (DHID / 32)         // 24

__device__ __forceinline__ void load_stage(uint32_t dst, int kc, int tid,
                                           const __nv_bfloat16* __restrict__ A_h,
                                           const __nv_bfloat16* __restrict__ A_l,
                                           const __nv_bfloat16* __restrict__ B_h,
                                           const __nv_bfloat16* __restrict__ B_l) {
#pragma unroll
    for (int i = 0; i < 2; ++i) {
        int idx = tid + i * 256;
        int row = idx >> 2;
        int c   = idx & 3;
        uint32_t d = dst + (uint32_t)(row * GP_B + c * 16);
        size_t so = (size_t)row * DHID + kc + c * 8;
        cp16(d + O_AH, A_h + so);
        cp16(d + O_AL, A_l + so);
        cp16(d + O_BH, B_h + so);
        cp16(d + O_BL, B_l + so);
    }
}

__device__ __forceinline__ void mma_chunk(uint32_t st, const uint32_t* aoff,
                                          const uint32_t* boff, float acc[4][4][4]) {
#pragma unroll
    for (int ks = 0; ks < 2; ++ks) {
        uint32_t k2 = (uint32_t)ks * 32;
        uint32_t ah[4][4], al[4][4], bh[4][2], bl[4][2];
#pragma unroll
        for (int mi = 0; mi < 4; ++mi)
            ldsm4(ah[mi][0], ah[mi][1], ah[mi][2], ah[mi][3], st + O_AH + aoff[mi] + k2);
#pragma unroll
        for (int mi = 0; mi < 4; ++mi)
            ldsm4(al[mi][0], al[mi][1], al[mi][2], al[mi][3], st + O_AL + aoff[mi] + k2);
#pragma unroll
        for (int p = 0; p < 2; ++p) {
            uint32_t r0, r1, r2, r3;
            ldsm4(r0, r1, r2, r3, st + O_BH + boff[p] + k2);
            bh[p * 2][0] = r0; bh[p * 2][1] = r1;
            bh[p * 2 + 1][0] = r2; bh[p * 2 + 1][1] = r3;
            ldsm4(r0, r1, r2, r3, st + O_BL + boff[p] + k2);
            bl[p * 2][0] = r0; bl[p * 2][1] = r1;
            bl[p * 2 + 1][0] = r2; bl[p * 2 + 1][1] = r3;
        }
#pragma unroll
        for (int mi = 0; mi < 4; ++mi)
#pragma unroll
            for (int ni = 0; ni < 4; ++ni) {
                mma16816(acc[mi][ni], ah[mi][0], ah[mi][1], ah[mi][2], ah[mi][3],
                         bh[ni][0], bh[ni][1]);
                mma16816(acc[mi][ni], al[mi][0], al[mi][1], al[mi][2], al[mi][3],
                         bh[ni][0], bh[ni][1]);
                mma16816(acc[mi][ni], ah[mi][0], ah[mi][1], ah[mi][2], ah[mi][3],
                         bl[ni][0], bl[ni][1]);
            }
    }
}

// ---------------- tensor-core fused attention --------------------------------
#define SCP      132
#define SC_OFF   0
#define ST_OFF   67584
#define AH_OFF   67584
#define AL_OFF   102400
#define AP_B     272
#define QT_OFF   137216
#define QSTG_B   36864
#define QP_B     144
#define QB_OFF   210944
#define ASMEM    211456

__global__ __launch_bounds__(256)
void attn_tc_kernel(const __nv_bfloat16* __restrict__ Wph,
                    const __nv_bfloat16* __restrict__ Wpl,
                    const __nv_bfloat16* __restrict__ Wqh,
                    const __nv_bfloat16* __restrict__ Wql,
                    const __nv_bfloat16* __restrict__ Qh,
                    const __nv_bfloat16* __restrict__ Ql,
                    float* __restrict__ out) {
    extern __shared__ char smem[];
    uint32_t sb = smem_u32(smem);
    float* sc = (float*)(smem + SC_OFF);
    float* qb = (float*)(smem + QB_OFF);

    const int tid  = threadIdx.x;
    const int w    = tid >> 5;
    const int lane = tid & 31;
    const int wm   = w >> 2;
    const int wn   = w & 3;
    const int b    = blockIdx.y;
    const int pBase = blockIdx.x * 128;

    if (tid < 128) qb[tid] = g_qbias[b * NLQ + tid];

    const __nv_bfloat16* A_h = Wph + ((size_t)b * NLP + pBase) * DHID;
    const __nv_bfloat16* A_l = Wpl + ((size_t)b * NLP + pBase) * DHID;
    const __nv_bfloat16* B_h = Wqh + (size_t)b * NLQ * DHID;
    const __nv_bfloat16* B_l = Wql + (size_t)b * NLQ * DHID;
    const __nv_bfloat16* Q_h = Qh + (size_t)b * NLQ * DHID;
    const __nv_bfloat16* Q_l = Ql + (size_t)b * NLQ * DHID;

    const int j  = lane >> 3;
    const int rj = lane & 7;

    // ---- phase 1: scores = Wp @ Wq^T (split-bf16) ----
    {
        uint32_t aoff[4], boff[2];
#pragma unroll
        for (int mi = 0; mi < 4; ++mi)
            aoff[mi] = (uint32_t)((wm * 64 + mi * 16 + (j & 1) * 8 + rj) * GP_B + (j >> 1) * 16);
#pragma unroll
        for (int p = 0; p < 2; ++p)
            boff[p] = (uint32_t)((wn * 32 + p * 16 + (j >> 1) * 8 + rj) * GP_B + (j & 1) * 16);

        float acc[4][4][4];
#pragma unroll
        for (int mi = 0; mi < 4; ++mi)
#pragma unroll
            for (int ni = 0; ni < 4; ++ni)
#pragma unroll
                for (int r = 0; r < 4; ++r) acc[mi][ni][r] = 0.0f;

        load_stage(sb + ST_OFF + 0 * STAGE_B, 0, tid, A_h, A_l, B_h, B_l);
        CP_COMMIT();
        load_stage(sb + ST_OFF + 1 * STAGE_B, 32, tid, A_h, A_l, B_h, B_l);
        CP_COMMIT();

        for (int t = 0; t < NCHUNK; ++t) {
            if (t + 1 < NCHUNK) CP_WAIT1(); else CP_WAIT0();
            __syncthreads();
            if (t + 2 < NCHUNK) {
                load_stage(sb + ST_OFF + (uint32_t)((t + 2) % 3) * STAGE_B,
                           (t + 2) * 32, tid, A_h, A_l, B_h, B_l);
                CP_COMMIT();
            }
            mma_chunk(sb + ST_OFF + (uint32_t)(t % 3) * STAGE_B, aoff, boff, acc);
        }
        __syncthreads();

        const int rGrp = lane >> 2;
        const int cGrp = (lane & 3) * 2;
#pragma unroll
        for (int mi = 0; mi < 4; ++mi) {
            int pr = wm * 64 + mi * 16 + rGrp;
#pragma unroll
            for (int ni = 0; ni < 4; ++ni) {
                int q0 = wn * 32 + ni * 8 + cGrp;
                float b0 = qb[q0], b1 = qb[q0 + 1];
                sc[pr * SCP + q0]           = acc[mi][ni][0] + b0;
                sc[pr * SCP + q0 + 1]       = acc[mi][ni][1] + b1;
                sc[(pr + 8) * SCP + q0]     = acc[mi][ni][2] + b0;
                sc[(pr + 8) * SCP + q0 + 1] = acc[mi][ni][3] + b1;
            }
        }
    }
    __syncthreads();

    // prefetch first Q tile while softmax runs
    {
#pragma unroll
        for (int i = 0; i < 4; ++i) {
            int idx = tid + i * 256;
            int row = idx >> 3;
            int c   = idx & 7;
            uint32_t d = sb + QT_OFF + (uint32_t)(row * QP_B + c * 16);
            size_t so = (size_t)row * DHID + c * 8;
            cp16(d, Q_h + so);
            cp16(d + 18432, Q_l + so);
        }
        CP_COMMIT();
    }

    // ---- phase 2: softmax per p-row ----
    if (tid < 128) {
        float* row = sc + tid * SCP;
        float mx = -INFINITY;
#pragma unroll 8
        for (int c = 0; c < 128; ++c) mx = fmaxf(mx, row[c]);
        float s = 0.0f;
#pragma unroll 8
        for (int c = 0; c < 128; ++c) {
            float e = __expf(row[c] - mx);
            row[c] = e;
            s += e;
        }
        float inv = 1.0f / s;
#pragma unroll 8
        for (int c = 0; c < 128; ++c) row[c] *= inv;
    }
    __syncthreads();

    // alpha -> bf16 hi/lo (smem)
    {
        for (int i = tid; i < 128 * 32; i += 256) {
            int p  = i >> 5;
            int q4 = (i & 31) * 4;
            float4 v = *(float4*)&sc[p * SCP + q4];
            __nv_bfloat16 h0, h1, h2, h3, l0, l1, l2, l3;
            split2(v.x, h0, l0); split2(v.y, h1, l1);
            split2(v.z, h2, l2); split2(v.w, h3, l3);
            __nv_bfloat162* ph = (__nv_bfloat162*)(smem + AH_OFF + p * AP_B + q4 * 2);
            __nv_bfloat162* pl = (__nv_bfloat162*)(smem + AL_OFF + p * AP_B + q4 * 2);
            ph[0] = __nv_bfloat162(h0, h1); ph[1] = __nv_bfloat162(h2, h3);
            pl[0] = __nv_bfloat162(l0, l1); pl[1] = __nv_bfloat162(l2, l3);
        }
    }
    __syncthreads();

    // ---- phase 3: out = alpha @ question ----
    {
        uint32_t aoff3[4];
#pragma unroll
        for (int mi = 0; mi < 4; ++mi)
            aoff3[mi] = (uint32_t)((wm * 64 + mi * 16 + (j & 1) * 8 + rj) * AP_B + (j >> 1) * 16);
        uint32_t boffq = (uint32_t)(((j & 1) * 8 + rj) * QP_B + wn * 32 + (j >> 1) * 16);

        for (int dc = 0; dc < 12; ++dc) {
            uint32_t qs = sb + QT_OFF + (uint32_t)(dc & 1) * QSTG_B;
            if (dc + 1 < 12) {
                uint32_t nq = sb + QT_OFF + (uint32_t)((dc + 1) & 1) * QSTG_B;
                int koff = (dc + 1) * 64;
#pragma unroll
                for (int i = 0; i < 4; ++i) {
                    int idx = tid + i * 256;
                    int row = idx >> 3;
                    int c   = idx & 7;
                    uint32_t d = nq + (uint32_t)(row * QP_B + c * 16);
                    size_t so = (size_t)row * DHID + koff + c * 8;
                    cp16(d, Q_h + so);
                    cp16(d + 18432, Q_l + so);
                }
                CP_COMMIT();
                CP_WAIT1();
            } else {
                CP_WAIT0();
            }
            __syncthreads();

            float acc[4][2][4];
#pragma unroll
            for (int mi = 0; mi < 4; ++mi)
#pragma unroll
                for (int ni = 0; ni < 2; ++ni)
#pragma unroll
                    for (int r = 0; r < 4; ++r) acc[mi][ni][r] = 0.0f;

#pragma unroll
            for (int ks = 0; ks < 8; ++ks) {
                uint32_t ka = (uint32_t)ks * 32;
                uint32_t kq = (uint32_t)ks * 16 * QP_B;
                uint32_t ah[4][4], al[4][4];
#pragma unroll
                for (int mi = 0; mi < 4; ++mi)
                    ldsm4(ah[mi][0], ah[mi][1], ah[mi][2], ah[mi][3],
                          sb + AH_OFF + aoff3[mi] + ka);
#pragma unroll
                for (int mi = 0; mi < 4; ++mi)
                    ldsm4(al[mi][0], al[mi][1], al[mi][2], al[mi][3],
                          sb + AL_OFF + aoff3[mi] + ka);
                uint32_t bh[2][2], bl[2][2];
                {
                    uint32_t r0, r1, r2, r3;
                    ldsm4t(r0, r1, r2, r3, qs + boffq + kq);
                    bh[0][0] = r0; bh[0][1] = r1; bh[1][0] = r2; bh[1][1] = r3;
                    ldsm4t(r0, r1, r2, r3, qs + 18432 + boffq + kq);
                    bl[0][0] = r0; bl[0][1] = r1; bl[1][0] = r2; bl[1][1] = r3;
                }
#pragma unroll
                for (int mi = 0; mi < 4; ++mi)
#pragma unroll
                    for (int ni = 0; ni < 2; ++ni) {
                        mma16816(acc[mi][ni], ah[mi][0], ah[mi][1], ah[mi][2], ah[mi][3],
                                 bh[ni][0], bh[ni][1]);
                        mma16816(acc[mi][ni], al[mi][0], al[mi][1], al[mi][2], al[mi][3],
                                 bh[ni][0], bh[ni][1]);
                        mma16816(acc[mi][ni], ah[mi][0], ah[mi][1], ah[mi][2], ah[mi][3],
                                 bl[ni][0], bl[ni][1]);
                    }
            }

            const int rGrp = lane >> 2;
            const int cGrp = (lane & 3) * 2;
#pragma unroll
            for (int mi = 0; mi < 4; ++mi) {
                size_t gr = (size_t)b * NLP + pBase + wm * 64 + mi * 16 + rGrp;
#pragma unroll
                for (int ni = 0; ni < 2; ++ni) {
                    int d = dc * 64 + wn * 16 + ni * 8 + cGrp;
                    float2 v0 = {acc[mi][ni][0], acc[mi][ni][1]};
                    float2 v1 = {acc[mi][ni][2], acc[mi][ni][3]};
                    *(float2*)(out + gr * DHID + d)       = v0;
                    *(float2*)(out + (gr + 8) * DHID + d) = v1;
                }
            }
            __syncthreads();
        }
    }
}

// ---------------------------------------------------------------------------
extern "C" void kernel_launch(void* const* d_in, const int* in_sizes, int n_in,
                              void* d_out, int out_size) {
    const float* passage  = (const float*)d_in[0];
    const float* question = (const float*)d_in[2];
    const unsigned char* qmask = (const unsigned char*)d_in[3];
    const float* Ww = (const float*)d_in[4];
    const float* Wb = (const float*)d_in[5];
    float* out = (float*)d_out;

    int8_t *p1, *p0, *q1, *q0, *w1, *w0;
    float *sp, *sq, *sw;
    __nv_bfloat16 *qh, *ql, *wph, *wpl, *wqh, *wql;
    cudaGetSymbolAddress((void**)&p1, g_P1);
    cudaGetSymbolAddress((void**)&p0, g_P0);
    cudaGetSymbolAddress((void**)&sp, g_sP);
    cudaGetSymbolAddress((void**)&q1, g_Q1i);
    cudaGetSymbolAddress((void**)&q0, g_Q0i);
    cudaGetSymbolAddress((void**)&sq, g_sQ);
    cudaGetSymbolAddress((void**)&w1, g_W1);
    cudaGetSymbolAddress((void**)&w0, g_W0);
    cudaGetSymbolAddress((void**)&sw, g_sW);
    cudaGetSymbolAddress((void**)&qh, g_Qh);
    cudaGetSymbolAddress((void**)&ql, g_Ql);
    cudaGetSymbolAddress((void**)&wph, g_Wph);
    cudaGetSymbolAddress((void**)&wpl, g_Wpl);
    cudaGetSymbolAddress((void**)&wqh, g_Wqh);
    cudaGetSymbolAddress((void**)&wql, g_Wql);

    mask_prep_kernel<<<1, 256>>>(qmask, NB * NLQ);

    int nq4 = NB * NLQ * DHID / 4;
    split_kernel<<<(nq4 + 255) / 256, 256>>>((const float4*)question,
                                             (__nv_bfloat162*)qh, (__nv_bfloat162*)ql, nq4);

    quant_rows_kernel<<<NB * NLP, 192>>>(passage, p1, p0, sp);
    quant_rows_kernel<<<NB * NLQ, 192>>>(question, q1, q0, sq);
    wquant_kernel<<<DHID, 256>>>(Ww, w1, w0, sw);

    cudaFuncSetAttribute(gemm_i8_kernel, cudaFuncAttributeMaxDynamicSharedMemorySize, I8_SMEM);
    gemm_i8_kernel<<<dim3(DHID / 64, YP + (NB * NLQ) / 128), 256, I8_SMEM>>>(
        p1, p0, sp, q1, q0, sq, w1, w0, sw, Wb, wph, wpl, wqh, wql);

    cudaFuncSetAttribute(attn_tc_kernel, cudaFuncAttributeMaxDynamicSharedMemorySize, ASMEM);
    attn_tc_kernel<<<dim3(NLP / 128, NB), 256, ASMEM>>>(wph, wpl, wqh, wql, qh, ql, out);
}

// round 7
// speedup vs baseline: 1.6887x; 1.6887x over previous
#include <cuda_runtime.h>
#include <cuda_bf16.h>
#include <math.h>
#include <stdint.h>
#include <stddef.h>

#define DHID 768
#define NB   64
#define NLP  1024
#define NLQ  128
#define PROWS (NB * NLP)

// ---------------- scratch (__device__ globals; allocation-free rule) --------
__device__ float g_qbias[NB * NLQ];
__device__ __align__(16) __nv_bfloat16 g_Ph[(size_t)NB * NLP * DHID];
__device__ __align__(16) __nv_bfloat16 g_Pl[(size_t)NB * NLP * DHID];
__device__ __align__(16) __nv_bfloat16 g_Qh[(size_t)NB * NLQ * DHID];
__device__ __align__(16) __nv_bfloat16 g_Ql[(size_t)NB * NLQ * DHID];
__device__ __align__(16) __nv_bfloat16 g_Wth[DHID * DHID];   // W^T hi [n][k]
__device__ __align__(16) __nv_bfloat16 g_Wtl[DHID * DHID];   // W^T lo [n][k]
__device__ __align__(16) __nv_bfloat16 g_Wph[(size_t)NB * NLP * DHID];
__device__ __align__(16) __nv_bfloat16 g_Wpl[(size_t)NB * NLP * DHID];
__device__ __align__(16) __nv_bfloat16 g_Wqh[(size_t)NB * NLQ * DHID];
__device__ __align__(16) __nv_bfloat16 g_Wql[(size_t)NB * NLQ * DHID];

// ---------------- small asm helpers ----------------------------------------
__device__ __forceinline__ uint32_t smem_u32(const void* p) {
    uint32_t a;
    asm("{ .reg .u64 t; cvta.to.shared.u64 t, %1; cvt.u32.u64 %0, t; }" : "=r"(a) : "l"(p));
    return a;
}
__device__ __forceinline__ void cp16(uint32_t dst, const void* src) {
    asm volatile("cp.async.cg.shared.global [%0], [%1], 16;" :: "r"(dst), "l"(src));
}
__device__ __forceinline__ void cp4(uint32_t dst, const void* src) {
    asm volatile("cp.async.ca.shared.global [%0], [%1], 4;" :: "r"(dst), "l"(src));
}
#define CP_COMMIT() asm volatile("cp.async.commit_group;" ::: "memory")
#define CP_WAIT1()  asm volatile("cp.async.wait_group 1;" ::: "memory")
#define CP_WAIT0()  asm volatile("cp.async.wait_group 0;" ::: "memory")

__device__ __forceinline__ void ldsm4(uint32_t& r0, uint32_t& r1, uint32_t& r2,
                                      uint32_t& r3, uint32_t a) {
    asm volatile("ldmatrix.sync.aligned.m8n8.x4.shared.b16 {%0,%1,%2,%3}, [%4];"
                 : "=r"(r0), "=r"(r1), "=r"(r2), "=r"(r3) : "r"(a));
}
__device__ __forceinline__ void ldsm4t(uint32_t& r0, uint32_t& r1, uint32_t& r2,
                                       uint32_t& r3, uint32_t a) {
    asm volatile("ldmatrix.sync.aligned.m8n8.x4.trans.shared.b16 {%0,%1,%2,%3}, [%4];"
                 : "=r"(r0), "=r"(r1), "=r"(r2), "=r"(r3) : "r"(a));
}
__device__ __forceinline__ void mma16816(float* c, uint32_t a0, uint32_t a1,
                                         uint32_t a2, uint32_t a3,
                                         uint32_t b0, uint32_t b1) {
    asm volatile("mma.sync.aligned.m16n8k16.row.col.f32.bf16.bf16.f32 "
                 "{%0,%1,%2,%3}, {%4,%5,%6,%7}, {%8,%9}, {%0,%1,%2,%3};"
                 : "+f"(c[0]), "+f"(c[1]), "+f"(c[2]), "+f"(c[3])
                 : "r"(a0), "r"(a1), "r"(a2), "r"(a3), "r"(b0), "r"(b1));
}
__device__ __forceinline__ void split2(float v, __nv_bfloat16& h, __nv_bfloat16& l) {
    h = __float2bfloat16(v);
    l = __float2bfloat16(v - __bfloat162float(h));
}

// ---------------- mask prep (dtype-sniffing) --------------------------------
__global__ void mask_prep_kernel(const unsigned char* __restrict__ qm, int n) {
    __shared__ int mode;
    if (threadIdx.x == 0) mode = 0;
    __syncthreads();
    for (int i = threadIdx.x; i < n; i += blockDim.x) {
        int r = i & 3;
        unsigned char c = qm[i];
        if (r != 0 && c != 0) {
            if (r == 3 && c == 0x3F) atomicMax(&mode, 2);
            else                     atomicMax(&mode, 1);
        }
    }
    __syncthreads();
    int m = mode;
    for (int i = threadIdx.x; i < n; i += blockDim.x) {
        int v;
        if (m == 2)      v = (((const float*)(const void*)qm)[i] != 0.0f);
        else if (m == 1) v = (qm[i] != 0);
        else             v = (((const int*)(const void*)qm)[i] != 0);
        g_qbias[i] = v ? -1e30f : 0.0f;
    }
}

// ---------------- fp32 -> (hi,lo) bf16 split --------------------------------
__global__ void split_kernel(const float4* __restrict__ x,
                             __nv_bfloat162* __restrict__ h,
                             __nv_bfloat162* __restrict__ l, int n4) {
    int i = blockIdx.x * blockDim.x + threadIdx.x;
    if (i >= n4) return;
    float4 v = x[i];
    __nv_bfloat16 h0, h1, h2, h3, l0, l1, l2, l3;
    split2(v.x, h0, l0); split2(v.y, h1, l1);
    split2(v.z, h2, l2); split2(v.w, h3, l3);
    h[i * 2]     = __nv_bfloat162(h0, h1);
    h[i * 2 + 1] = __nv_bfloat162(h2, h3);
    l[i * 2]     = __nv_bfloat162(l0, l1);
    l[i * 2 + 1] = __nv_bfloat162(l2, l3);
}

// ---------------- W[k][n] -> W^T split (hi/lo) ------------------------------
__global__ void wsplit_kernel(const float* __restrict__ W,
                              __nv_bfloat16* __restrict__ Wth,
                              __nv_bfloat16* __restrict__ Wtl) {
    __shared__ float t[32][33];
    int bx = blockIdx.x * 32;  // k
    int by = blockIdx.y * 32;  // n
    for (int yy = threadIdx.y; yy < 32; yy += 8)
        t[yy][threadIdx.x] = W[(size_t)(bx + yy) * DHID + by + threadIdx.x];
    __syncthreads();
    for (int yy = threadIdx.y; yy < 32; yy += 8) {
        float v = t[threadIdx.x][yy];
        __nv_bfloat16 h, l;
        split2(v, h, l);
        size_t o = (size_t)(by + yy) * DHID + bx + threadIdx.x;
        Wth[o] = h;
        Wtl[o] = l;
    }
}

// ---------------- common tiling constants -----------------------------------
#define GP_B      80
#define ARR_B     (128 * GP_B)
#define O_AH      0
#define O_AL      (1 * ARR_B)
#define O_BH      (2 * ARR_B)
#define O_BL      (3 * ARR_B)
#define STAGE_B   (4 * ARR_B)         // 40960 (bf16 arrays)
#define NCHUNK    (DHID / 32)         // 24

// 3-product split-bf16 mainloop chunk (2 k16 steps), accumulate into acc[4][4][4]
__device__ __forceinline__ void mma_chunk(uint32_t st, const uint32_t* aoff,
                                          const uint32_t* boff, float acc[4][4][4]) {
#pragma unroll
    for (int ks = 0; ks < 2; ++ks) {
        uint32_t k2 = (uint32_t)ks * 32;
        uint32_t ah[4][4], al[4][4], bh[4][2], bl[4][2];
#pragma unroll
        for (int mi = 0; mi < 4; ++mi)
            ldsm4(ah[mi][0], ah[mi][1], ah[mi][2], ah[mi][3], st + O_AH + aoff[mi] + k2);
#pragma unroll
        for (int mi = 0; mi < 4; ++mi)
            ldsm4(al[mi][0], al[mi][1], al[mi][2], al[mi][3], st + O_AL + aoff[mi] + k2);
#pragma unroll
        for (int p = 0; p < 2; ++p) {
            uint32_t r0, r1, r2, r3;
            ldsm4(r0, r1, r2, r3, st + O_BH + boff[p] + k2);
            bh[p * 2][0] = r0; bh[p * 2][1] = r1;
            bh[p * 2 + 1][0] = r2; bh[p * 2 + 1][1] = r3;
            ldsm4(r0, r1, r2, r3, st + O_BL + boff[p] + k2);
            bl[p * 2][0] = r0; bl[p * 2][1] = r1;
            bl[p * 2 + 1][0] = r2; bl[p * 2 + 1][1] = r3;
        }
#pragma unroll
        for (int mi = 0; mi < 4; ++mi)
#pragma unroll
            for (int ni = 0; ni < 4; ++ni) {
                mma16816(acc[mi][ni], ah[mi][0], ah[mi][1], ah[mi][2], ah[mi][3],
                         bh[ni][0], bh[ni][1]);
                mma16816(acc[mi][ni], al[mi][0], al[mi][1], al[mi][2], al[mi][3],
                         bh[ni][0], bh[ni][1]);
                mma16816(acc[mi][ni], ah[mi][0], ah[mi][1], ah[mi][2], ah[mi][3],
                         bl[ni][0], bl[ni][1]);
            }
    }
}

// ---------------- hybrid projection GEMM (HMMA 128 rows + fp32 32 rows) -----
#define HYB_F     32                  // fp32 rows per P block
#define HYB_ROWS  (128 + HYB_F)       // 160
#define YPH       ((PROWS + HYB_ROWS - 1) / HYB_ROWS)   // 410
#define HS_W32    40960               // fp32 W tile [32][132] floats
#define HS_A32    57856               // fp32 A tile [k][row]: pitch 36 floats
#define HSTAGE    62464               // 40960 + 16896 + 4608
#define HSMEM     (3 * HSTAGE + 512)

__device__ __forceinline__ void load_stage_hyb(
    uint32_t dst, int kc, int tid, int aclamp,
    const __nv_bfloat16* __restrict__ A_h, const __nv_bfloat16* __restrict__ A_l,
    const __nv_bfloat16* __restrict__ B_h, const __nv_bfloat16* __restrict__ B_l,
    const float* __restrict__ Wf, const float* __restrict__ Af, int a32max, bool hyb) {
    for (int idx = tid; idx < 512; idx += 384) {
        int row = idx >> 2, c = idx & 3;
        uint32_t d = dst + (uint32_t)(row * GP_B + c * 16);
        int rr = row < aclamp ? row : aclamp;
        size_t soA = (size_t)rr * DHID + kc + c * 8;
        size_t soB = (size_t)row * DHID + kc + c * 8;
        cp16(d + O_AH, A_h + soA);
        cp16(d + O_AL, A_l + soA);
        cp16(d + O_BH, B_h + soB);
        cp16(d + O_BL, B_l + soB);
    }
    if (hyb) {
        for (int idx = tid; idx < 1024; idx += 384) {   // W32: 32 k-rows x 128 cols
            int kr = idx >> 5, c = idx & 31;
            cp16(dst + HS_W32 + (uint32_t)(kr * 528 + c * 16),
                 Wf + (size_t)(kc + kr) * DHID + c * 4);
        }
        for (int idx = tid; idx < 1024; idx += 384) {   // A32 transposed: [k][row]
            int kr = idx >> 5, row = idx & 31;
            int rr = row < a32max ? row : a32max;
            cp4(dst + HS_A32 + (uint32_t)(kr * 144 + row * 4),
                Af + (size_t)rr * DHID + kc + kr);
        }
    }
}

__device__ __forceinline__ void fp32_chunk(const char* sp, int t2, float facc[4][8]) {
    const float* Bs = (const float*)(sp + HS_W32);
    const float* As = (const float*)(sp + HS_A32);
    const int tx = t2 & 15, ty = t2 >> 4;
#pragma unroll 4
    for (int k = 0; k < 32; ++k) {
        float4 av = *(const float4*)(As + k * 36 + ty * 4);
        float4 b0 = *(const float4*)(Bs + k * 132 + tx * 8);
        float4 b1 = *(const float4*)(Bs + k * 132 + tx * 8 + 4);
        float a[4] = {av.x, av.y, av.z, av.w};
        float bv[8] = {b0.x, b0.y, b0.z, b0.w, b1.x, b1.y, b1.z, b1.w};
#pragma unroll
        for (int i = 0; i < 4; ++i)
#pragma unroll
            for (int jj = 0; jj < 8; ++jj)
                facc[i][jj] = fmaf(a[i], bv[jj], facc[i][jj]);
    }
}

__global__ __launch_bounds__(384)
void gemm_hyb_kernel(const __nv_bfloat16* __restrict__ Ph, const __nv_bfloat16* __restrict__ Pl,
                     const __nv_bfloat16* __restrict__ Qh, const __nv_bfloat16* __restrict__ Ql,
                     const __nv_bfloat16* __restrict__ Bh, const __nv_bfloat16* __restrict__ Bl,
                     const float* __restrict__ Pf,   // passage fp32
                     const float* __restrict__ Wf,   // W fp32 [k][n]
                     const float* __restrict__ bias,
                     __nv_bfloat16* __restrict__ Ph_out, __nv_bfloat16* __restrict__ Pl_out,
                     __nv_bfloat16* __restrict__ Qh_out, __nv_bfloat16* __restrict__ Ql_out) {
    extern __shared__ char smem[];
    uint32_t sb = smem_u32(smem);
    float* bias_s = (float*)(smem + 3 * HSTAGE);

    const int tid  = threadIdx.x;
    const int w    = tid >> 5;
    const int lane = tid & 31;
    const int yb   = blockIdx.y;
    const int nBase = blockIdx.x * 128;
    const bool hyb = (yb < YPH);

    const size_t mBase = hyb ? (size_t)yb * HYB_ROWS : (size_t)(yb - YPH) * 128;
    const __nv_bfloat16* A_h = (hyb ? Ph : Qh) + mBase * DHID;
    const __nv_bfloat16* A_l = (hyb ? Pl : Ql) + mBase * DHID;
    const __nv_bfloat16* B_h = Bh + (size_t)nBase * DHID;
    const __nv_bfloat16* B_l = Bl + (size_t)nBase * DHID;
    __nv_bfloat16* Ch = hyb ? Ph_out : Qh_out;
    __nv_bfloat16* Cl = hyb ? Pl_out : Ql_out;

    int aclamp = 127;
    const float* Af = Pf;
    int a32max = 31;
    if (hyb) {
        long long rem = (long long)PROWS - 1 - (long long)mBase;
        aclamp = rem < 127 ? (int)rem : 127;
        size_t abase = mBase + 128;
        if (abase >= PROWS) { abase = 0; a32max = 0; }
        else {
            long long r2 = (long long)PROWS - 1 - (long long)abase;
            a32max = r2 < 31 ? (int)r2 : 31;
        }
        Af = Pf + abase * DHID;
    }
    const float* Wfn = Wf + nBase;

    if (tid < 128) bias_s[tid] = bias[nBase + tid];

    const int j  = lane >> 3;
    const int rj = lane & 7;
    const int wm = (w & 7) >> 2;
    const int wn = w & 3;
    uint32_t aoff[4], boff[2];
#pragma unroll
    for (int mi = 0; mi < 4; ++mi)
        aoff[mi] = (uint32_t)((wm * 64 + mi * 16 + (j & 1) * 8 + rj) * GP_B + (j >> 1) * 16);
#pragma unroll
    for (int p = 0; p < 2; ++p)
        boff[p] = (uint32_t)((wn * 32 + p * 16 + (j >> 1) * 8 + rj) * GP_B + (j & 1) * 16);

    float acc[4][4][4];
    float facc[4][8];
#pragma unroll
    for (int mi = 0; mi < 4; ++mi)
#pragma unroll
        for (int ni = 0; ni < 4; ++ni)
#pragma unroll
            for (int r = 0; r < 4; ++r) acc[mi][ni][r] = 0.0f;
#pragma unroll
    for (int i = 0; i < 4; ++i)
#pragma unroll
        for (int jj = 0; jj < 8; ++jj) facc[i][jj] = 0.0f;

    load_stage_hyb(sb + 0 * HSTAGE, 0, tid, aclamp, A_h, A_l, B_h, B_l, Wfn, Af, a32max, hyb);
    CP_COMMIT();
    load_stage_hyb(sb + 1 * HSTAGE, 32, tid, aclamp, A_h, A_l, B_h, B_l, Wfn, Af, a32max, hyb);
    CP_COMMIT();

    for (int t = 0; t < NCHUNK; ++t) {
        if (t + 1 < NCHUNK) CP_WAIT1(); else CP_WAIT0();
        __syncthreads();
        if (t + 2 < NCHUNK) {
            load_stage_hyb(sb + (uint32_t)((t + 2) % 3) * HSTAGE, (t + 2) * 32, tid,
                           aclamp, A_h, A_l, B_h, B_l, Wfn, Af, a32max, hyb);
            CP_COMMIT();
        }
        if (tid < 256)
            mma_chunk(sb + (uint32_t)(t % 3) * HSTAGE, aoff, boff, acc);
        else if (hyb)
            fp32_chunk(smem + (size_t)(t % 3) * HSTAGE, tid - 256, facc);
    }

    if (tid < 256) {
        // HMMA epilogue: bias + relu, split hi/lo bf16 store (guarded rows)
        const int rGrp = lane >> 2;
        const int cGrp = (lane & 3) * 2;
#pragma unroll
        for (int mi = 0; mi < 4; ++mi) {
            size_t gr = mBase + wm * 64 + mi * 16 + rGrp;
#pragma unroll
            for (int ni = 0; ni < 4; ++ni) {
                int lc = wn * 32 + ni * 8 + cGrp;
                float b0 = bias_s[lc], b1 = bias_s[lc + 1];
                float v0 = fmaxf(acc[mi][ni][0] + b0, 0.0f);
                float v1 = fmaxf(acc[mi][ni][1] + b1, 0.0f);
                float v2 = fmaxf(acc[mi][ni][2] + b0, 0.0f);
                float v3 = fmaxf(acc[mi][ni][3] + b1, 0.0f);
                __nv_bfloat16 h0, h1, h2, h3, l0, l1, l2, l3;
                split2(v0, h0, l0); split2(v1, h1, l1);
                split2(v2, h2, l2); split2(v3, h3, l3);
                bool g0 = !hyb || (gr < PROWS);
                bool g1 = !hyb || (gr + 8 < PROWS);
                if (g0) {
                    size_t o0 = gr * DHID + nBase + lc;
                    *(__nv_bfloat162*)(Ch + o0) = __nv_bfloat162(h0, h1);
                    *(__nv_bfloat162*)(Cl + o0) = __nv_bfloat162(l0, l1);
                }
                if (g1) {
                    size_t o1 = (gr + 8) * DHID + nBase + lc;
                    *(__nv_bfloat162*)(Ch + o1) = __nv_bfloat162(h2, h3);
                    *(__nv_bfloat162*)(Cl + o1) = __nv_bfloat162(l2, l3);
                }
            }
        }
    } else if (hyb) {
        // fp32 epilogue: rows mBase+128 + ty*4+i, cols nBase + tx*8..
        const int t2 = tid - 256;
        const int tx = t2 & 15, ty = t2 >> 4;
#pragma unroll
        for (int i = 0; i < 4; ++i) {
            size_t g = mBase + 128 + ty * 4 + i;
            if (g < PROWS) {
                int c0 = tx * 8;
#pragma unroll
                for (int jj = 0; jj < 8; jj += 2) {
                    float v0 = fmaxf(facc[i][jj]     + bias_s[c0 + jj],     0.0f);
                    float v1 = fmaxf(facc[i][jj + 1] + bias_s[c0 + jj + 1], 0.0f);
                    __nv_bfloat16 h0, h1, l0, l1;
                    split2(v0, h0, l0); split2(v1, h1, l1);
                    size_t o = g * DHID + nBase + c0 + jj;
                    *(__nv_bfloat162*)(Ph_out + o) = __nv_bfloat162(h0, h1);
                    *(__nv_bfloat162*)(Pl_out + o) = __nv_bfloat162(l0, l1);
                }
            }
        }
    }
}

// ---------------- tensor-core fused attention (unchanged from R5) ------------
#define SCP      132
#define SC_OFF   0
#define ST_OFF   67584
#define AH_OFF   67584
#define AL_OFF   102400
#define AP_B     272
#define QT_OFF   137216
#define QSTG_B   36864
#define QP_B     144
#define QB_OFF   210944
#define ASMEM    211456

__device__ __forceinline__ void load_stage_a(uint32_t dst, int kc, int tid,
                                             const __nv_bfloat16* __restrict__ A_h,
                                             const __nv_bfloat16* __restrict__ A_l,
                                             const __nv_bfloat16* __restrict__ B_h,
                                             const __nv_bfloat16* __restrict__ B_l) {
#pragma unroll
    for (int i = 0; i < 2; ++i) {
        int idx = tid + i * 256;
        int row = idx >> 2;
        int c   = idx & 3;
        uint32_t d = dst + (uint32_t)(row * GP_B + c * 16);
        size_t so = (size_t)row * DHID + kc + c * 8;
        cp16(d + O_AH, A_h + so);
        cp16(d + O_AL, A_l + so);
        cp16(d + O_BH, B_h + so);
        cp16(d + O_BL, B_l + so);
    }
}

__global__ __launch_bounds__(256)
void attn_tc_kernel(const __nv_bfloat16* __restrict__ Wph,
                    const __nv_bfloat16* __restrict__ Wpl,
                    const __nv_bfloat16* __restrict__ Wqh,
                    const __nv_bfloat16* __restrict__ Wql,
                    const __nv_bfloat16* __restrict__ Qh,
                    const __nv_bfloat16* __restrict__ Ql,
                    float* __restrict__ out) {
    extern __shared__ char smem[];
    uint32_t sb = smem_u32(smem);
    float* sc = (float*)(smem + SC_OFF);
    float* qb = (float*)(smem + QB_OFF);

    const int tid  = threadIdx.x;
    const int w    = tid >> 5;
    const int lane = tid & 31;
    const int wm   = w >> 2;
    const int wn   = w & 3;
    const int b    = blockIdx.y;
    const int pBase = blockIdx.x * 128;

    if (tid < 128) qb[tid] = g_qbias[b * NLQ + tid];

    const __nv_bfloat16* A_h = Wph + ((size_t)b * NLP + pBase) * DHID;
    const __nv_bfloat16* A_l = Wpl + ((size_t)b * NLP + pBase) * DHID;
    const __nv_bfloat16* B_h = Wqh + (size_t)b * NLQ * DHID;
    const __nv_bfloat16* B_l = Wql + (size_t)b * NLQ * DHID;
    const __nv_bfloat16* Q_h = Qh + (size_t)b * NLQ * DHID;
    const __nv_bfloat16* Q_l = Ql + (size_t)b * NLQ * DHID;

    const int j  = lane >> 3;
    const int rj = lane & 7;

    // ---- phase 1: scores = Wp @ Wq^T (split-bf16) ----
    {
        uint32_t aoff[4], boff[2];
#pragma unroll
        for (int mi = 0; mi < 4; ++mi)
            aoff[mi] = (uint32_t)((wm * 64 + mi * 16 + (j & 1) * 8 + rj) * GP_B + (j >> 1) * 16);
#pragma unroll
        for (int p = 0; p < 2; ++p)
            boff[p] = (uint32_t)((wn * 32 + p * 16 + (j >> 1) * 8 + rj) * GP_B + (j & 1) * 16);

        float acc[4][4][4];
#pragma unroll
        for (int mi = 0; mi < 4; ++mi)
#pragma unroll
            for (int ni = 0; ni < 4; ++ni)
#pragma unroll
                for (int r = 0; r < 4; ++r) acc[mi][ni][r] = 0.0f;

        load_stage_a(sb + ST_OFF + 0 * STAGE_B, 0, tid, A_h, A_l, B_h, B_l);
        CP_COMMIT();
        load_stage_a(sb + ST_OFF + 1 * STAGE_B, 32, tid, A_h, A_l, B_h, B_l);
        CP_COMMIT();

        for (int t = 0; t < NCHUNK; ++t) {
            if (t + 1 < NCHUNK) CP_WAIT1(); else CP_WAIT0();
            __syncthreads();
            if (t + 2 < NCHUNK) {
                load_stage_a(sb + ST_OFF + (uint32_t)((t + 2) % 3) * STAGE_B,
                             (t + 2) * 32, tid, A_h, A_l, B_h, B_l);
                CP_COMMIT();
            }
            mma_chunk(sb + ST_OFF + (uint32_t)(t % 3) * STAGE_B, aoff, boff, acc);
        }
        __syncthreads();

        const int rGrp = lane >> 2;
        const int cGrp = (lane & 3) * 2;
#pragma unroll
        for (int mi = 0; mi < 4; ++mi) {
            int pr = wm * 64 + mi * 16 + rGrp;
#pragma unroll
            for (int ni = 0; ni < 4; ++ni) {
                int q0 = wn * 32 + ni * 8 + cGrp;
                float b0 = qb[q0], b1 = qb[q0 + 1];
                sc[pr * SCP + q0]           = acc[mi][ni][0] + b0;
                sc[pr * SCP + q0 + 1]       = acc[mi][ni][1] + b1;
                sc[(pr + 8) * SCP + q0]     = acc[mi][ni][2] + b0;
                sc[(pr + 8) * SCP + q0 + 1] = acc[mi][ni][3] + b1;
            }
        }
    }
    __syncthreads();

    // prefetch first Q tile while softmax runs
    {
#pragma unroll
        for (int i = 0; i < 4; ++i) {
            int idx = tid + i * 256;
            int row = idx >> 3;
            int c   = idx & 7;
            uint32_t d = sb + QT_OFF + (uint32_t)(row * QP_B + c * 16);
            size_t so = (size_t)row * DHID + c * 8;
            cp16(d, Q_h + so);
            cp16(d + 18432, Q_l + so);
        }
        CP_COMMIT();
    }

    // ---- phase 2: softmax per p-row ----
    if (tid < 128) {
        float* row = sc + tid * SCP;
        float mx = -INFINITY;
#pragma unroll 8
        for (int c = 0; c < 128; ++c) mx = fmaxf(mx, row[c]);
        float s = 0.0f;
#pragma unroll 8
        for (int c = 0; c < 128; ++c) {
            float e = __expf(row[c] - mx);
            row[c] = e;
            s += e;
        }
        float inv = 1.0f / s;
#pragma unroll 8
        for (int c = 0; c < 128; ++c) row[c] *= inv;
    }
    __syncthreads();

    // alpha -> bf16 hi/lo (smem)
    {
        for (int i = tid; i < 128 * 32; i += 256) {
            int p  = i >> 5;
            int q4 = (i & 31) * 4;
            float4 v = *(float4*)&sc[p * SCP + q4];
            __nv_bfloat16 h0, h1, h2, h3, l0, l1, l2, l3;
            split2(v.x, h0, l0); split2(v.y, h1, l1);
            split2(v.z, h2, l2); split2(v.w, h3, l3);
            __nv_bfloat162* ph = (__nv_bfloat162*)(smem + AH_OFF + p * AP_B + q4 * 2);
            __nv_bfloat162* pl = (__nv_bfloat162*)(smem + AL_OFF + p * AP_B + q4 * 2);
            ph[0] = __nv_bfloat162(h0, h1); ph[1] = __nv_bfloat162(h2, h3);
            pl[0] = __nv_bfloat162(l0, l1); pl[1] = __nv_bfloat162(l2, l3);
        }
    }
    __syncthreads();

    // ---- phase 3: out = alpha @ question ----
    {
        uint32_t aoff3[4];
#pragma unroll
        for (int mi = 0; mi < 4; ++mi)
            aoff3[mi] = (uint32_t)((wm * 64 + mi * 16 + (j & 1) * 8 + rj) * AP_B + (j >> 1) * 16);
        uint32_t boffq = (uint32_t)(((j & 1) * 8 + rj) * QP_B + wn * 32 + (j >> 1) * 16);

        for (int dc = 0; dc < 12; ++dc) {
            uint32_t qs = sb + QT_OFF + (uint32_t)(dc & 1) * QSTG_B;
            if (dc + 1 < 12) {
                uint32_t nq = sb + QT_OFF + (uint32_t)((dc + 1) & 1) * QSTG_B;
                int koff = (dc + 1) * 64;
#pragma unroll
                for (int i = 0; i < 4; ++i) {
                    int idx = tid + i * 256;
                    int row = idx >> 3;
                    int c   = idx & 7;
                    uint32_t d = nq + (uint32_t)(row * QP_B + c * 16);
                    size_t so = (size_t)row * DHID + koff + c * 8;
                    cp16(d, Q_h + so);
                    cp16(d + 18432, Q_l + so);
                }
                CP_COMMIT();
                CP_WAIT1();
            } else {
                CP_WAIT0();
            }
            __syncthreads();

            float acc[4][2][4];
#pragma unroll
            for (int mi = 0; mi < 4; ++mi)
#pragma unroll
                for (int ni = 0; ni < 2; ++ni)
#pragma unroll
                    for (int r = 0; r < 4; ++r) acc[mi][ni][r] = 0.0f;

#pragma unroll
            for (int ks = 0; ks < 8; ++ks) {
                uint32_t ka = (uint32_t)ks * 32;
                uint32_t kq = (uint32_t)ks * 16 * QP_B;
                uint32_t ah[4][4], al[4][4];
#pragma unroll
                for (int mi = 0; mi < 4; ++mi)
                    ldsm4(ah[mi][0], ah[mi][1], ah[mi][2], ah[mi][3],
                          sb + AH_OFF + aoff3[mi] + ka);
#pragma unroll
                for (int mi = 0; mi < 4; ++mi)
                    ldsm4(al[mi][0], al[mi][1], al[mi][2], al[mi][3],
                          sb + AL_OFF + aoff3[mi] + ka);
                uint32_t bh[2][2], bl[2][2];
                {
                    uint32_t r0, r1, r2, r3;
                    ldsm4t(r0, r1, r2, r3, qs + boffq + kq);
                    bh[0][0] = r0; bh[0][1] = r1; bh[1][0] = r2; bh[1][1] = r3;
                    ldsm4t(r0, r1, r2, r3, qs + 18432 + boffq + kq);
                    bl[0][0] = r0; bl[0][1] = r1; bl[1][0] = r2; bl[1][1] = r3;
                }
#pragma unroll
                for (int mi = 0; mi < 4; ++mi)
#pragma unroll
                    for (int ni = 0; ni < 2; ++ni) {
                        mma16816(acc[mi][ni], ah[mi][0], ah[mi][1], ah[mi][2], ah[mi][3],
                                 bh[ni][0], bh[ni][1]);
                        mma16816(acc[mi][ni], al[mi][0], al[mi][1], al[mi][2], al[mi][3],
                                 bh[ni][0], bh[ni][1]);
                        mma16816(acc[mi][ni], ah[mi][0], ah[mi][1], ah[mi][2], ah[mi][3],
                                 bl[ni][0], bl[ni][1]);
                    }
            }

            const int rGrp = lane >> 2;
            const int cGrp = (lane & 3) * 2;
#pragma unroll
            for (int mi = 0; mi < 4; ++mi) {
                size_t gr = (size_t)b * NLP + pBase + wm * 64 + mi * 16 + rGrp;
#pragma unroll
                for (int ni = 0; ni < 2; ++ni) {
                    int d = dc * 64 + wn * 16 + ni * 8 + cGrp;
                    float2 v0 = {acc[mi][ni][0], acc[mi][ni][1]};
                    float2 v1 = {acc[mi][ni][2], acc[mi][ni][3]};
                    *(float2*)(out + gr * DHID + d)       = v0;
                    *(float2*)(out + (gr + 8) * DHID + d) = v1;
                }
            }
            __syncthreads();
        }
    }
}

// ---------------------------------------------------------------------------
extern "C" void kernel_launch(void* const* d_in, const int* in_sizes, int n_in,
                              void* d_out, int out_size) {
    const float* passage  = (const float*)d_in[0];
    const float* question = (const float*)d_in[2];
    const unsigned char* qmask = (const unsigned char*)d_in[3];
    const float* Ww = (const float*)d_in[4];
    const float* Wb = (const float*)d_in[5];
    float* out = (float*)d_out;

    __nv_bfloat16 *ph, *pl, *qh, *ql, *wth, *wtl, *wph, *wpl, *wqh, *wql;
    cudaGetSymbolAddress((void**)&ph,  g_Ph);
    cudaGetSymbolAddress((void**)&pl,  g_Pl);
    cudaGetSymbolAddress((void**)&qh,  g_Qh);
    cudaGetSymbolAddress((void**)&ql,  g_Ql);
    cudaGetSymbolAddress((void**)&wth, g_Wth);
    cudaGetSymbolAddress((void**)&wtl, g_Wtl);
    cudaGetSymbolAddress((void**)&wph, g_Wph);
    cudaGetSymbolAddress((void**)&wpl, g_Wpl);
    cudaGetSymbolAddress((void**)&wqh, g_Wqh);
    cudaGetSymbolAddress((void**)&wql, g_Wql);

    mask_prep_kernel<<<1, 256>>>(qmask, NB * NLQ);

    int np4 = NB * NLP * DHID / 4;
    int nq4 = NB * NLQ * DHID / 4;
    split_kernel<<<(np4 + 255) / 256, 256>>>((const float4*)passage,
                                             (__nv_bfloat162*)ph, (__nv_bfloat162*)pl, np4);
    split_kernel<<<(nq4 + 255) / 256, 256>>>((const float4*)question,
                                             (__nv_bfloat162*)qh, (__nv_bfloat162*)ql, nq4);
    wsplit_kernel<<<dim3(DHID / 32, DHID / 32), dim3(32, 8)>>>(Ww, wth, wtl);

    cudaFuncSetAttribute(gemm_hyb_kernel, cudaFuncAttributeMaxDynamicSharedMemorySize, HSMEM);
    gemm_hyb_kernel<<<dim3(DHID / 128, YPH + (NB * NLQ) / 128), 384, HSMEM>>>(
        ph, pl, qh, ql, wth, wtl, passage, Ww, Wb, wph, wpl, wqh, wql);

    cudaFuncSetAttribute(attn_tc_kernel, cudaFuncAttributeMaxDynamicSharedMemorySize, ASMEM);
    attn_tc_kernel<<<dim3(NLP / 128, NB), 256, ASMEM>>>(wph, wpl, wqh, wql, qh, ql, out);
}

// round 8
// speedup vs baseline: 2.5386x; 1.5032x over previous
#include <cuda_runtime.h>
#include <cuda_bf16.h>
#include <math.h>
#include <stdint.h>
#include <stddef.h>

#define DHID 768
#define NB   64
#define NLP  1024
#define NLQ  128

// ---------------- scratch (__device__ globals; allocation-free rule) --------
__device__ float g_qbias[NB * NLQ];
__device__ __align__(16) __nv_bfloat16 g_Qh[(size_t)NB * NLQ * DHID];
__device__ __align__(16) __nv_bfloat16 g_Ql[(size_t)NB * NLQ * DHID];
__device__ __align__(16) __nv_bfloat16 g_Wth[DHID * DHID];   // W^T hi [n][k]
__device__ __align__(16) __nv_bfloat16 g_Wtl[DHID * DHID];   // W^T lo [n][k]
__device__ __align__(16) __nv_bfloat16 g_Wph[(size_t)NB * NLP * DHID];
__device__ __align__(16) __nv_bfloat16 g_Wpl[(size_t)NB * NLP * DHID];
__device__ __align__(16) __nv_bfloat16 g_Wqh[(size_t)NB * NLQ * DHID];
__device__ __align__(16) __nv_bfloat16 g_Wql[(size_t)NB * NLQ * DHID];

// ---------------- small asm helpers ----------------------------------------
__device__ __forceinline__ uint32_t smem_u32(const void* p) {
    uint32_t a;
    asm("{ .reg .u64 t; cvta.to.shared.u64 t, %1; cvt.u32.u64 %0, t; }" : "=r"(a) : "l"(p));
    return a;
}
__device__ __forceinline__ void cp16(uint32_t dst, const void* src) {
    asm volatile("cp.async.cg.shared.global [%0], [%1], 16;" :: "r"(dst), "l"(src));
}
#define CP_COMMIT() asm volatile("cp.async.commit_group;" ::: "memory")
#define CP_WAIT1()  asm volatile("cp.async.wait_group 1;" ::: "memory")
#define CP_WAIT0()  asm volatile("cp.async.wait_group 0;" ::: "memory")

__device__ __forceinline__ void ldsm4(uint32_t& r0, uint32_t& r1, uint32_t& r2,
                                      uint32_t& r3, uint32_t a) {
    asm volatile("ldmatrix.sync.aligned.m8n8.x4.shared.b16 {%0,%1,%2,%3}, [%4];"
                 : "=r"(r0), "=r"(r1), "=r"(r2), "=r"(r3) : "r"(a));
}
__device__ __forceinline__ void ldsm4t(uint32_t& r0, uint32_t& r1, uint32_t& r2,
                                       uint32_t& r3, uint32_t a) {
    asm volatile("ldmatrix.sync.aligned.m8n8.x4.trans.shared.b16 {%0,%1,%2,%3}, [%4];"
                 : "=r"(r0), "=r"(r1), "=r"(r2), "=r"(r3) : "r"(a));
}
__device__ __forceinline__ void mma16816(float* c, uint32_t a0, uint32_t a1,
                                         uint32_t a2, uint32_t a3,
                                         uint32_t b0, uint32_t b1) {
    asm volatile("mma.sync.aligned.m16n8k16.row.col.f32.bf16.bf16.f32 "
                 "{%0,%1,%2,%3}, {%4,%5,%6,%7}, {%8,%9}, {%0,%1,%2,%3};"
                 : "+f"(c[0]), "+f"(c[1]), "+f"(c[2]), "+f"(c[3])
                 : "r"(a0), "r"(a1), "r"(a2), "r"(a3), "r"(b0), "r"(b1));
}
__device__ __forceinline__ void split2(float v, __nv_bfloat16& h, __nv_bfloat16& l) {
    h = __float2bfloat16(v);
    l = __float2bfloat16(v - __bfloat162float(h));
}

// ---------------- mask prep (dtype-sniffing) --------------------------------
__global__ void mask_prep_kernel(const unsigned char* __restrict__ qm, int n) {
    __shared__ int mode;
    if (threadIdx.x == 0) mode = 0;
    __syncthreads();
    for (int i = threadIdx.x; i < n; i += blockDim.x) {
        int r = i & 3;
        unsigned char c = qm[i];
        if (r != 0 && c != 0) {
            if (r == 3 && c == 0x3F) atomicMax(&mode, 2);
            else                     atomicMax(&mode, 1);
        }
    }
    __syncthreads();
    int m = mode;
    for (int i = threadIdx.x; i < n; i += blockDim.x) {
        int v;
        if (m == 2)      v = (((const float*)(const void*)qm)[i] != 0.0f);
        else if (m == 1) v = (qm[i] != 0);
        else             v = (((const int*)(const void*)qm)[i] != 0);
        g_qbias[i] = v ? -1e30f : 0.0f;
    }
}

// ---------------- fp32 -> (hi,lo) bf16 split (question only, for attn) ------
__global__ void split_kernel(const float4* __restrict__ x,
                             __nv_bfloat162* __restrict__ h,
                             __nv_bfloat162* __restrict__ l, int n4) {
    int i = blockIdx.x * blockDim.x + threadIdx.x;
    if (i >= n4) return;
    float4 v = x[i];
    __nv_bfloat16 h0, h1, h2, h3, l0, l1, l2, l3;
    split2(v.x, h0, l0); split2(v.y, h1, l1);
    split2(v.z, h2, l2); split2(v.w, h3, l3);
    h[i * 2]     = __nv_bfloat162(h0, h1);
    h[i * 2 + 1] = __nv_bfloat162(h2, h3);
    l[i * 2]     = __nv_bfloat162(l0, l1);
    l[i * 2 + 1] = __nv_bfloat162(l2, l3);
}

// ---------------- W[k][n] -> W^T split (hi/lo) ------------------------------
__global__ void wsplit_kernel(const float* __restrict__ W,
                              __nv_bfloat16* __restrict__ Wth,
                              __nv_bfloat16* __restrict__ Wtl) {
    __shared__ float t[32][33];
    int bx = blockIdx.x * 32;  // k
    int by = blockIdx.y * 32;  // n
    for (int yy = threadIdx.y; yy < 32; yy += 8)
        t[yy][threadIdx.x] = W[(size_t)(bx + yy) * DHID + by + threadIdx.x];
    __syncthreads();
    for (int yy = threadIdx.y; yy < 32; yy += 8) {
        float v = t[threadIdx.x][yy];
        __nv_bfloat16 h, l;
        split2(v, h, l);
        size_t o = (size_t)(by + yy) * DHID + bx + threadIdx.x;
        Wth[o] = h;
        Wtl[o] = l;
    }
}

// ---------------- common tiling constants -----------------------------------
#define GP_B      80
#define ARR_B     (128 * GP_B)
#define O_AH      0
#define O_AL      (1 * ARR_B)
#define O_BH      (2 * ARR_B)
#define O_BL      (3 * ARR_B)
#define STAGE_B   (4 * ARR_B)         // 40960
#define NCHUNK    (DHID / 32)         // 24

// 3-product split-bf16 mainloop chunk (2 k16 steps), accumulate into acc[4][4][4]
__device__ __forceinline__ void mma_chunk(uint32_t st, const uint32_t* aoff,
                                          const uint32_t* boff, float acc[4][4][4]) {
#pragma unroll
    for (int ks = 0; ks < 2; ++ks) {
        uint32_t k2 = (uint32_t)ks * 32;
        uint32_t ah[4][4], al[4][4], bh[4][2], bl[4][2];
#pragma unroll
        for (int mi = 0; mi < 4; ++mi)
            ldsm4(ah[mi][0], ah[mi][1], ah[mi][2], ah[mi][3], st + O_AH + aoff[mi] + k2);
#pragma unroll
        for (int mi = 0; mi < 4; ++mi)
            ldsm4(al[mi][0], al[mi][1], al[mi][2], al[mi][3], st + O_AL + aoff[mi] + k2);
#pragma unroll
        for (int p = 0; p < 2; ++p) {
            uint32_t r0, r1, r2, r3;
            ldsm4(r0, r1, r2, r3, st + O_BH + boff[p] + k2);
            bh[p * 2][0] = r0; bh[p * 2][1] = r1;
            bh[p * 2 + 1][0] = r2; bh[p * 2 + 1][1] = r3;
            ldsm4(r0, r1, r2, r3, st + O_BL + boff[p] + k2);
            bl[p * 2][0] = r0; bl[p * 2][1] = r1;
            bl[p * 2 + 1][0] = r2; bl[p * 2 + 1][1] = r3;
        }
#pragma unroll
        for (int mi = 0; mi < 4; ++mi)
#pragma unroll
            for (int ni = 0; ni < 4; ++ni) {
                mma16816(acc[mi][ni], ah[mi][0], ah[mi][1], ah[mi][2], ah[mi][3],
                         bh[ni][0], bh[ni][1]);
                mma16816(acc[mi][ni], al[mi][0], al[mi][1], al[mi][2], al[mi][3],
                         bh[ni][0], bh[ni][1]);
                mma16816(acc[mi][ni], ah[mi][0], ah[mi][1], ah[mi][2], ah[mi][3],
                         bl[ni][0], bl[ni][1]);
            }
    }
}

// ---------------- merged projection GEMM (fp32 A in-register split) ----------
// A (passage/question fp32) loaded via LDG.128, converted to bf16 hi/lo in
// registers, STS'd into the standard stage layout. B via cp.async (hi/lo).
#define GSMEM (3 * STAGE_B + 512)
#define YP    ((NB * NLP) / 128)      // 512 P row-blocks

__device__ __forceinline__ void load_stageB(uint32_t dst, int kc, int tid,
                                            const __nv_bfloat16* __restrict__ B_h,
                                            const __nv_bfloat16* __restrict__ B_l) {
#pragma unroll
    for (int i = 0; i < 2; ++i) {
        int idx = tid + i * 256;
        int row = idx >> 2;
        int c   = idx & 3;
        uint32_t d = dst + (uint32_t)(row * GP_B + c * 16);
        size_t so = (size_t)row * DHID + kc + c * 8;
        cp16(d + O_BH, B_h + so);
        cp16(d + O_BL, B_l + so);
    }
}

__device__ __forceinline__ void ldgA(const float* __restrict__ Af, int kc, int tid,
                                     float4 ra[2][2]) {
#pragma unroll
    for (int i = 0; i < 2; ++i) {
        int idx = tid + i * 256;
        int row = idx >> 2;
        int c   = idx & 3;
        const float* p = Af + (size_t)row * DHID + kc + c * 8;
        ra[i][0] = *(const float4*)p;
        ra[i][1] = *(const float4*)(p + 4);
    }
}

__device__ __forceinline__ void stsA(char* stage, int tid, const float4 ra[2][2]) {
#pragma unroll
    for (int i = 0; i < 2; ++i) {
        int idx = tid + i * 256;
        int row = idx >> 2;
        int c   = idx & 3;
        float f[8] = {ra[i][0].x, ra[i][0].y, ra[i][0].z, ra[i][0].w,
                      ra[i][1].x, ra[i][1].y, ra[i][1].z, ra[i][1].w};
        uint32_t H[4], L[4];
#pragma unroll
        for (int q = 0; q < 4; ++q) {
            __nv_bfloat16 h0, l0, h1, l1;
            split2(f[2 * q],     h0, l0);
            split2(f[2 * q + 1], h1, l1);
            __nv_bfloat162 ph(h0, h1), pl(l0, l1);
            H[q] = *reinterpret_cast<uint32_t*>(&ph);
            L[q] = *reinterpret_cast<uint32_t*>(&pl);
        }
        char* d = stage + row * GP_B + c * 16;
        *(uint4*)(d + O_AH) = make_uint4(H[0], H[1], H[2], H[3]);
        *(uint4*)(d + O_AL) = make_uint4(L[0], L[1], L[2], L[3]);
    }
}

__global__ __launch_bounds__(256)
void gemm_mma_kernel(const float* __restrict__ Pf,
                     const float* __restrict__ Qf,
                     const __nv_bfloat16* __restrict__ Bh,
                     const __nv_bfloat16* __restrict__ Bl,
                     const float* __restrict__ bias,
                     __nv_bfloat16* __restrict__ Ph_out,
                     __nv_bfloat16* __restrict__ Pl_out,
                     __nv_bfloat16* __restrict__ Qh_out,
                     __nv_bfloat16* __restrict__ Ql_out) {
    extern __shared__ char smem[];
    uint32_t sb = smem_u32(smem);
    float* bias_s = (float*)(smem + 3 * STAGE_B);

    const int tid  = threadIdx.x;
    const int w    = tid >> 5;
    const int lane = tid & 31;
    const int wm   = w >> 2;
    const int wn   = w & 3;
    const int yb   = blockIdx.y;
    const bool isQ = (yb >= YP);
    const size_t mBase = (size_t)(isQ ? yb - YP : yb) * 128;
    const int    nBase = blockIdx.x * 128;

    if (tid < 128) bias_s[tid] = bias[nBase + tid];

    const float* Af = (isQ ? Qf : Pf) + mBase * DHID;
    const __nv_bfloat16* B_h = Bh + (size_t)nBase * DHID;
    const __nv_bfloat16* B_l = Bl + (size_t)nBase * DHID;
    __nv_bfloat16* Ch = isQ ? Qh_out : Ph_out;
    __nv_bfloat16* Cl = isQ ? Ql_out : Pl_out;

    const int j  = lane >> 3;
    const int rj = lane & 7;
    uint32_t aoff[4], boff[2];
#pragma unroll
    for (int mi = 0; mi < 4; ++mi)
        aoff[mi] = (uint32_t)((wm * 64 + mi * 16 + (j & 1) * 8 + rj) * GP_B + (j >> 1) * 16);
#pragma unroll
    for (int p = 0; p < 2; ++p)
        boff[p] = (uint32_t)((wn * 32 + p * 16 + (j >> 1) * 8 + rj) * GP_B + (j & 1) * 16);

    float acc[4][4][4];
#pragma unroll
    for (int mi = 0; mi < 4; ++mi)
#pragma unroll
        for (int ni = 0; ni < 4; ++ni)
#pragma unroll
            for (int r = 0; r < 4; ++r) acc[mi][ni][r] = 0.0f;

    float4 ra[2][2];
    // prologue: stages 0,1 filled; LDG for chunk 2 in flight
    ldgA(Af, 0, tid, ra);
    load_stageB(sb + 0 * STAGE_B, 0, tid, B_h, B_l);
    CP_COMMIT();
    stsA(smem + (size_t)0 * STAGE_B, tid, ra);
    ldgA(Af, 32, tid, ra);
    load_stageB(sb + 1 * STAGE_B, 32, tid, B_h, B_l);
    CP_COMMIT();
    stsA(smem + (size_t)1 * STAGE_B, tid, ra);
    ldgA(Af, 64, tid, ra);

    for (int t = 0; t < NCHUNK; ++t) {
        if (t + 1 < NCHUNK) CP_WAIT1(); else CP_WAIT0();
        __syncthreads();
        if (t + 2 < NCHUNK) {
            load_stageB(sb + (uint32_t)((t + 2) % 3) * STAGE_B, (t + 2) * 32, tid, B_h, B_l);
            CP_COMMIT();
            stsA(smem + (size_t)((t + 2) % 3) * STAGE_B, tid, ra);
            if (t + 3 < NCHUNK) ldgA(Af, (t + 3) * 32, tid, ra);
        }
        mma_chunk(sb + (uint32_t)(t % 3) * STAGE_B, aoff, boff, acc);
    }

    // epilogue: bias + relu, split hi/lo bf16 store
    const int rGrp = lane >> 2;
    const int cGrp = (lane & 3) * 2;
#pragma unroll
    for (int mi = 0; mi < 4; ++mi) {
        size_t gr = mBase + wm * 64 + mi * 16 + rGrp;
#pragma unroll
        for (int ni = 0; ni < 4; ++ni) {
            int lc = wn * 32 + ni * 8 + cGrp;
            float b0 = bias_s[lc], b1 = bias_s[lc + 1];
            float v0 = fmaxf(acc[mi][ni][0] + b0, 0.0f);
            float v1 = fmaxf(acc[mi][ni][1] + b1, 0.0f);
            float v2 = fmaxf(acc[mi][ni][2] + b0, 0.0f);
            float v3 = fmaxf(acc[mi][ni][3] + b1, 0.0f);
            __nv_bfloat16 h0, h1, h2, h3, l0, l1, l2, l3;
            split2(v0, h0, l0); split2(v1, h1, l1);
            split2(v2, h2, l2); split2(v3, h3, l3);
            size_t o0 = gr * DHID + nBase + lc;
            size_t o1 = (gr + 8) * DHID + nBase + lc;
            *(__nv_bfloat162*)(Ch + o0) = __nv_bfloat162(h0, h1);
            *(__nv_bfloat162*)(Cl + o0) = __nv_bfloat162(l0, l1);
            *(__nv_bfloat162*)(Ch + o1) = __nv_bfloat162(h2, h3);
            *(__nv_bfloat162*)(Cl + o1) = __nv_bfloat162(l2, l3);
        }
    }
}

// ---------------- tensor-core fused attention --------------------------------
#define SCP      132
#define SC_OFF   0
#define ST_OFF   67584
#define AH_OFF   67584
#define AL_OFF   102400
#define AP_B     272
#define QT_OFF   137216
#define QSTG_B   36864
#define QP_B     144
#define QB_OFF   210944
#define RED_OFF  211456
#define ASMEM    213504

__device__ __forceinline__ void load_stage_a(uint32_t dst, int kc, int tid,
                                             const __nv_bfloat16* __restrict__ A_h,
                                             const __nv_bfloat16* __restrict__ A_l,
                                             const __nv_bfloat16* __restrict__ B_h,
                                             const __nv_bfloat16* __restrict__ B_l) {
#pragma unroll
    for (int i = 0; i < 2; ++i) {
        int idx = tid + i * 256;
        int row = idx >> 2;
        int c   = idx & 3;
        uint32_t d = dst + (uint32_t)(row * GP_B + c * 16);
        size_t so = (size_t)row * DHID + kc + c * 8;
        cp16(d + O_AH, A_h + so);
        cp16(d + O_AL, A_l + so);
        cp16(d + O_BH, B_h + so);
        cp16(d + O_BL, B_l + so);
    }
}

__global__ __launch_bounds__(256)
void attn_tc_kernel(const __nv_bfloat16* __restrict__ Wph,
                    const __nv_bfloat16* __restrict__ Wpl,
                    const __nv_bfloat16* __restrict__ Wqh,
                    const __nv_bfloat16* __restrict__ Wql,
                    const __nv_bfloat16* __restrict__ Qh,
                    const __nv_bfloat16* __restrict__ Ql,
                    float* __restrict__ out) {
    extern __shared__ char smem[];
    uint32_t sb = smem_u32(smem);
    float* sc = (float*)(smem + SC_OFF);
    float* qb = (float*)(smem + QB_OFF);
    float* red  = (float*)(smem + RED_OFF);        // 256
    float* red2 = red + 256;                       // 256

    const int tid  = threadIdx.x;
    const int w    = tid >> 5;
    const int lane = tid & 31;
    const int wm   = w >> 2;
    const int wn   = w & 3;
    const int b    = blockIdx.y;
    const int pBase = blockIdx.x * 128;

    if (tid < 128) qb[tid] = g_qbias[b * NLQ + tid];

    const __nv_bfloat16* A_h = Wph + ((size_t)b * NLP + pBase) * DHID;
    const __nv_bfloat16* A_l = Wpl + ((size_t)b * NLP + pBase) * DHID;
    const __nv_bfloat16* B_h = Wqh + (size_t)b * NLQ * DHID;
    const __nv_bfloat16* B_l = Wql + (size_t)b * NLQ * DHID;
    const __nv_bfloat16* Q_h = Qh + (size_t)b * NLQ * DHID;
    const __nv_bfloat16* Q_l = Ql + (size_t)b * NLQ * DHID;

    const int j  = lane >> 3;
    const int rj = lane & 7;

    // ---- phase 1: scores = Wp @ Wq^T (split-bf16) ----
    {
        uint32_t aoff[4], boff[2];
#pragma unroll
        for (int mi = 0; mi < 4; ++mi)
            aoff[mi] = (uint32_t)((wm * 64 + mi * 16 + (j & 1) * 8 + rj) * GP_B + (j >> 1) * 16);
#pragma unroll
        for (int p = 0; p < 2; ++p)
            boff[p] = (uint32_t)((wn * 32 + p * 16 + (j >> 1) * 8 + rj) * GP_B + (j & 1) * 16);

        float acc[4][4][4];
#pragma unroll
        for (int mi = 0; mi < 4; ++mi)
#pragma unroll
            for (int ni = 0; ni < 4; ++ni)
#pragma unroll
                for (int r = 0; r < 4; ++r) acc[mi][ni][r] = 0.0f;

        load_stage_a(sb + ST_OFF + 0 * STAGE_B, 0, tid, A_h, A_l, B_h, B_l);
        CP_COMMIT();
        load_stage_a(sb + ST_OFF + 1 * STAGE_B, 32, tid, A_h, A_l, B_h, B_l);
        CP_COMMIT();

        for (int t = 0; t < NCHUNK; ++t) {
            if (t + 1 < NCHUNK) CP_WAIT1(); else CP_WAIT0();
            __syncthreads();
            if (t + 2 < NCHUNK) {
                load_stage_a(sb + ST_OFF + (uint32_t)((t + 2) % 3) * STAGE_B,
                             (t + 2) * 32, tid, A_h, A_l, B_h, B_l);
                CP_COMMIT();
            }
            mma_chunk(sb + ST_OFF + (uint32_t)(t % 3) * STAGE_B, aoff, boff, acc);
        }
        __syncthreads();

        const int rGrp = lane >> 2;
        const int cGrp = (lane & 3) * 2;
#pragma unroll
        for (int mi = 0; mi < 4; ++mi) {
            int pr = wm * 64 + mi * 16 + rGrp;
#pragma unroll
            for (int ni = 0; ni < 4; ++ni) {
                int q0 = wn * 32 + ni * 8 + cGrp;
                float b0 = qb[q0], b1 = qb[q0 + 1];
                sc[pr * SCP + q0]           = acc[mi][ni][0] + b0;
                sc[pr * SCP + q0 + 1]       = acc[mi][ni][1] + b1;
                sc[(pr + 8) * SCP + q0]     = acc[mi][ni][2] + b0;
                sc[(pr + 8) * SCP + q0 + 1] = acc[mi][ni][3] + b1;
            }
        }
    }
    __syncthreads();

    // prefetch first Q tile while softmax runs
    {
#pragma unroll
        for (int i = 0; i < 4; ++i) {
            int idx = tid + i * 256;
            int row = idx >> 3;
            int c   = idx & 7;
            uint32_t d = sb + QT_OFF + (uint32_t)(row * QP_B + c * 16);
            size_t so = (size_t)row * DHID + c * 8;
            cp16(d, Q_h + so);
            cp16(d + 18432, Q_l + so);
        }
        CP_COMMIT();
    }

    // ---- phase 2: softmax per p-row, 2 threads per row ----
    {
        int r    = tid & 127;
        int half = tid >> 7;
        float* row = sc + r * SCP + half * 64;
        float mx = -INFINITY;
#pragma unroll 8
        for (int c = 0; c < 64; ++c) mx = fmaxf(mx, row[c]);
        red[tid] = mx;
        __syncthreads();
        float m = fmaxf(red[r], red[r + 128]);
        float s = 0.0f;
#pragma unroll 8
        for (int c = 0; c < 64; ++c) {
            float e = __expf(row[c] - m);
            row[c] = e;
            s += e;
        }
        red2[tid] = s;
        __syncthreads();
        float inv = 1.0f / (red2[r] + red2[r + 128]);
#pragma unroll 8
        for (int c = 0; c < 64; ++c) row[c] *= inv;
    }
    __syncthreads();

    // alpha -> bf16 hi/lo (smem)
    {
        for (int i = tid; i < 128 * 32; i += 256) {
            int p  = i >> 5;
            int q4 = (i & 31) * 4;
            float4 v = *(float4*)&sc[p * SCP + q4];
            __nv_bfloat16 h0, h1, h2, h3, l0, l1, l2, l3;
            split2(v.x, h0, l0); split2(v.y, h1, l1);
            split2(v.z, h2, l2); split2(v.w, h3, l3);
            __nv_bfloat162* ph = (__nv_bfloat162*)(smem + AH_OFF + p * AP_B + q4 * 2);
            __nv_bfloat162* pl = (__nv_bfloat162*)(smem + AL_OFF + p * AP_B + q4 * 2);
            ph[0] = __nv_bfloat162(h0, h1); ph[1] = __nv_bfloat162(h2, h3);
            pl[0] = __nv_bfloat162(l0, l1); pl[1] = __nv_bfloat162(l2, l3);
        }
    }
    __syncthreads();

    // ---- phase 3: out = alpha @ question ----
    {
        uint32_t aoff3[4];
#pragma unroll
        for (int mi = 0; mi < 4; ++mi)
            aoff3[mi] = (uint32_t)((wm * 64 + mi * 16 + (j & 1) * 8 + rj) * AP_B + (j >> 1) * 16);
        uint32_t boffq = (uint32_t)(((j & 1) * 8 + rj) * QP_B + wn * 32 + (j >> 1) * 16);

        for (int dc = 0; dc < 12; ++dc) {
            uint32_t qs = sb + QT_OFF + (uint32_t)(dc & 1) * QSTG_B;
            if (dc + 1 < 12) {
                uint32_t nq = sb + QT_OFF + (uint32_t)((dc + 1) & 1) * QSTG_B;
                int koff = (dc + 1) * 64;
#pragma unroll
                for (int i = 0; i < 4; ++i) {
                    int idx = tid + i * 256;
                    int row = idx >> 3;
                    int c   = idx & 7;
                    uint32_t d = nq + (uint32_t)(row * QP_B + c * 16);
                    size_t so = (size_t)row * DHID + koff + c * 8;
                    cp16(d, Q_h + so);
                    cp16(d + 18432, Q_l + so);
                }
                CP_COMMIT();
                CP_WAIT1();
            } else {
                CP_WAIT0();
            }
            __syncthreads();

            float acc[4][2][4];
#pragma unroll
            for (int mi = 0; mi < 4; ++mi)
#pragma unroll
                for (int ni = 0; ni < 2; ++ni)
#pragma unroll
                    for (int r = 0; r < 4; ++r) acc[mi][ni][r] = 0.0f;

#pragma unroll
            for (int ks = 0; ks < 8; ++ks) {
                uint32_t ka = (uint32_t)ks * 32;
                uint32_t kq = (uint32_t)ks * 16 * QP_B;
                uint32_t ah[4][4], al[4][4];
#pragma unroll
                for (int mi = 0; mi < 4; ++mi)
                    ldsm4(ah[mi][0], ah[mi][1], ah[mi][2], ah[mi][3],
                          sb + AH_OFF + aoff3[mi] + ka);
#pragma unroll
                for (int mi = 0; mi < 4; ++mi)
                    ldsm4(al[mi][0], al[mi][1], al[mi][2], al[mi][3],
                          sb + AL_OFF + aoff3[mi] + ka);
                uint32_t bh[2][2], bl[2][2];
                {
                    uint32_t r0, r1, r2, r3;
                    ldsm4t(r0, r1, r2, r3, qs + boffq + kq);
                    bh[0][0] = r0; bh[0][1] = r1; bh[1][0] = r2; bh[1][1] = r3;
                    ldsm4t(r0, r1, r2, r3, qs + 18432 + boffq + kq);
                    bl[0][0] = r0; bl[0][1] = r1; bl[1][0] = r2; bl[1][1] = r3;
                }
#pragma unroll
                for (int mi = 0; mi < 4; ++mi)
#pragma unroll
                    for (int ni = 0; ni < 2; ++ni) {
                        mma16816(acc[mi][ni], ah[mi][0], ah[mi][1], ah[mi][2], ah[mi][3],
                                 bh[ni][0], bh[ni][1]);
                        mma16816(acc[mi][ni], al[mi][0], al[mi][1], al[mi][2], al[mi][3],
                                 bh[ni][0], bh[ni][1]);
                        mma16816(acc[mi][ni], ah[mi][0], ah[mi][1], ah[mi][2], ah[mi][3],
                                 bl[ni][0], bl[ni][1]);
                    }
            }

            const int rGrp = lane >> 2;
            const int cGrp = (lane & 3) * 2;
#pragma unroll
            for (int mi = 0; mi < 4; ++mi) {
                size_t gr = (size_t)b * NLP + pBase + wm * 64 + mi * 16 + rGrp;
#pragma unroll
                for (int ni = 0; ni < 2; ++ni) {
                    int d = dc * 64 + wn * 16 + ni * 8 + cGrp;
                    float2 v0 = {acc[mi][ni][0], acc[mi][ni][1]};
                    float2 v1 = {acc[mi][ni][2], acc[mi][ni][3]};
                    *(float2*)(out + gr * DHID + d)       = v0;
                    *(float2*)(out + (gr + 8) * DHID + d) = v1;
                }
            }
            __syncthreads();
        }
    }
}

// ---------------------------------------------------------------------------
extern "C" void kernel_launch(void* const* d_in, const int* in_sizes, int n_in,
                              void* d_out, int out_size) {
    const float* passage  = (const float*)d_in[0];
    const float* question = (const float*)d_in[2];
    const unsigned char* qmask = (const unsigned char*)d_in[3];
    const float* Ww = (const float*)d_in[4];
    const float* Wb = (const float*)d_in[5];
    float* out = (float*)d_out;

    __nv_bfloat16 *qh, *ql, *wth, *wtl, *wph, *wpl, *wqh, *wql;
    cudaGetSymbolAddress((void**)&qh,  g_Qh);
    cudaGetSymbolAddress((void**)&ql,  g_Ql);
    cudaGetSymbolAddress((void**)&wth, g_Wth);
    cudaGetSymbolAddress((void**)&wtl, g_Wtl);
    cudaGetSymbolAddress((void**)&wph, g_Wph);
    cudaGetSymbolAddress((void**)&wpl, g_Wpl);
    cudaGetSymbolAddress((void**)&wqh, g_Wqh);
    cudaGetSymbolAddress((void**)&wql, g_Wql);

    mask_prep_kernel<<<1, 256>>>(qmask, NB * NLQ);

    int nq4 = NB * NLQ * DHID / 4;
    split_kernel<<<(nq4 + 255) / 256, 256>>>((const float4*)question,
                                             (__nv_bfloat162*)qh, (__nv_bfloat162*)ql, nq4);
    wsplit_kernel<<<dim3(DHID / 32, DHID / 32), dim3(32, 8)>>>(Ww, wth, wtl);

    cudaFuncSetAttribute(gemm_mma_kernel, cudaFuncAttributeMaxDynamicSharedMemorySize, GSMEM);
    gemm_mma_kernel<<<dim3(DHID / 128, YP + (NB * NLQ) / 128), 256, GSMEM>>>(
        passage, question, wth, wtl, Wb, wph, wpl, wqh, wql);

    cudaFuncSetAttribute(attn_tc_kernel, cudaFuncAttributeMaxDynamicSharedMemorySize, ASMEM);
    attn_tc_kernel<<<dim3(NLP / 128, NB), 256, ASMEM>>>(wph, wpl, wqh, wql, qh, ql, out);
}

// round 9
// speedup vs baseline: 2.7885x; 1.0984x over previous
#include <cuda_runtime.h>
#include <cuda_bf16.h>
#include <math.h>
#include <stdint.h>
#include <stddef.h>

#define DHID 768
#define NB   64
#define NLP  1024
#define NLQ  128

// ---------------- scratch (__device__ globals; allocation-free rule) --------
__device__ float g_qbias[NB * NLQ];
__device__ __align__(16) __nv_bfloat16 g_Ph[(size_t)NB * NLP * DHID];
__device__ __align__(16) __nv_bfloat16 g_Pl[(size_t)NB * NLP * DHID];
__device__ __align__(16) __nv_bfloat16 g_Qh[(size_t)NB * NLQ * DHID];
__device__ __align__(16) __nv_bfloat16 g_Ql[(size_t)NB * NLQ * DHID];
__device__ __align__(16) __nv_bfloat16 g_Wth[DHID * DHID];   // W^T hi [n][k]
__device__ __align__(16) __nv_bfloat16 g_Wtl[DHID * DHID];   // W^T lo [n][k]
__device__ __align__(16) __nv_bfloat16 g_Wph[(size_t)NB * NLP * DHID];
__device__ __align__(16) __nv_bfloat16 g_Wpl[(size_t)NB * NLP * DHID];
__device__ __align__(16) __nv_bfloat16 g_Wqh[(size_t)NB * NLQ * DHID];
__device__ __align__(16) __nv_bfloat16 g_Wql[(size_t)NB * NLQ * DHID];

// ---------------- small asm helpers ----------------------------------------
__device__ __forceinline__ uint32_t smem_u32(const void* p) {
    uint32_t a;
    asm("{ .reg .u64 t; cvta.to.shared.u64 t, %1; cvt.u32.u64 %0, t; }" : "=r"(a) : "l"(p));
    return a;
}
__device__ __forceinline__ void cp16(uint32_t dst, const void* src) {
    asm volatile("cp.async.cg.shared.global [%0], [%1], 16;" :: "r"(dst), "l"(src));
}
#define CP_COMMIT() asm volatile("cp.async.commit_group;" ::: "memory")
#define CP_WAIT1()  asm volatile("cp.async.wait_group 1;" ::: "memory")
#define CP_WAIT0()  asm volatile("cp.async.wait_group 0;" ::: "memory")

__device__ __forceinline__ void ldsm4(uint32_t& r0, uint32_t& r1, uint32_t& r2,
                                      uint32_t& r3, uint32_t a) {
    asm volatile("ldmatrix.sync.aligned.m8n8.x4.shared.b16 {%0,%1,%2,%3}, [%4];"
                 : "=r"(r0), "=r"(r1), "=r"(r2), "=r"(r3) : "r"(a));
}
__device__ __forceinline__ void ldsm4t(uint32_t& r0, uint32_t& r1, uint32_t& r2,
                                       uint32_t& r3, uint32_t a) {
    asm volatile("ldmatrix.sync.aligned.m8n8.x4.trans.shared.b16 {%0,%1,%2,%3}, [%4];"
                 : "=r"(r0), "=r"(r1), "=r"(r2), "=r"(r3) : "r"(a));
}
__device__ __forceinline__ void mma16816(float* c, uint32_t a0, uint32_t a1,
                                         uint32_t a2, uint32_t a3,
                                         uint32_t b0, uint32_t b1) {
    asm volatile("mma.sync.aligned.m16n8k16.row.col.f32.bf16.bf16.f32 "
                 "{%0,%1,%2,%3}, {%4,%5,%6,%7}, {%8,%9}, {%0,%1,%2,%3};"
                 : "+f"(c[0]), "+f"(c[1]), "+f"(c[2]), "+f"(c[3])
                 : "r"(a0), "r"(a1), "r"(a2), "r"(a3), "r"(b0), "r"(b1));
}
__device__ __forceinline__ void split2(float v, __nv_bfloat16& h, __nv_bfloat16& l) {
    h = __float2bfloat16(v);
    l = __float2bfloat16(v - __bfloat162float(h));
}

// ---------------- mask prep (dtype-sniffing) --------------------------------
__global__ void mask_prep_kernel(const unsigned char* __restrict__ qm, int n) {
    __shared__ int mode;
    if (threadIdx.x == 0) mode = 0;
    __syncthreads();
    for (int i = threadIdx.x; i < n; i += blockDim.x) {
        int r = i & 3;
        unsigned char c = qm[i];
        if (r != 0 && c != 0) {
            if (r == 3 && c == 0x3F) atomicMax(&mode, 2);
            else                     atomicMax(&mode, 1);
        }
    }
    __syncthreads();
    int m = mode;
    for (int i = threadIdx.x; i < n; i += blockDim.x) {
        int v;
        if (m == 2)      v = (((const float*)(const void*)qm)[i] != 0.0f);
        else if (m == 1) v = (qm[i] != 0);
        else             v = (((const int*)(const void*)qm)[i] != 0);
        g_qbias[i] = v ? -1e30f : 0.0f;
    }
}

// ---------------- fp32 -> (hi,lo) bf16 split --------------------------------
__global__ void split_kernel(const float4* __restrict__ x,
                             __nv_bfloat162* __restrict__ h,
                             __nv_bfloat162* __restrict__ l, int n4) {
    int i = blockIdx.x * blockDim.x + threadIdx.x;
    if (i >= n4) return;
    float4 v = x[i];
    __nv_bfloat16 h0, h1, h2, h3, l0, l1, l2, l3;
    split2(v.x, h0, l0); split2(v.y, h1, l1);
    split2(v.z, h2, l2); split2(v.w, h3, l3);
    h[i * 2]     = __nv_bfloat162(h0, h1);
    h[i * 2 + 1] = __nv_bfloat162(h2, h3);
    l[i * 2]     = __nv_bfloat162(l0, l1);
    l[i * 2 + 1] = __nv_bfloat162(l2, l3);
}

// ---------------- W[k][n] -> W^T split (hi/lo) ------------------------------
__global__ void wsplit_kernel(const float* __restrict__ W,
                              __nv_bfloat16* __restrict__ Wth,
                              __nv_bfloat16* __restrict__ Wtl) {
    __shared__ float t[32][33];
    int bx = blockIdx.x * 32;  // k
    int by = blockIdx.y * 32;  // n
    for (int yy = threadIdx.y; yy < 32; yy += 8)
        t[yy][threadIdx.x] = W[(size_t)(bx + yy) * DHID + by + threadIdx.x];
    __syncthreads();
    for (int yy = threadIdx.y; yy < 32; yy += 8) {
        float v = t[threadIdx.x][yy];
        __nv_bfloat16 h, l;
        split2(v, h, l);
        size_t o = (size_t)(by + yy) * DHID + bx + threadIdx.x;
        Wth[o] = h;
        Wtl[o] = l;
    }
}

// ---------------- common tiling constants -----------------------------------
#define GP_B      80
#define ARR_B     (128 * GP_B)
#define O_AH      0
#define O_AL      (1 * ARR_B)
#define O_BH      (2 * ARR_B)
#define O_BL      (3 * ARR_B)
#define STAGE_B   (4 * ARR_B)         // 40960
#define NCHUNK    (DHID / 32)         // 24

__device__ __forceinline__ void load_stage(uint32_t dst, int kc, int tid,
                                           const __nv_bfloat16* __restrict__ A_h,
                                           const __nv_bfloat16* __restrict__ A_l,
                                           const __nv_bfloat16* __restrict__ B_h,
                                           const __nv_bfloat16* __restrict__ B_l) {
#pragma unroll
    for (int i = 0; i < 2; ++i) {
        int idx = tid + i * 256;
        int row = idx >> 2;
        int c   = idx & 3;
        uint32_t d = dst + (uint32_t)(row * GP_B + c * 16);
        size_t so = (size_t)row * DHID + kc + c * 8;
        cp16(d + O_AH, A_h + so);
        cp16(d + O_AL, A_l + so);
        cp16(d + O_BH, B_h + so);
        cp16(d + O_BL, B_l + so);
    }
}

// 3-product split-bf16 mainloop chunk (2 k16 steps), accumulate into acc[4][4][4]
__device__ __forceinline__ void mma_chunk(uint32_t st, const uint32_t* aoff,
                                          const uint32_t* boff, float acc[4][4][4]) {
#pragma unroll
    for (int ks = 0; ks < 2; ++ks) {
        uint32_t k2 = (uint32_t)ks * 32;
        uint32_t ah[4][4], al[4][4], bh[4][2], bl[4][2];
#pragma unroll
        for (int mi = 0; mi < 4; ++mi)
            ldsm4(ah[mi][0], ah[mi][1], ah[mi][2], ah[mi][3], st + O_AH + aoff[mi] + k2);
#pragma unroll
        for (int mi = 0; mi < 4; ++mi)
            ldsm4(al[mi][0], al[mi][1], al[mi][2], al[mi][3], st + O_AL + aoff[mi] + k2);
#pragma unroll
        for (int p = 0; p < 2; ++p) {
            uint32_t r0, r1, r2, r3;
            ldsm4(r0, r1, r2, r3, st + O_BH + boff[p] + k2);
            bh[p * 2][0] = r0; bh[p * 2][1] = r1;
            bh[p * 2 + 1][0] = r2; bh[p * 2 + 1][1] = r3;
            ldsm4(r0, r1, r2, r3, st + O_BL + boff[p] + k2);
            bl[p * 2][0] = r0; bl[p * 2][1] = r1;
            bl[p * 2 + 1][0] = r2; bl[p * 2 + 1][1] = r3;
        }
#pragma unroll
        for (int mi = 0; mi < 4; ++mi)
#pragma unroll
            for (int ni = 0; ni < 4; ++ni) {
                mma16816(acc[mi][ni], ah[mi][0], ah[mi][1], ah[mi][2], ah[mi][3],
                         bh[ni][0], bh[ni][1]);
                mma16816(acc[mi][ni], al[mi][0], al[mi][1], al[mi][2], al[mi][3],
                         bh[ni][0], bh[ni][1]);
                mma16816(acc[mi][ni], ah[mi][0], ah[mi][1], ah[mi][2], ah[mi][3],
                         bl[ni][0], bl[ni][1]);
            }
    }
}

// ---------------- merged projection GEMM: 2-stage, 2 CTAs/SM ----------------
#define GSMEM (2 * STAGE_B + 512)     // 82432
#define YP    ((NB * NLP) / 128)      // 512 P row-blocks

__global__ __launch_bounds__(256, 2)
void gemm_mma_kernel(const __nv_bfloat16* __restrict__ Ph,
                     const __nv_bfloat16* __restrict__ Pl,
                     const __nv_bfloat16* __restrict__ Qh,
                     const __nv_bfloat16* __restrict__ Ql,
                     const __nv_bfloat16* __restrict__ Bh,
                     const __nv_bfloat16* __restrict__ Bl,
                     const float* __restrict__ bias,
                     __nv_bfloat16* __restrict__ Ph_out,
                     __nv_bfloat16* __restrict__ Pl_out,
                     __nv_bfloat16* __restrict__ Qh_out,
                     __nv_bfloat16* __restrict__ Ql_out) {
    extern __shared__ char smem[];
    uint32_t sb = smem_u32(smem);
    float* bias_s = (float*)(smem + 2 * STAGE_B);

    const int tid  = threadIdx.x;
    const int w    = tid >> 5;
    const int lane = tid & 31;
    const int wm   = w >> 2;
    const int wn   = w & 3;
    const int yb   = blockIdx.y;
    const bool isQ = (yb >= YP);
    const size_t mBase = (size_t)(isQ ? yb - YP : yb) * 128;
    const int    nBase = blockIdx.x * 128;

    if (tid < 128) bias_s[tid] = bias[nBase + tid];

    const __nv_bfloat16* A_h = (isQ ? Qh : Ph) + mBase * DHID;
    const __nv_bfloat16* A_l = (isQ ? Ql : Pl) + mBase * DHID;
    const __nv_bfloat16* B_h = Bh + (size_t)nBase * DHID;
    const __nv_bfloat16* B_l = Bl + (size_t)nBase * DHID;
    __nv_bfloat16* Ch = isQ ? Qh_out : Ph_out;
    __nv_bfloat16* Cl = isQ ? Ql_out : Pl_out;

    const int j  = lane >> 3;
    const int rj = lane & 7;
    uint32_t aoff[4], boff[2];
#pragma unroll
    for (int mi = 0; mi < 4; ++mi)
        aoff[mi] = (uint32_t)((wm * 64 + mi * 16 + (j & 1) * 8 + rj) * GP_B + (j >> 1) * 16);
#pragma unroll
    for (int p = 0; p < 2; ++p)
        boff[p] = (uint32_t)((wn * 32 + p * 16 + (j >> 1) * 8 + rj) * GP_B + (j & 1) * 16);

    float acc[4][4][4];
#pragma unroll
    for (int mi = 0; mi < 4; ++mi)
#pragma unroll
        for (int ni = 0; ni < 4; ++ni)
#pragma unroll
            for (int r = 0; r < 4; ++r) acc[mi][ni][r] = 0.0f;

    // 2-stage pipeline, 1 sync per chunk:
    //   WAIT0(load t done) ; sync(stage (t+1)%2 free) ; issue load(t+1) ; mma(t)
    load_stage(sb + 0 * STAGE_B, 0, tid, A_h, A_l, B_h, B_l);
    CP_COMMIT();

    for (int t = 0; t < NCHUNK; ++t) {
        CP_WAIT0();
        __syncthreads();
        if (t + 1 < NCHUNK) {
            load_stage(sb + (uint32_t)((t + 1) & 1) * STAGE_B, (t + 1) * 32, tid,
                       A_h, A_l, B_h, B_l);
            CP_COMMIT();
        }
        mma_chunk(sb + (uint32_t)(t & 1) * STAGE_B, aoff, boff, acc);
    }

    // epilogue: bias + relu, split hi/lo bf16 store
    const int rGrp = lane >> 2;
    const int cGrp = (lane & 3) * 2;
#pragma unroll
    for (int mi = 0; mi < 4; ++mi) {
        size_t gr = mBase + wm * 64 + mi * 16 + rGrp;
#pragma unroll
        for (int ni = 0; ni < 4; ++ni) {
            int lc = wn * 32 + ni * 8 + cGrp;
            float b0 = bias_s[lc], b1 = bias_s[lc + 1];
            float v0 = fmaxf(acc[mi][ni][0] + b0, 0.0f);
            float v1 = fmaxf(acc[mi][ni][1] + b1, 0.0f);
            float v2 = fmaxf(acc[mi][ni][2] + b0, 0.0f);
            float v3 = fmaxf(acc[mi][ni][3] + b1, 0.0f);
            __nv_bfloat16 h0, h1, h2, h3, l0, l1, l2, l3;
            split2(v0, h0, l0); split2(v1, h1, l1);
            split2(v2, h2, l2); split2(v3, h3, l3);
            size_t o0 = gr * DHID + nBase + lc;
            size_t o1 = (gr + 8) * DHID + nBase + lc;
            *(__nv_bfloat162*)(Ch + o0) = __nv_bfloat162(h0, h1);
            *(__nv_bfloat162*)(Cl + o0) = __nv_bfloat162(l0, l1);
            *(__nv_bfloat162*)(Ch + o1) = __nv_bfloat162(h2, h3);
            *(__nv_bfloat162*)(Cl + o1) = __nv_bfloat162(l2, l3);
        }
    }
}

// ---------------- tensor-core fused attention --------------------------------
#define SCP      132
#define SC_OFF   0
#define ST_OFF   67584
#define AH_OFF   67584
#define AL_OFF   102400
#define AP_B     272
#define QT_OFF   137216
#define QSTG_B   36864
#define QP_B     144
#define QB_OFF   210944
#define RED_OFF  211456
#define ASMEM    213504

__device__ __forceinline__ void load_stage_a(uint32_t dst, int kc, int tid,
                                             const __nv_bfloat16* __restrict__ A_h,
                                             const __nv_bfloat16* __restrict__ A_l,
                                             const __nv_bfloat16* __restrict__ B_h,
                                             const __nv_bfloat16* __restrict__ B_l) {
#pragma unroll
    for (int i = 0; i < 2; ++i) {
        int idx = tid + i * 256;
        int row = idx >> 2;
        int c   = idx & 3;
        uint32_t d = dst + (uint32_t)(row * GP_B + c * 16);
        size_t so = (size_t)row * DHID + kc + c * 8;
        cp16(d + O_AH, A_h + so);
        cp16(d + O_AL, A_l + so);
        cp16(d + O_BH, B_h + so);
        cp16(d + O_BL, B_l + so);
    }
}

__global__ __launch_bounds__(256)
void attn_tc_kernel(const __nv_bfloat16* __restrict__ Wph,
                    const __nv_bfloat16* __restrict__ Wpl,
                    const __nv_bfloat16* __restrict__ Wqh,
                    const __nv_bfloat16* __restrict__ Wql,
                    const __nv_bfloat16* __restrict__ Qh,
                    const __nv_bfloat16* __restrict__ Ql,
                    float* __restrict__ out) {
    extern __shared__ char smem[];
    uint32_t sb = smem_u32(smem);
    float* sc = (float*)(smem + SC_OFF);
    float* qb = (float*)(smem + QB_OFF);
    float* red  = (float*)(smem + RED_OFF);        // 256
    float* red2 = red + 256;                       // 256

    const int tid  = threadIdx.x;
    const int w    = tid >> 5;
    const int lane = tid & 31;
    const int wm   = w >> 2;
    const int wn   = w & 3;
    const int b    = blockIdx.y;
    const int pBase = blockIdx.x * 128;

    if (tid < 128) qb[tid] = g_qbias[b * NLQ + tid];

    const __nv_bfloat16* A_h = Wph + ((size_t)b * NLP + pBase) * DHID;
    const __nv_bfloat16* A_l = Wpl + ((size_t)b * NLP + pBase) * DHID;
    const __nv_bfloat16* B_h = Wqh + (size_t)b * NLQ * DHID;
    const __nv_bfloat16* B_l = Wql + (size_t)b * NLQ * DHID;
    const __nv_bfloat16* Q_h = Qh + (size_t)b * NLQ * DHID;
    const __nv_bfloat16* Q_l = Ql + (size_t)b * NLQ * DHID;

    const int j  = lane >> 3;
    const int rj = lane & 7;

    // ---- phase 1: scores = Wp @ Wq^T (split-bf16) ----
    {
        uint32_t aoff[4], boff[2];
#pragma unroll
        for (int mi = 0; mi < 4; ++mi)
            aoff[mi] = (uint32_t)((wm * 64 + mi * 16 + (j & 1) * 8 + rj) * GP_B + (j >> 1) * 16);
#pragma unroll
        for (int p = 0; p < 2; ++p)
            boff[p] = (uint32_t)((wn * 32 + p * 16 + (j >> 1) * 8 + rj) * GP_B + (j & 1) * 16);

        float acc[4][4][4];
#pragma unroll
        for (int mi = 0; mi < 4; ++mi)
#pragma unroll
            for (int ni = 0; ni < 4; ++ni)
#pragma unroll
                for (int r = 0; r < 4; ++r) acc[mi][ni][r] = 0.0f;

        load_stage_a(sb + ST_OFF + 0 * STAGE_B, 0, tid, A_h, A_l, B_h, B_l);
        CP_COMMIT();
        load_stage_a(sb + ST_OFF + 1 * STAGE_B, 32, tid, A_h, A_l, B_h, B_l);
        CP_COMMIT();

        for (int t = 0; t < NCHUNK; ++t) {
            if (t + 1 < NCHUNK) CP_WAIT1(); else CP_WAIT0();
            __syncthreads();
            if (t + 2 < NCHUNK) {
                load_stage_a(sb + ST_OFF + (uint32_t)((t + 2) % 3) * STAGE_B,
                             (t + 2) * 32, tid, A_h, A_l, B_h, B_l);
                CP_COMMIT();
            }
            mma_chunk(sb + ST_OFF + (uint32_t)(t % 3) * STAGE_B, aoff, boff, acc);
        }
        __syncthreads();

        const int rGrp = lane >> 2;
        const int cGrp = (lane & 3) * 2;
#pragma unroll
        for (int mi = 0; mi < 4; ++mi) {
            int pr = wm * 64 + mi * 16 + rGrp;
#pragma unroll
            for (int ni = 0; ni < 4; ++ni) {
                int q0 = wn * 32 + ni * 8 + cGrp;
                float b0 = qb[q0], b1 = qb[q0 + 1];
                sc[pr * SCP + q0]           = acc[mi][ni][0] + b0;
                sc[pr * SCP + q0 + 1]       = acc[mi][ni][1] + b1;
                sc[(pr + 8) * SCP + q0]     = acc[mi][ni][2] + b0;
                sc[(pr + 8) * SCP + q0 + 1] = acc[mi][ni][3] + b1;
            }
        }
    }
    __syncthreads();

    // prefetch first Q tile while softmax runs
    {
#pragma unroll
        for (int i = 0; i < 4; ++i) {
            int idx = tid + i * 256;
            int row = idx >> 3;
            int c   = idx & 7;
            uint32_t d = sb + QT_OFF + (uint32_t)(row * QP_B + c * 16);
            size_t so = (size_t)row * DHID + c * 8;
            cp16(d, Q_h + so);
            cp16(d + 18432, Q_l + so);
        }
        CP_COMMIT();
    }

    // ---- phase 2: softmax per p-row, 2 threads per row ----
    {
        int r    = tid & 127;
        int half = tid >> 7;
        float* row = sc + r * SCP + half * 64;
        float mx = -INFINITY;
#pragma unroll 8
        for (int c = 0; c < 64; ++c) mx = fmaxf(mx, row[c]);
        red[tid] = mx;
        __syncthreads();
        float m = fmaxf(red[r], red[r + 128]);
        float s = 0.0f;
#pragma unroll 8
        for (int c = 0; c < 64; ++c) {
            float e = __expf(row[c] - m);
            row[c] = e;
            s += e;
        }
        red2[tid] = s;
        __syncthreads();
        float inv = 1.0f / (red2[r] + red2[r + 128]);
#pragma unroll 8
        for (int c = 0; c < 64; ++c) row[c] *= inv;
    }
    __syncthreads();

    // alpha -> bf16 hi/lo (smem)
    {
        for (int i = tid; i < 128 * 32; i += 256) {
            int p  = i >> 5;
            int q4 = (i & 31) * 4;
            float4 v = *(float4*)&sc[p * SCP + q4];
            __nv_bfloat16 h0, h1, h2, h3, l0, l1, l2, l3;
            split2(v.x, h0, l0); split2(v.y, h1, l1);
            split2(v.z, h2, l2); split2(v.w, h3, l3);
            __nv_bfloat162* ph = (__nv_bfloat162*)(smem + AH_OFF + p * AP_B + q4 * 2);
            __nv_bfloat162* pl = (__nv_bfloat162*)(smem + AL_OFF + p * AP_B + q4 * 2);
            ph[0] = __nv_bfloat162(h0, h1); ph[1] = __nv_bfloat162(h2, h3);
            pl[0] = __nv_bfloat162(l0, l1); pl[1] = __nv_bfloat162(l2, l3);
        }
    }
    __syncthreads();

    // ---- phase 3: out = alpha @ question ----
    {
        uint32_t aoff3[4];
#pragma unroll
        for (int mi = 0; mi < 4; ++mi)
            aoff3[mi] = (uint32_t)((wm * 64 + mi * 16 + (j & 1) * 8 + rj) * AP_B + (j >> 1) * 16);
        uint32_t boffq = (uint32_t)(((j & 1) * 8 + rj) * QP_B + wn * 32 + (j >> 1) * 16);

        for (int dc = 0; dc < 12; ++dc) {
            uint32_t qs = sb + QT_OFF + (uint32_t)(dc & 1) * QSTG_B;
            if (dc + 1 < 12) {
                uint32_t nq = sb + QT_OFF + (uint32_t)((dc + 1) & 1) * QSTG_B;
                int koff = (dc + 1) * 64;
#pragma unroll
                for (int i = 0; i < 4; ++i) {
                    int idx = tid + i * 256;
                    int row = idx >> 3;
                    int c   = idx & 7;
                    uint32_t d = nq + (uint32_t)(row * QP_B + c * 16);
                    size_t so = (size_t)row * DHID + koff + c * 8;
                    cp16(d, Q_h + so);
                    cp16(d + 18432, Q_l + so);
                }
                CP_COMMIT();
                CP_WAIT1();
            } else {
                CP_WAIT0();
            }
            __syncthreads();

            float acc[4][2][4];
#pragma unroll
            for (int mi = 0; mi < 4; ++mi)
#pragma unroll
                for (int ni = 0; ni < 2; ++ni)
#pragma unroll
                    for (int r = 0; r < 4; ++r) acc[mi][ni][r] = 0.0f;

#pragma unroll
            for (int ks = 0; ks < 8; ++ks) {
                uint32_t ka = (uint32_t)ks * 32;
                uint32_t kq = (uint32_t)ks * 16 * QP_B;
                uint32_t ah[4][4], al[4][4];
#pragma unroll
                for (int mi = 0; mi < 4; ++mi)
                    ldsm4(ah[mi][0], ah[mi][1], ah[mi][2], ah[mi][3],
                          sb + AH_OFF + aoff3[mi] + ka);
#pragma unroll
                for (int mi = 0; mi < 4; ++mi)
                    ldsm4(al[mi][0], al[mi][1], al[mi][2], al[mi][3],
                          sb + AL_OFF + aoff3[mi] + ka);
                uint32_t bh[2][2], bl[2][2];
                {
                    uint32_t r0, r1, r2, r3;
                    ldsm4t(r0, r1, r2, r3, qs + boffq + kq);
                    bh[0][0] = r0; bh[0][1] = r1; bh[1][0] = r2; bh[1][1] = r3;
                    ldsm4t(r0, r1, r2, r3, qs + 18432 + boffq + kq);
                    bl[0][0] = r0; bl[0][1] = r1; bl[1][0] = r2; bl[1][1] = r3;
                }
#pragma unroll
                for (int mi = 0; mi < 4; ++mi)
#pragma unroll
                    for (int ni = 0; ni < 2; ++ni) {
                        mma16816(acc[mi][ni], ah[mi][0], ah[mi][1], ah[mi][2], ah[mi][3],
                                 bh[ni][0], bh[ni][1]);
                        mma16816(acc[mi][ni], al[mi][0], al[mi][1], al[mi][2], al[mi][3],
                                 bh[ni][0], bh[ni][1]);
                        mma16816(acc[mi][ni], ah[mi][0], ah[mi][1], ah[mi][2], ah[mi][3],
                                 bl[ni][0], bl[ni][1]);
                    }
            }

            const int rGrp = lane >> 2;
            const int cGrp = (lane & 3) * 2;
#pragma unroll
            for (int mi = 0; mi < 4; ++mi) {
                size_t gr = (size_t)b * NLP + pBase + wm * 64 + mi * 16 + rGrp;
#pragma unroll
                for (int ni = 0; ni < 2; ++ni) {
                    int d = dc * 64 + wn * 16 + ni * 8 + cGrp;
                    float2 v0 = {acc[mi][ni][0], acc[mi][ni][1]};
                    float2 v1 = {acc[mi][ni][2], acc[mi][ni][3]};
                    *(float2*)(out + gr * DHID + d)       = v0;
                    *(float2*)(out + (gr + 8) * DHID + d) = v1;
                }
            }
            __syncthreads();
        }
    }
}

// ---------------------------------------------------------------------------
extern "C" void kernel_launch(void* const* d_in, const int* in_sizes, int n_in,
                              void* d_out, int out_size) {
    const float* passage  = (const float*)d_in[0];
    const float* question = (const float*)d_in[2];
    const unsigned char* qmask = (const unsigned char*)d_in[3];
    const float* Ww = (const float*)d_in[4];
    const float* Wb = (const float*)d_in[5];
    float* out = (float*)d_out;

    __nv_bfloat16 *ph, *pl, *qh, *ql, *wth, *wtl, *wph, *wpl, *wqh, *wql;
    cudaGetSymbolAddress((void**)&ph,  g_Ph);
    cudaGetSymbolAddress((void**)&pl,  g_Pl);
    cudaGetSymbolAddress((void**)&qh,  g_Qh);
    cudaGetSymbolAddress((void**)&ql,  g_Ql);
    cudaGetSymbolAddress((void**)&wth, g_Wth);
    cudaGetSymbolAddress((void**)&wtl, g_Wtl);
    cudaGetSymbolAddress((void**)&wph, g_Wph);
    cudaGetSymbolAddress((void**)&wpl, g_Wpl);
    cudaGetSymbolAddress((void**)&wqh, g_Wqh);
    cudaGetSymbolAddress((void**)&wql, g_Wql);

    mask_prep_kernel<<<1, 256>>>(qmask, NB * NLQ);

    int np4 = NB * NLP * DHID / 4;
    int nq4 = NB * NLQ * DHID / 4;
    split_kernel<<<(np4 + 255) / 256, 256>>>((const float4*)passage,
                                             (__nv_bfloat162*)ph, (__nv_bfloat162*)pl, np4);
    split_kernel<<<(nq4 + 255) / 256, 256>>>((const float4*)question,
                                             (__nv_bfloat162*)qh, (__nv_bfloat162*)ql, nq4);
    wsplit_kernel<<<dim3(DHID / 32, DHID / 32), dim3(32, 8)>>>(Ww, wth, wtl);

    cudaFuncSetAttribute(gemm_mma_kernel, cudaFuncAttributeMaxDynamicSharedMemorySize, GSMEM);
    gemm_mma_kernel<<<dim3(DHID / 128, YP + (NB * NLQ) / 128), 256, GSMEM>>>(
        ph, pl, qh, ql, wth, wtl, Wb, wph, wpl, wqh, wql);

    cudaFuncSetAttribute(attn_tc_kernel, cudaFuncAttributeMaxDynamicSharedMemorySize, ASMEM);
    attn_tc_kernel<<<dim3(NLP / 128, NB), 256, ASMEM>>>(wph, wpl, wqh, wql, qh, ql, out);
}

// round 10
// speedup vs baseline: 2.8256x; 1.0133x over previous
#include <cuda_runtime.h>
#include <cuda_bf16.h>
#include <math.h>
#include <stdint.h>
#include <stddef.h>

#define DHID 768
#define NB   64
#define NLP  1024
#define NLQ  128

// ---------------- scratch (__device__ globals; allocation-free rule) --------
__device__ float g_qbias[NB * NLQ];
__device__ __align__(16) __nv_bfloat16 g_Ph[(size_t)NB * NLP * DHID];
__device__ __align__(16) __nv_bfloat16 g_Pl[(size_t)NB * NLP * DHID];
__device__ __align__(16) __nv_bfloat16 g_Qh[(size_t)NB * NLQ * DHID];
__device__ __align__(16) __nv_bfloat16 g_Ql[(size_t)NB * NLQ * DHID];
__device__ __align__(16) __nv_bfloat16 g_Wth[DHID * DHID];   // W^T hi [n][k]
__device__ __align__(16) __nv_bfloat16 g_Wtl[DHID * DHID];   // W^T lo [n][k]
__device__ __align__(16) __nv_bfloat16 g_Wph[(size_t)NB * NLP * DHID];
__device__ __align__(16) __nv_bfloat16 g_Wpl[(size_t)NB * NLP * DHID];
__device__ __align__(16) __nv_bfloat16 g_Wqh[(size_t)NB * NLQ * DHID];
__device__ __align__(16) __nv_bfloat16 g_Wql[(size_t)NB * NLQ * DHID];

// ---------------- small asm helpers ----------------------------------------
__device__ __forceinline__ uint32_t smem_u32(const void* p) {
    uint32_t a;
    asm("{ .reg .u64 t; cvta.to.shared.u64 t, %1; cvt.u32.u64 %0, t; }" : "=r"(a) : "l"(p));
    return a;
}
__device__ __forceinline__ void cp16(uint32_t dst, const void* src) {
    asm volatile("cp.async.cg.shared.global [%0], [%1], 16;" :: "r"(dst), "l"(src));
}
#define CP_COMMIT() asm volatile("cp.async.commit_group;" ::: "memory")
#define CP_WAIT0()  asm volatile("cp.async.wait_group 0;" ::: "memory")

__device__ __forceinline__ void ldsm4(uint32_t& r0, uint32_t& r1, uint32_t& r2,
                                      uint32_t& r3, uint32_t a) {
    asm volatile("ldmatrix.sync.aligned.m8n8.x4.shared.b16 {%0,%1,%2,%3}, [%4];"
                 : "=r"(r0), "=r"(r1), "=r"(r2), "=r"(r3) : "r"(a));
}
__device__ __forceinline__ void ldsm4t(uint32_t& r0, uint32_t& r1, uint32_t& r2,
                                       uint32_t& r3, uint32_t a) {
    asm volatile("ldmatrix.sync.aligned.m8n8.x4.trans.shared.b16 {%0,%1,%2,%3}, [%4];"
                 : "=r"(r0), "=r"(r1), "=r"(r2), "=r"(r3) : "r"(a));
}
__device__ __forceinline__ void mma16816(float* c, uint32_t a0, uint32_t a1,
                                         uint32_t a2, uint32_t a3,
                                         uint32_t b0, uint32_t b1) {
    asm volatile("mma.sync.aligned.m16n8k16.row.col.f32.bf16.bf16.f32 "
                 "{%0,%1,%2,%3}, {%4,%5,%6,%7}, {%8,%9}, {%0,%1,%2,%3};"
                 : "+f"(c[0]), "+f"(c[1]), "+f"(c[2]), "+f"(c[3])
                 : "r"(a0), "r"(a1), "r"(a2), "r"(a3), "r"(b0), "r"(b1));
}
__device__ __forceinline__ void split2(float v, __nv_bfloat16& h, __nv_bfloat16& l) {
    h = __float2bfloat16(v);
    l = __float2bfloat16(v - __bfloat162float(h));
}

// ---------------- mask prep (dtype-sniffing) --------------------------------
__global__ void mask_prep_kernel(const unsigned char* __restrict__ qm, int n) {
    __shared__ int mode;
    if (threadIdx.x == 0) mode = 0;
    __syncthreads();
    for (int i = threadIdx.x; i < n; i += blockDim.x) {
        int r = i & 3;
        unsigned char c = qm[i];
        if (r != 0 && c != 0) {
            if (r == 3 && c == 0x3F) atomicMax(&mode, 2);
            else                     atomicMax(&mode, 1);
        }
    }
    __syncthreads();
    int m = mode;
    for (int i = threadIdx.x; i < n; i += blockDim.x) {
        int v;
        if (m == 2)      v = (((const float*)(const void*)qm)[i] != 0.0f);
        else if (m == 1) v = (qm[i] != 0);
        else             v = (((const int*)(const void*)qm)[i] != 0);
        g_qbias[i] = v ? -1e30f : 0.0f;
    }
}

// ---------------- fp32 -> (hi,lo) bf16 split --------------------------------
__global__ void split_kernel(const float4* __restrict__ x,
                             __nv_bfloat162* __restrict__ h,
                             __nv_bfloat162* __restrict__ l, int n4) {
    int i = blockIdx.x * blockDim.x + threadIdx.x;
    if (i >= n4) return;
    float4 v = x[i];
    __nv_bfloat16 h0, h1, h2, h3, l0, l1, l2, l3;
    split2(v.x, h0, l0); split2(v.y, h1, l1);
    split2(v.z, h2, l2); split2(v.w, h3, l3);
    h[i * 2]     = __nv_bfloat162(h0, h1);
    h[i * 2 + 1] = __nv_bfloat162(h2, h3);
    l[i * 2]     = __nv_bfloat162(l0, l1);
    l[i * 2 + 1] = __nv_bfloat162(l2, l3);
}

// ---------------- W[k][n] -> W^T split (hi/lo) ------------------------------
__global__ void wsplit_kernel(const float* __restrict__ W,
                              __nv_bfloat16* __restrict__ Wth,
                              __nv_bfloat16* __restrict__ Wtl) {
    __shared__ float t[32][33];
    int bx = blockIdx.x * 32;  // k
    int by = blockIdx.y * 32;  // n
    for (int yy = threadIdx.y; yy < 32; yy += 8)
        t[yy][threadIdx.x] = W[(size_t)(bx + yy) * DHID + by + threadIdx.x];
    __syncthreads();
    for (int yy = threadIdx.y; yy < 32; yy += 8) {
        float v = t[threadIdx.x][yy];
        __nv_bfloat16 h, l;
        split2(v, h, l);
        size_t o = (size_t)(by + yy) * DHID + bx + threadIdx.x;
        Wth[o] = h;
        Wtl[o] = l;
    }
}

// ---------------- common tiling constants -----------------------------------
#define GP_B      80
#define ARR_B     (128 * GP_B)
#define O_AH      0
#define O_AL      (1 * ARR_B)
#define O_BH      (2 * ARR_B)
#define O_BL      (3 * ARR_B)
#define STAGE_B   (4 * ARR_B)         // 40960
#define NCHUNK    (DHID / 32)         // 24

__device__ __forceinline__ void load_stage(uint32_t dst, int kc, int tid,
                                           const __nv_bfloat16* __restrict__ A_h,
                                           const __nv_bfloat16* __restrict__ A_l,
                                           const __nv_bfloat16* __restrict__ B_h,
                                           const __nv_bfloat16* __restrict__ B_l) {
#pragma unroll
    for (int i = 0; i < 2; ++i) {
        int idx = tid + i * 256;
        int row = idx >> 2;
        int c   = idx & 3;
        uint32_t d = dst + (uint32_t)(row * GP_B + c * 16);
        size_t so = (size_t)row * DHID + kc + c * 8;
        cp16(d + O_AH, A_h + so);
        cp16(d + O_AL, A_l + so);
        cp16(d + O_BH, B_h + so);
        cp16(d + O_BL, B_l + so);
    }
}

// 3-product split-bf16 mainloop chunk (2 k16 steps)
__device__ __forceinline__ void mma_chunk(uint32_t st, const uint32_t* aoff,
                                          const uint32_t* boff, float acc[4][4][4]) {
#pragma unroll
    for (int ks = 0; ks < 2; ++ks) {
        uint32_t k2 = (uint32_t)ks * 32;
        uint32_t ah[4][4], al[4][4], bh[4][2], bl[4][2];
#pragma unroll
        for (int mi = 0; mi < 4; ++mi)
            ldsm4(ah[mi][0], ah[mi][1], ah[mi][2], ah[mi][3], st + O_AH + aoff[mi] + k2);
#pragma unroll
        for (int mi = 0; mi < 4; ++mi)
            ldsm4(al[mi][0], al[mi][1], al[mi][2], al[mi][3], st + O_AL + aoff[mi] + k2);
#pragma unroll
        for (int p = 0; p < 2; ++p) {
            uint32_t r0, r1, r2, r3;
            ldsm4(r0, r1, r2, r3, st + O_BH + boff[p] + k2);
            bh[p * 2][0] = r0; bh[p * 2][1] = r1;
            bh[p * 2 + 1][0] = r2; bh[p * 2 + 1][1] = r3;
            ldsm4(r0, r1, r2, r3, st + O_BL + boff[p] + k2);
            bl[p * 2][0] = r0; bl[p * 2][1] = r1;
            bl[p * 2 + 1][0] = r2; bl[p * 2 + 1][1] = r3;
        }
#pragma unroll
        for (int mi = 0; mi < 4; ++mi)
#pragma unroll
            for (int ni = 0; ni < 4; ++ni) {
                mma16816(acc[mi][ni], ah[mi][0], ah[mi][1], ah[mi][2], ah[mi][3],
                         bh[ni][0], bh[ni][1]);
                mma16816(acc[mi][ni], al[mi][0], al[mi][1], al[mi][2], al[mi][3],
                         bh[ni][0], bh[ni][1]);
                mma16816(acc[mi][ni], ah[mi][0], ah[mi][1], ah[mi][2], ah[mi][3],
                         bl[ni][0], bl[ni][1]);
            }
    }
}

// ---------------- merged projection GEMM: 2-stage, 2 CTAs/SM ----------------
#define GSMEM (2 * STAGE_B + 512)     // 82432
#define YP    ((NB * NLP) / 128)      // 512 P row-blocks

__global__ __launch_bounds__(256, 2)
void gemm_mma_kernel(const __nv_bfloat16* __restrict__ Ph,
                     const __nv_bfloat16* __restrict__ Pl,
                     const __nv_bfloat16* __restrict__ Qh,
                     const __nv_bfloat16* __restrict__ Ql,
                     const __nv_bfloat16* __restrict__ Bh,
                     const __nv_bfloat16* __restrict__ Bl,
                     const float* __restrict__ bias,
                     __nv_bfloat16* __restrict__ Ph_out,
                     __nv_bfloat16* __restrict__ Pl_out,
                     __nv_bfloat16* __restrict__ Qh_out,
                     __nv_bfloat16* __restrict__ Ql_out) {
    extern __shared__ char smem[];
    uint32_t sb = smem_u32(smem);
    float* bias_s = (float*)(smem + 2 * STAGE_B);

    const int tid  = threadIdx.x;
    const int w    = tid >> 5;
    const int lane = tid & 31;
    const int wm   = w >> 2;
    const int wn   = w & 3;
    const int yb   = blockIdx.y;
    const bool isQ = (yb >= YP);
    const size_t mBase = (size_t)(isQ ? yb - YP : yb) * 128;
    const int    nBase = blockIdx.x * 128;

    if (tid < 128) bias_s[tid] = bias[nBase + tid];

    const __nv_bfloat16* A_h = (isQ ? Qh : Ph) + mBase * DHID;
    const __nv_bfloat16* A_l = (isQ ? Ql : Pl) + mBase * DHID;
    const __nv_bfloat16* B_h = Bh + (size_t)nBase * DHID;
    const __nv_bfloat16* B_l = Bl + (size_t)nBase * DHID;
    __nv_bfloat16* Ch = isQ ? Qh_out : Ph_out;
    __nv_bfloat16* Cl = isQ ? Ql_out : Pl_out;

    const int j  = lane >> 3;
    const int rj = lane & 7;
    uint32_t aoff[4], boff[2];
#pragma unroll
    for (int mi = 0; mi < 4; ++mi)
        aoff[mi] = (uint32_t)((wm * 64 + mi * 16 + (j & 1) * 8 + rj) * GP_B + (j >> 1) * 16);
#pragma unroll
    for (int p = 0; p < 2; ++p)
        boff[p] = (uint32_t)((wn * 32 + p * 16 + (j >> 1) * 8 + rj) * GP_B + (j & 1) * 16);

    float acc[4][4][4];
#pragma unroll
    for (int mi = 0; mi < 4; ++mi)
#pragma unroll
        for (int ni = 0; ni < 4; ++ni)
#pragma unroll
            for (int r = 0; r < 4; ++r) acc[mi][ni][r] = 0.0f;

    load_stage(sb + 0 * STAGE_B, 0, tid, A_h, A_l, B_h, B_l);
    CP_COMMIT();

    for (int t = 0; t < NCHUNK; ++t) {
        CP_WAIT0();
        __syncthreads();
        if (t + 1 < NCHUNK) {
            load_stage(sb + (uint32_t)((t + 1) & 1) * STAGE_B, (t + 1) * 32, tid,
                       A_h, A_l, B_h, B_l);
            CP_COMMIT();
        }
        mma_chunk(sb + (uint32_t)(t & 1) * STAGE_B, aoff, boff, acc);
    }

    const int rGrp = lane >> 2;
    const int cGrp = (lane & 3) * 2;
#pragma unroll
    for (int mi = 0; mi < 4; ++mi) {
        size_t gr = mBase + wm * 64 + mi * 16 + rGrp;
#pragma unroll
        for (int ni = 0; ni < 4; ++ni) {
            int lc = wn * 32 + ni * 8 + cGrp;
            float b0 = bias_s[lc], b1 = bias_s[lc + 1];
            float v0 = fmaxf(acc[mi][ni][0] + b0, 0.0f);
            float v1 = fmaxf(acc[mi][ni][1] + b1, 0.0f);
            float v2 = fmaxf(acc[mi][ni][2] + b0, 0.0f);
            float v3 = fmaxf(acc[mi][ni][3] + b1, 0.0f);
            __nv_bfloat16 h0, h1, h2, h3, l0, l1, l2, l3;
            split2(v0, h0, l0); split2(v1, h1, l1);
            split2(v2, h2, l2); split2(v3, h3, l3);
            size_t o0 = gr * DHID + nBase + lc;
            size_t o1 = (gr + 8) * DHID + nBase + lc;
            *(__nv_bfloat162*)(Ch + o0) = __nv_bfloat162(h0, h1);
            *(__nv_bfloat162*)(Cl + o0) = __nv_bfloat162(l0, l1);
            *(__nv_bfloat162*)(Ch + o1) = __nv_bfloat162(h2, h3);
            *(__nv_bfloat162*)(Cl + o1) = __nv_bfloat162(l2, l3);
        }
    }
}

// ---------------- tensor-core fused attention: 2 CTAs/SM ---------------------
// smem: [0:40960) phase-1 stage, reused as Q tile (hi@0, lo@18432) in phase 3
//       [40960:75776) alpha hi   (pitch 272)
//       [75776:110592) alpha lo  (pitch 272)
//       [110592:111104) qbias
//       [111104:113152) red scratch (128 rows x 4 warps)
#define AH_OFF   40960
#define AL_OFF   75776
#define AP_B     272
#define QB_OFF   110592
#define RED_OFF  111104
#define ASMEM    113152
#define QP_B     144

__global__ __launch_bounds__(256, 2)
void attn_tc_kernel(const __nv_bfloat16* __restrict__ Wph,
                    const __nv_bfloat16* __restrict__ Wpl,
                    const __nv_bfloat16* __restrict__ Wqh,
                    const __nv_bfloat16* __restrict__ Wql,
                    const __nv_bfloat16* __restrict__ Qh,
                    const __nv_bfloat16* __restrict__ Ql,
                    float* __restrict__ out) {
    extern __shared__ char smem[];
    uint32_t sb = smem_u32(smem);
    float* qb  = (float*)(smem + QB_OFF);
    float* red = (float*)(smem + RED_OFF);

    const int tid  = threadIdx.x;
    const int w    = tid >> 5;
    const int lane = tid & 31;
    const int wm   = w >> 2;
    const int wn   = w & 3;
    const int b    = blockIdx.y;
    const int pBase = blockIdx.x * 128;

    if (tid < 128) qb[tid] = g_qbias[b * NLQ + tid];

    const __nv_bfloat16* A_h = Wph + ((size_t)b * NLP + pBase) * DHID;
    const __nv_bfloat16* A_l = Wpl + ((size_t)b * NLP + pBase) * DHID;
    const __nv_bfloat16* B_h = Wqh + (size_t)b * NLQ * DHID;
    const __nv_bfloat16* B_l = Wql + (size_t)b * NLQ * DHID;
    const __nv_bfloat16* Q_h = Qh + (size_t)b * NLQ * DHID;
    const __nv_bfloat16* Q_l = Ql + (size_t)b * NLQ * DHID;

    const int j  = lane >> 3;
    const int rj = lane & 7;
    const int rGrp = lane >> 2;
    const int cGrp = (lane & 3) * 2;

    // ---- phase 1: scores = Wp @ Wq^T, single-stage pipeline ----
    float acc[4][4][4];
#pragma unroll
    for (int mi = 0; mi < 4; ++mi)
#pragma unroll
        for (int ni = 0; ni < 4; ++ni)
#pragma unroll
            for (int r = 0; r < 4; ++r) acc[mi][ni][r] = 0.0f;
    {
        uint32_t aoff[4], boff[2];
#pragma unroll
        for (int mi = 0; mi < 4; ++mi)
            aoff[mi] = (uint32_t)((wm * 64 + mi * 16 + (j & 1) * 8 + rj) * GP_B + (j >> 1) * 16);
#pragma unroll
        for (int p = 0; p < 2; ++p)
            boff[p] = (uint32_t)((wn * 32 + p * 16 + (j >> 1) * 8 + rj) * GP_B + (j & 1) * 16);

        load_stage(sb, 0, tid, A_h, A_l, B_h, B_l);
        CP_COMMIT();
        for (int t = 0; t < NCHUNK; ++t) {
            CP_WAIT0();
            __syncthreads();
            mma_chunk(sb, aoff, boff, acc);
            __syncthreads();
            if (t + 1 < NCHUNK) {
                load_stage(sb, (t + 1) * 32, tid, A_h, A_l, B_h, B_l);
                CP_COMMIT();
            }
        }
    }

    // ---- phase 2: mask bias + softmax in registers ----
    {
#pragma unroll
        for (int mi = 0; mi < 4; ++mi)
#pragma unroll
            for (int ni = 0; ni < 4; ++ni) {
                int q0 = wn * 32 + ni * 8 + cGrp;
                float b0 = qb[q0], b1 = qb[q0 + 1];
                acc[mi][ni][0] += b0; acc[mi][ni][1] += b1;
                acc[mi][ni][2] += b0; acc[mi][ni][3] += b1;
            }

        // per-thread row maxima over this warp's 8 q-values per row
        float mrow[4][2];
#pragma unroll
        for (int mi = 0; mi < 4; ++mi) {
            mrow[mi][0] = -INFINITY; mrow[mi][1] = -INFINITY;
#pragma unroll
            for (int ni = 0; ni < 4; ++ni) {
                mrow[mi][0] = fmaxf(mrow[mi][0], fmaxf(acc[mi][ni][0], acc[mi][ni][1]));
                mrow[mi][1] = fmaxf(mrow[mi][1], fmaxf(acc[mi][ni][2], acc[mi][ni][3]));
            }
        }
#pragma unroll
        for (int o = 1; o <= 2; o <<= 1)
#pragma unroll
            for (int mi = 0; mi < 4; ++mi) {
                mrow[mi][0] = fmaxf(mrow[mi][0], __shfl_xor_sync(0xFFFFFFFFu, mrow[mi][0], o));
                mrow[mi][1] = fmaxf(mrow[mi][1], __shfl_xor_sync(0xFFFFFFFFu, mrow[mi][1], o));
            }
        if ((lane & 3) == 0)
#pragma unroll
            for (int mi = 0; mi < 4; ++mi) {
                red[(wm * 64 + mi * 16 + rGrp) * 4 + wn]     = mrow[mi][0];
                red[(wm * 64 + mi * 16 + rGrp + 8) * 4 + wn] = mrow[mi][1];
            }
        __syncthreads();
        float M[4][2];
#pragma unroll
        for (int mi = 0; mi < 4; ++mi)
#pragma unroll
            for (int h = 0; h < 2; ++h) {
                const float* rr = &red[(wm * 64 + mi * 16 + rGrp + h * 8) * 4];
                M[mi][h] = fmaxf(fmaxf(rr[0], rr[1]), fmaxf(rr[2], rr[3]));
            }
        __syncthreads();   // before red reuse for sums

        float srow[4][2];
#pragma unroll
        for (int mi = 0; mi < 4; ++mi) { srow[mi][0] = 0.0f; srow[mi][1] = 0.0f; }
#pragma unroll
        for (int mi = 0; mi < 4; ++mi)
#pragma unroll
            for (int ni = 0; ni < 4; ++ni) {
                float e0 = __expf(acc[mi][ni][0] - M[mi][0]);
                float e1 = __expf(acc[mi][ni][1] - M[mi][0]);
                float e2 = __expf(acc[mi][ni][2] - M[mi][1]);
                float e3 = __expf(acc[mi][ni][3] - M[mi][1]);
                acc[mi][ni][0] = e0; acc[mi][ni][1] = e1;
                acc[mi][ni][2] = e2; acc[mi][ni][3] = e3;
                srow[mi][0] += e0 + e1;
                srow[mi][1] += e2 + e3;
            }
#pragma unroll
        for (int o = 1; o <= 2; o <<= 1)
#pragma unroll
            for (int mi = 0; mi < 4; ++mi) {
                srow[mi][0] += __shfl_xor_sync(0xFFFFFFFFu, srow[mi][0], o);
                srow[mi][1] += __shfl_xor_sync(0xFFFFFFFFu, srow[mi][1], o);
            }
        if ((lane & 3) == 0)
#pragma unroll
            for (int mi = 0; mi < 4; ++mi) {
                red[(wm * 64 + mi * 16 + rGrp) * 4 + wn]     = srow[mi][0];
                red[(wm * 64 + mi * 16 + rGrp + 8) * 4 + wn] = srow[mi][1];
            }
        __syncthreads();
        float INV[4][2];
#pragma unroll
        for (int mi = 0; mi < 4; ++mi)
#pragma unroll
            for (int h = 0; h < 2; ++h) {
                const float* rr = &red[(wm * 64 + mi * 16 + rGrp + h * 8) * 4];
                INV[mi][h] = 1.0f / (rr[0] + rr[1] + rr[2] + rr[3]);
            }

        // write alpha hi/lo directly to smem
#pragma unroll
        for (int mi = 0; mi < 4; ++mi) {
            int pr = wm * 64 + mi * 16 + rGrp;
#pragma unroll
            for (int ni = 0; ni < 4; ++ni) {
                int q0 = wn * 32 + ni * 8 + cGrp;
                float a0 = acc[mi][ni][0] * INV[mi][0];
                float a1 = acc[mi][ni][1] * INV[mi][0];
                float a2 = acc[mi][ni][2] * INV[mi][1];
                float a3 = acc[mi][ni][3] * INV[mi][1];
                __nv_bfloat16 h0, h1, h2, h3, l0, l1, l2, l3;
                split2(a0, h0, l0); split2(a1, h1, l1);
                split2(a2, h2, l2); split2(a3, h3, l3);
                *(__nv_bfloat162*)(smem + AH_OFF + pr * AP_B + q0 * 2)       = __nv_bfloat162(h0, h1);
                *(__nv_bfloat162*)(smem + AL_OFF + pr * AP_B + q0 * 2)       = __nv_bfloat162(l0, l1);
                *(__nv_bfloat162*)(smem + AH_OFF + (pr + 8) * AP_B + q0 * 2) = __nv_bfloat162(h2, h3);
                *(__nv_bfloat162*)(smem + AL_OFF + (pr + 8) * AP_B + q0 * 2) = __nv_bfloat162(l2, l3);
            }
        }
    }
    __syncthreads();

    // ---- phase 3: out = alpha @ question; Q single-buffered in stage region ----
    {
        uint32_t aoff3[4];
#pragma unroll
        for (int mi = 0; mi < 4; ++mi)
            aoff3[mi] = (uint32_t)(AH_OFF + (wm * 64 + mi * 16 + (j & 1) * 8 + rj) * AP_B + (j >> 1) * 16);
        uint32_t boffq = (uint32_t)(((j & 1) * 8 + rj) * QP_B + wn * 32 + (j >> 1) * 16);
        const uint32_t dAL = AL_OFF - AH_OFF;

        for (int dc = 0; dc < 12; ++dc) {
            // Q region free: all prior ldsm reads complete (loop-top barrier)
            if (dc > 0) __syncthreads();
#pragma unroll
            for (int i = 0; i < 4; ++i) {
                int idx = tid + i * 256;
                int row = idx >> 3;
                int c   = idx & 7;
                uint32_t d = sb + (uint32_t)(row * QP_B + c * 16);
                size_t so = (size_t)row * DHID + dc * 64 + c * 8;
                cp16(d, Q_h + so);
                cp16(d + 18432, Q_l + so);
            }
            CP_COMMIT();
            CP_WAIT0();
            __syncthreads();

            float o3[4][2][4];
#pragma unroll
            for (int mi = 0; mi < 4; ++mi)
#pragma unroll
                for (int ni = 0; ni < 2; ++ni)
#pragma unroll
                    for (int r = 0; r < 4; ++r) o3[mi][ni][r] = 0.0f;

#pragma unroll
            for (int ks = 0; ks < 8; ++ks) {
                uint32_t ka = (uint32_t)ks * 32;
                uint32_t kq = (uint32_t)ks * 16 * QP_B;
                uint32_t ah[4][4], al[4][4];
#pragma unroll
                for (int mi = 0; mi < 4; ++mi)
                    ldsm4(ah[mi][0], ah[mi][1], ah[mi][2], ah[mi][3],
                          sb + aoff3[mi] + ka);
#pragma unroll
                for (int mi = 0; mi < 4; ++mi)
                    ldsm4(al[mi][0], al[mi][1], al[mi][2], al[mi][3],
                          sb + aoff3[mi] + dAL + ka);
                uint32_t bh[2][2], bl[2][2];
                {
                    uint32_t r0, r1, r2, r3;
                    ldsm4t(r0, r1, r2, r3, sb + boffq + kq);
                    bh[0][0] = r0; bh[0][1] = r1; bh[1][0] = r2; bh[1][1] = r3;
                    ldsm4t(r0, r1, r2, r3, sb + 18432 + boffq + kq);
                    bl[0][0] = r0; bl[0][1] = r1; bl[1][0] = r2; bl[1][1] = r3;
                }
#pragma unroll
                for (int mi = 0; mi < 4; ++mi)
#pragma unroll
                    for (int ni = 0; ni < 2; ++ni) {
                        mma16816(o3[mi][ni], ah[mi][0], ah[mi][1], ah[mi][2], ah[mi][3],
                                 bh[ni][0], bh[ni][1]);
                        mma16816(o3[mi][ni], al[mi][0], al[mi][1], al[mi][2], al[mi][3],
                                 bh[ni][0], bh[ni][1]);
                        mma16816(o3[mi][ni], ah[mi][0], ah[mi][1], ah[mi][2], ah[mi][3],
                                 bl[ni][0], bl[ni][1]);
                    }
            }

#pragma unroll
            for (int mi = 0; mi < 4; ++mi) {
                size_t gr = (size_t)b * NLP + pBase + wm * 64 + mi * 16 + rGrp;
#pragma unroll
                for (int ni = 0; ni < 2; ++ni) {
                    int d = dc * 64 + wn * 16 + ni * 8 + cGrp;
                    float2 v0 = {o3[mi][ni][0], o3[mi][ni][1]};
                    float2 v1 = {o3[mi][ni][2], o3[mi][ni][3]};
                    *(float2*)(out + gr * DHID + d)       = v0;
                    *(float2*)(out + (gr + 8) * DHID + d) = v1;
                }
            }
        }
    }
}

// ---------------------------------------------------------------------------
extern "C" void kernel_launch(void* const* d_in, const int* in_sizes, int n_in,
                              void* d_out, int out_size) {
    const float* passage  = (const float*)d_in[0];
    const float* question = (const float*)d_in[2];
    const unsigned char* qmask = (const unsigned char*)d_in[3];
    const float* Ww = (const float*)d_in[4];
    const float* Wb = (const float*)d_in[5];
    float* out = (float*)d_out;

    __nv_bfloat16 *ph, *pl, *qh, *ql, *wth, *wtl, *wph, *wpl, *wqh, *wql;
    cudaGetSymbolAddress((void**)&ph,  g_Ph);
    cudaGetSymbolAddress((void**)&pl,  g_Pl);
    cudaGetSymbolAddress((void**)&qh,  g_Qh);
    cudaGetSymbolAddress((void**)&ql,  g_Ql);
    cudaGetSymbolAddress((void**)&wth, g_Wth);
    cudaGetSymbolAddress((void**)&wtl, g_Wtl);
    cudaGetSymbolAddress((void**)&wph, g_Wph);
    cudaGetSymbolAddress((void**)&wpl, g_Wpl);
    cudaGetSymbolAddress((void**)&wqh, g_Wqh);
    cudaGetSymbolAddress((void**)&wql, g_Wql);

    mask_prep_kernel<<<1, 256>>>(qmask, NB * NLQ);

    int np4 = NB * NLP * DHID / 4;
    int nq4 = NB * NLQ * DHID / 4;
    split_kernel<<<(np4 + 255) / 256, 256>>>((const float4*)passage,
                                             (__nv_bfloat162*)ph, (__nv_bfloat162*)pl, np4);
    split_kernel<<<(nq4 + 255) / 256, 256>>>((const float4*)question,
                                             (__nv_bfloat162*)qh, (__nv_bfloat162*)ql, nq4);
    wsplit_kernel<<<dim3(DHID / 32, DHID / 32), dim3(32, 8)>>>(Ww, wth, wtl);

    cudaFuncSetAttribute(gemm_mma_kernel, cudaFuncAttributeMaxDynamicSharedMemorySize, GSMEM);
    gemm_mma_kernel<<<dim3(DHID / 128, YP + (NB * NLQ) / 128), 256, GSMEM>>>(
        ph, pl, qh, ql, wth, wtl, Wb, wph, wpl, wqh, wql);

    cudaFuncSetAttribute(attn_tc_kernel, cudaFuncAttributeMaxDynamicSharedMemorySize, ASMEM);
    attn_tc_kernel<<<dim3(NLP / 128, NB), 256, ASMEM>>>(wph, wpl, wqh, wql, qh, ql, out);
}

// round 12
// speedup vs baseline: 2.9477x; 1.0432x over previous
#include <cuda_runtime.h>
#include <cuda_bf16.h>
#include <math.h>
#include <stdint.h>
#include <stddef.h>

#define DHID 768
#define NB   64
#define NLP  1024
#define NLQ  128

// ---------------- scratch (__device__ globals; allocation-free rule) --------
__device__ float g_qbias[NB * NLQ];
__device__ __align__(16) __nv_bfloat16 g_Qh[(size_t)NB * NLQ * DHID];
__device__ __align__(16) __nv_bfloat16 g_Ql[(size_t)NB * NLQ * DHID];
__device__ __align__(16) __nv_bfloat16 g_Wth[DHID * DHID];   // W^T hi [n][k]
__device__ __align__(16) __nv_bfloat16 g_Wtl[DHID * DHID];   // W^T lo [n][k]
__device__ __align__(16) __nv_bfloat16 g_Wph[(size_t)NB * NLP * DHID];
__device__ __align__(16) __nv_bfloat16 g_Wpl[(size_t)NB * NLP * DHID];
__device__ __align__(16) __nv_bfloat16 g_Wqh[(size_t)NB * NLQ * DHID];
__device__ __align__(16) __nv_bfloat16 g_Wql[(size_t)NB * NLQ * DHID];

// ---------------- small asm helpers ----------------------------------------
__device__ __forceinline__ uint32_t smem_u32(const void* p) {
    uint32_t a;
    asm("{ .reg .u64 t; cvta.to.shared.u64 t, %1; cvt.u32.u64 %0, t; }" : "=r"(a) : "l"(p));
    return a;
}
__device__ __forceinline__ void cp16(uint32_t dst, const void* src) {
    asm volatile("cp.async.cg.shared.global [%0], [%1], 16;" :: "r"(dst), "l"(src));
}
#define CP_COMMIT() asm volatile("cp.async.commit_group;" ::: "memory")
#define CP_WAIT0()  asm volatile("cp.async.wait_group 0;" ::: "memory")

__device__ __forceinline__ void ldsm4(uint32_t& r0, uint32_t& r1, uint32_t& r2,
                                      uint32_t& r3, uint32_t a) {
    asm volatile("ldmatrix.sync.aligned.m8n8.x4.shared.b16 {%0,%1,%2,%3}, [%4];"
                 : "=r"(r0), "=r"(r1), "=r"(r2), "=r"(r3) : "r"(a));
}
__device__ __forceinline__ void ldsm4t(uint32_t& r0, uint32_t& r1, uint32_t& r2,
                                       uint32_t& r3, uint32_t a) {
    asm volatile("ldmatrix.sync.aligned.m8n8.x4.trans.shared.b16 {%0,%1,%2,%3}, [%4];"
                 : "=r"(r0), "=r"(r1), "=r"(r2), "=r"(r3) : "r"(a));
}
__device__ __forceinline__ void mma16816(float* c, uint32_t a0, uint32_t a1,
                                         uint32_t a2, uint32_t a3,
                                         uint32_t b0, uint32_t b1) {
    asm volatile("mma.sync.aligned.m16n8k16.row.col.f32.bf16.bf16.f32 "
                 "{%0,%1,%2,%3}, {%4,%5,%6,%7}, {%8,%9}, {%0,%1,%2,%3};"
                 : "+f"(c[0]), "+f"(c[1]), "+f"(c[2]), "+f"(c[3])
                 : "r"(a0), "r"(a1), "r"(a2), "r"(a3), "r"(b0), "r"(b1));
}
__device__ __forceinline__ void split2(float v, __nv_bfloat16& h, __nv_bfloat16& l) {
    h = __float2bfloat16(v);
    l = __float2bfloat16(v - __bfloat162float(h));
}

// ---------------- mask prep (dtype-sniffing) --------------------------------
__global__ void mask_prep_kernel(const unsigned char* __restrict__ qm, int n) {
    __shared__ int mode;
    if (threadIdx.x == 0) mode = 0;
    __syncthreads();
    for (int i = threadIdx.x; i < n; i += blockDim.x) {
        int r = i & 3;
        unsigned char c = qm[i];
        if (r != 0 && c != 0) {
            if (r == 3 && c == 0x3F) atomicMax(&mode, 2);
            else                     atomicMax(&mode, 1);
        }
    }
    __syncthreads();
    int m = mode;
    for (int i = threadIdx.x; i < n; i += blockDim.x) {
        int v;
        if (m == 2)      v = (((const float*)(const void*)qm)[i] != 0.0f);
        else if (m == 1) v = (qm[i] != 0);
        else             v = (((const int*)(const void*)qm)[i] != 0);
        g_qbias[i] = v ? -1e30f : 0.0f;
    }
}

// ---------------- fp32 -> (hi,lo) bf16 split (question only, for attn) ------
__global__ void split_kernel(const float4* __restrict__ x,
                             __nv_bfloat162* __restrict__ h,
                             __nv_bfloat162* __restrict__ l, int n4) {
    int i = blockIdx.x * blockDim.x + threadIdx.x;
    if (i >= n4) return;
    float4 v = x[i];
    __nv_bfloat16 h0, h1, h2, h3, l0, l1, l2, l3;
    split2(v.x, h0, l0); split2(v.y, h1, l1);
    split2(v.z, h2, l2); split2(v.w, h3, l3);
    h[i * 2]     = __nv_bfloat162(h0, h1);
    h[i * 2 + 1] = __nv_bfloat162(h2, h3);
    l[i * 2]     = __nv_bfloat162(l0, l1);
    l[i * 2 + 1] = __nv_bfloat162(l2, l3);
}

// ---------------- W[k][n] -> W^T split (hi/lo) ------------------------------
__global__ void wsplit_kernel(const float* __restrict__ W,
                              __nv_bfloat16* __restrict__ Wth,
                              __nv_bfloat16* __restrict__ Wtl) {
    __shared__ float t[32][33];
    int bx = blockIdx.x * 32;  // k
    int by = blockIdx.y * 32;  // n
    for (int yy = threadIdx.y; yy < 32; yy += 8)
        t[yy][threadIdx.x] = W[(size_t)(bx + yy) * DHID + by + threadIdx.x];
    __syncthreads();
    for (int yy = threadIdx.y; yy < 32; yy += 8) {
        float v = t[threadIdx.x][yy];
        __nv_bfloat16 h, l;
        split2(v, h, l);
        size_t o = (size_t)(by + yy) * DHID + bx + threadIdx.x;
        Wth[o] = h;
        Wtl[o] = l;
    }
}

// ---------------- common tiling constants -----------------------------------
#define GP_B      80
#define ARR_B     (128 * GP_B)
#define O_AH      0
#define O_AL      (1 * ARR_B)
#define O_BH      (2 * ARR_B)
#define O_BL      (3 * ARR_B)
#define STAGE_B   (4 * ARR_B)         // 40960
#define NCHUNK    (DHID / 32)         // 24

// B hi/lo loader (cp.async) into the standard stage layout
__device__ __forceinline__ void load_stageB(uint32_t dst, int kc, int tid,
                                            const __nv_bfloat16* __restrict__ B_h,
                                            const __nv_bfloat16* __restrict__ B_l) {
#pragma unroll
    for (int i = 0; i < 2; ++i) {
        int idx = tid + i * 256;
        int row = idx >> 2;
        int c   = idx & 3;
        uint32_t d = dst + (uint32_t)(row * GP_B + c * 16);
        size_t so = (size_t)row * DHID + kc + c * 8;
        cp16(d + O_BH, B_h + so);
        cp16(d + O_BL, B_l + so);
    }
}

// full hi/lo loader (A+B) — used by the attention kernel
__device__ __forceinline__ void load_stage(uint32_t dst, int kc, int tid,
                                           const __nv_bfloat16* __restrict__ A_h,
                                           const __nv_bfloat16* __restrict__ A_l,
                                           const __nv_bfloat16* __restrict__ B_h,
                                           const __nv_bfloat16* __restrict__ B_l) {
#pragma unroll
    for (int i = 0; i < 2; ++i) {
        int idx = tid + i * 256;
        int row = idx >> 2;
        int c   = idx & 3;
        uint32_t d = dst + (uint32_t)(row * GP_B + c * 16);
        size_t so = (size_t)row * DHID + kc + c * 8;
        cp16(d + O_AH, A_h + so);
        cp16(d + O_AL, A_l + so);
        cp16(d + O_BH, B_h + so);
        cp16(d + O_BL, B_l + so);
    }
}

// 3-product split-bf16 mainloop chunk (2 k16 steps)
__device__ __forceinline__ void mma_chunk(uint32_t st, const uint32_t* aoff,
                                          const uint32_t* boff, float acc[4][4][4]) {
#pragma unroll
    for (int ks = 0; ks < 2; ++ks) {
        uint32_t k2 = (uint32_t)ks * 32;
        uint32_t ah[4][4], al[4][4], bh[4][2], bl[4][2];
#pragma unroll
        for (int mi = 0; mi < 4; ++mi)
            ldsm4(ah[mi][0], ah[mi][1], ah[mi][2], ah[mi][3], st + O_AH + aoff[mi] + k2);
#pragma unroll
        for (int mi = 0; mi < 4; ++mi)
            ldsm4(al[mi][0], al[mi][1], al[mi][2], al[mi][3], st + O_AL + aoff[mi] + k2);
#pragma unroll
        for (int p = 0; p < 2; ++p) {
            uint32_t r0, r1, r2, r3;
            ldsm4(r0, r1, r2, r3, st + O_BH + boff[p] + k2);
            bh[p * 2][0] = r0; bh[p * 2][1] = r1;
            bh[p * 2 + 1][0] = r2; bh[p * 2 + 1][1] = r3;
            ldsm4(r0, r1, r2, r3, st + O_BL + boff[p] + k2);
            bl[p * 2][0] = r0; bl[p * 2][1] = r1;
            bl[p * 2 + 1][0] = r2; bl[p * 2 + 1][1] = r3;
        }
#pragma unroll
        for (int mi = 0; mi < 4; ++mi)
#pragma unroll
            for (int ni = 0; ni < 4; ++ni) {
                mma16816(acc[mi][ni], ah[mi][0], ah[mi][1], ah[mi][2], ah[mi][3],
                         bh[ni][0], bh[ni][1]);
                mma16816(acc[mi][ni], al[mi][0], al[mi][1], al[mi][2], al[mi][3],
                         bh[ni][0], bh[ni][1]);
                mma16816(acc[mi][ni], ah[mi][0], ah[mi][1], ah[mi][2], ah[mi][3],
                         bl[ni][0], bl[ni][1]);
            }
    }
}

// ---------------- projection GEMM: fused A split, 2-stage, 2 CTAs/SM --------
// A (passage/question fp32) staged via cp.async into f32buf (16B-aligned
// pitch 144), converted smem->smem into the hi/lo stage layout.
#define F32_OFF   (2 * STAGE_B)       // 81920
#define F32_PITCH 144                 // 128B row + 16B pad (16B-aligned rows)
#define F32_SZ    (128 * F32_PITCH)   // 18432
#define BIAS_OFF  (F32_OFF + F32_SZ)  // 100352
#define GSMEM     (BIAS_OFF + 512)    // 100864
#define YP        ((NB * NLP) / 128)  // 512 P row-blocks

__device__ __forceinline__ void loadA32(uint32_t f32b, const float* __restrict__ Af,
                                        int kc, int tid) {
#pragma unroll
    for (int i = 0; i < 4; ++i) {
        int idx = tid + i * 256;          // 0..1023 16B units
        int row = idx >> 3;               // 0..127
        int c   = idx & 7;                // 8 units of 16B per 128B row
        cp16(f32b + (uint32_t)(row * F32_PITCH + c * 16),
             Af + (size_t)row * DHID + kc + c * 4);
    }
}

__device__ __forceinline__ void convertA(const char* f32s, char* stage, int tid) {
#pragma unroll
    for (int i = 0; i < 2; ++i) {
        int idx = tid + i * 256;          // 0..511 output 16B-hi units
        int row = idx >> 2;
        int c   = idx & 3;                // 32B fp32 -> 16B hi + 16B lo
        const float4* s = (const float4*)(f32s + row * F32_PITCH + c * 32);
        float4 v0 = s[0], v1 = s[1];
        float f[8] = {v0.x, v0.y, v0.z, v0.w, v1.x, v1.y, v1.z, v1.w};
        uint32_t H[4], L[4];
#pragma unroll
        for (int q = 0; q < 4; ++q) {
            __nv_bfloat16 h0, l0, h1, l1;
            split2(f[2 * q],     h0, l0);
            split2(f[2 * q + 1], h1, l1);
            __nv_bfloat162 ph(h0, h1), pl(l0, l1);
            H[q] = *reinterpret_cast<uint32_t*>(&ph);
            L[q] = *reinterpret_cast<uint32_t*>(&pl);
        }
        char* d = stage + row * GP_B + c * 16;
        *(uint4*)(d + O_AH) = make_uint4(H[0], H[1], H[2], H[3]);
        *(uint4*)(d + O_AL) = make_uint4(L[0], L[1], L[2], L[3]);
    }
}

__global__ __launch_bounds__(256, 2)
void gemm_mma_kernel(const float* __restrict__ Pf,
                     const float* __restrict__ Qf,
                     const __nv_bfloat16* __restrict__ Bh,
                     const __nv_bfloat16* __restrict__ Bl,
                     const float* __restrict__ bias,
                     __nv_bfloat16* __restrict__ Ph_out,
                     __nv_bfloat16* __restrict__ Pl_out,
                     __nv_bfloat16* __restrict__ Qh_out,
                     __nv_bfloat16* __restrict__ Ql_out) {
    extern __shared__ char smem[];
    uint32_t sb = smem_u32(smem);
    const uint32_t f32b = sb + F32_OFF;
    float* bias_s = (float*)(smem + BIAS_OFF);

    const int tid  = threadIdx.x;
    const int w    = tid >> 5;
    const int lane = tid & 31;
    const int wm   = w >> 2;
    const int wn   = w & 3;
    const int yb   = blockIdx.y;
    const bool isQ = (yb >= YP);
    const size_t mBase = (size_t)(isQ ? yb - YP : yb) * 128;
    const int    nBase = blockIdx.x * 128;

    if (tid < 128) bias_s[tid] = bias[nBase + tid];

    const float* Af = (isQ ? Qf : Pf) + mBase * DHID;
    const __nv_bfloat16* B_h = Bh + (size_t)nBase * DHID;
    const __nv_bfloat16* B_l = Bl + (size_t)nBase * DHID;
    __nv_bfloat16* Ch = isQ ? Qh_out : Ph_out;
    __nv_bfloat16* Cl = isQ ? Ql_out : Pl_out;

    const int j  = lane >> 3;
    const int rj = lane & 7;
    uint32_t aoff[4], boff[2];
#pragma unroll
    for (int mi = 0; mi < 4; ++mi)
        aoff[mi] = (uint32_t)((wm * 64 + mi * 16 + (j & 1) * 8 + rj) * GP_B + (j >> 1) * 16);
#pragma unroll
    for (int p = 0; p < 2; ++p)
        boff[p] = (uint32_t)((wn * 32 + p * 16 + (j >> 1) * 8 + rj) * GP_B + (j & 1) * 16);

    float acc[4][4][4];
#pragma unroll
    for (int mi = 0; mi < 4; ++mi)
#pragma unroll
        for (int ni = 0; ni < 4; ++ni)
#pragma unroll
            for (int r = 0; r < 4; ++r) acc[mi][ni][r] = 0.0f;

    // prologue: A32(0)+B(0) -> convert stage0 -> A32(1) staged
    loadA32(f32b, Af, 0, tid);
    load_stageB(sb + 0 * STAGE_B, 0, tid, B_h, B_l);
    CP_COMMIT();
    CP_WAIT0();
    __syncthreads();
    convertA(smem + F32_OFF, smem + 0 * STAGE_B, tid);
    __syncthreads();
    loadA32(f32b, Af, 32, tid);
    CP_COMMIT();
    CP_WAIT0();
    __syncthreads();
    // invariant entering t: stage[t&1] ready (A converted, B arrived);
    // f32buf holds A32(t+1), arrived.

    for (int t = 0; t < NCHUNK; ++t) {
        if (t + 1 < NCHUNK)
            convertA(smem + F32_OFF, smem + (size_t)((t + 1) & 1) * STAGE_B, tid);
        __syncthreads();               // convert visible; f32buf free
        if (t + 2 < NCHUNK) loadA32(f32b, Af, (t + 2) * 32, tid);
        if (t + 1 < NCHUNK) load_stageB(sb + (uint32_t)((t + 1) & 1) * STAGE_B,
                                        (t + 1) * 32, tid, B_h, B_l);
        CP_COMMIT();
        mma_chunk(sb + (uint32_t)(t & 1) * STAGE_B, aoff, boff, acc);
        CP_WAIT0();
        __syncthreads();
    }

    // epilogue: bias + relu, split hi/lo bf16 store
    const int rGrp = lane >> 2;
    const int cGrp = (lane & 3) * 2;
#pragma unroll
    for (int mi = 0; mi < 4; ++mi) {
        size_t gr = mBase + wm * 64 + mi * 16 + rGrp;
#pragma unroll
        for (int ni = 0; ni < 4; ++ni) {
            int lc = wn * 32 + ni * 8 + cGrp;
            float b0 = bias_s[lc], b1 = bias_s[lc + 1];
            float v0 = fmaxf(acc[mi][ni][0] + b0, 0.0f);
            float v1 = fmaxf(acc[mi][ni][1] + b1, 0.0f);
            float v2 = fmaxf(acc[mi][ni][2] + b0, 0.0f);
            float v3 = fmaxf(acc[mi][ni][3] + b1, 0.0f);
            __nv_bfloat16 h0, h1, h2, h3, l0, l1, l2, l3;
            split2(v0, h0, l0); split2(v1, h1, l1);
            split2(v2, h2, l2); split2(v3, h3, l3);
            size_t o0 = gr * DHID + nBase + lc;
            size_t o1 = (gr + 8) * DHID + nBase + lc;
            *(__nv_bfloat162*)(Ch + o0) = __nv_bfloat162(h0, h1);
            *(__nv_bfloat162*)(Cl + o0) = __nv_bfloat162(l0, l1);
            *(__nv_bfloat162*)(Ch + o1) = __nv_bfloat162(h2, h3);
            *(__nv_bfloat162*)(Cl + o1) = __nv_bfloat162(l2, l3);
        }
    }
}

// ---------------- tensor-core fused attention: 2 CTAs/SM ---------------------
#define AH_OFF   40960
#define AL_OFF   75776
#define AP_B     272
#define QB_OFF   110592
#define RED_OFF  111104
#define ASMEM    113152
#define QP_B     144

__global__ __launch_bounds__(256, 2)
void attn_tc_kernel(const __nv_bfloat16* __restrict__ Wph,
                    const __nv_bfloat16* __restrict__ Wpl,
                    const __nv_bfloat16* __restrict__ Wqh,
                    const __nv_bfloat16* __restrict__ Wql,
                    const __nv_bfloat16* __restrict__ Qh,
                    const __nv_bfloat16* __restrict__ Ql,
                    float* __restrict__ out) {
    extern __shared__ char smem[];
    uint32_t sb = smem_u32(smem);
    float* qb  = (float*)(smem + QB_OFF);
    float* red = (float*)(smem + RED_OFF);

    const int tid  = threadIdx.x;
    const int w    = tid >> 5;
    const int lane = tid & 31;
    const int wm   = w >> 2;
    const int wn   = w & 3;
    const int b    = blockIdx.y;
    const int pBase = blockIdx.x * 128;

    if (tid < 128) qb[tid] = g_qbias[b * NLQ + tid];

    const __nv_bfloat16* A_h = Wph + ((size_t)b * NLP + pBase) * DHID;
    const __nv_bfloat16* A_l = Wpl + ((size_t)b * NLP + pBase) * DHID;
    const __nv_bfloat16* B_h = Wqh + (size_t)b * NLQ * DHID;
    const __nv_bfloat16* B_l = Wql + (size_t)b * NLQ * DHID;
    const __nv_bfloat16* Q_h = Qh + (size_t)b * NLQ * DHID;
    const __nv_bfloat16* Q_l = Ql + (size_t)b * NLQ * DHID;

    const int j  = lane >> 3;
    const int rj = lane & 7;
    const int rGrp = lane >> 2;
    const int cGrp = (lane & 3) * 2;

    // ---- phase 1: scores = Wp @ Wq^T, single-stage pipeline ----
    float acc[4][4][4];
#pragma unroll
    for (int mi = 0; mi < 4; ++mi)
#pragma unroll
        for (int ni = 0; ni < 4; ++ni)
#pragma unroll
            for (int r = 0; r < 4; ++r) acc[mi][ni][r] = 0.0f;
    {
        uint32_t aoff[4], boff[2];
#pragma unroll
        for (int mi = 0; mi < 4; ++mi)
            aoff[mi] = (uint32_t)((wm * 64 + mi * 16 + (j & 1) * 8 + rj) * GP_B + (j >> 1) * 16);
#pragma unroll
        for (int p = 0; p < 2; ++p)
            boff[p] = (uint32_t)((wn * 32 + p * 16 + (j >> 1) * 8 + rj) * GP_B + (j & 1) * 16);

        load_stage(sb, 0, tid, A_h, A_l, B_h, B_l);
        CP_COMMIT();
        for (int t = 0; t < NCHUNK; ++t) {
            CP_WAIT0();
            __syncthreads();
            mma_chunk(sb, aoff, boff, acc);
            __syncthreads();
            if (t + 1 < NCHUNK) {
                load_stage(sb, (t + 1) * 32, tid, A_h, A_l, B_h, B_l);
                CP_COMMIT();
            }
        }
    }

    // ---- phase 2: mask bias + softmax in registers ----
    {
#pragma unroll
        for (int mi = 0; mi < 4; ++mi)
#pragma unroll
            for (int ni = 0; ni < 4; ++ni) {
                int q0 = wn * 32 + ni * 8 + cGrp;
                float b0 = qb[q0], b1 = qb[q0 + 1];
                acc[mi][ni][0] += b0; acc[mi][ni][1] += b1;
                acc[mi][ni][2] += b0; acc[mi][ni][3] += b1;
            }

        float mrow[4][2];
#pragma unroll
        for (int mi = 0; mi < 4; ++mi) {
            mrow[mi][0] = -INFINITY; mrow[mi][1] = -INFINITY;
#pragma unroll
            for (int ni = 0; ni < 4; ++ni) {
                mrow[mi][0] = fmaxf(mrow[mi][0], fmaxf(acc[mi][ni][0], acc[mi][ni][1]));
                mrow[mi][1] = fmaxf(mrow[mi][1], fmaxf(acc[mi][ni][2], acc[mi][ni][3]));
            }
        }
#pragma unroll
        for (int o = 1; o <= 2; o <<= 1)
#pragma unroll
            for (int mi = 0; mi < 4; ++mi) {
                mrow[mi][0] = fmaxf(mrow[mi][0], __shfl_xor_sync(0xFFFFFFFFu, mrow[mi][0], o));
                mrow[mi][1] = fmaxf(mrow[mi][1], __shfl_xor_sync(0xFFFFFFFFu, mrow[mi][1], o));
            }
        if ((lane & 3) == 0)
#pragma unroll
            for (int mi = 0; mi < 4; ++mi) {
                red[(wm * 64 + mi * 16 + rGrp) * 4 + wn]     = mrow[mi][0];
                red[(wm * 64 + mi * 16 + rGrp + 8) * 4 + wn] = mrow[mi][1];
            }
        __syncthreads();
        float M[4][2];
#pragma unroll
        for (int mi = 0; mi < 4; ++mi)
#pragma unroll
            for (int h = 0; h < 2; ++h) {
                const float* rr = &red[(wm * 64 + mi * 16 + rGrp + h * 8) * 4];
                M[mi][h] = fmaxf(fmaxf(rr[0], rr[1]), fmaxf(rr[2], rr[3]));
            }
        __syncthreads();

        float srow[4][2];
#pragma unroll
        for (int mi = 0; mi < 4; ++mi) { srow[mi][0] = 0.0f; srow[mi][1] = 0.0f; }
#pragma unroll
        for (int mi = 0; mi < 4; ++mi)
#pragma unroll
            for (int ni = 0; ni < 4; ++ni) {
                float e0 = __expf(acc[mi][ni][0] - M[mi][0]);
                float e1 = __expf(acc[mi][ni][1] - M[mi][0]);
                float e2 = __expf(acc[mi][ni][2] - M[mi][1]);
                float e3 = __expf(acc[mi][ni][3] - M[mi][1]);
                acc[mi][ni][0] = e0; acc[mi][ni][1] = e1;
                acc[mi][ni][2] = e2; acc[mi][ni][3] = e3;
                srow[mi][0] += e0 + e1;
                srow[mi][1] += e2 + e3;
            }
#pragma unroll
        for (int o = 1; o <= 2; o <<= 1)
#pragma unroll
            for (int mi = 0; mi < 4; ++mi) {
                srow[mi][0] += __shfl_xor_sync(0xFFFFFFFFu, srow[mi][0], o);
                srow[mi][1] += __shfl_xor_sync(0xFFFFFFFFu, srow[mi][1], o);
            }
        if ((lane & 3) == 0)
#pragma unroll
            for (int mi = 0; mi < 4; ++mi) {
                red[(wm * 64 + mi * 16 + rGrp) * 4 + wn]     = srow[mi][0];
                red[(wm * 64 + mi * 16 + rGrp + 8) * 4 + wn] = srow[mi][1];
            }
        __syncthreads();
        float INV[4][2];
#pragma unroll
        for (int mi = 0; mi < 4; ++mi)
#pragma unroll
            for (int h = 0; h < 2; ++h) {
                const float* rr = &red[(wm * 64 + mi * 16 + rGrp + h * 8) * 4];
                INV[mi][h] = 1.0f / (rr[0] + rr[1] + rr[2] + rr[3]);
            }

#pragma unroll
        for (int mi = 0; mi < 4; ++mi) {
            int pr = wm * 64 + mi * 16 + rGrp;
#pragma unroll
            for (int ni = 0; ni < 4; ++ni) {
                int q0 = wn * 32 + ni * 8 + cGrp;
                float a0 = acc[mi][ni][0] * INV[mi][0];
                float a1 = acc[mi][ni][1] * INV[mi][0];
                float a2 = acc[mi][ni][2] * INV[mi][1];
                float a3 = acc[mi][ni][3] * INV[mi][1];
                __nv_bfloat16 h0, h1, h2, h3, l0, l1, l2, l3;
                split2(a0, h0, l0); split2(a1, h1, l1);
                split2(a2, h2, l2); split2(a3, h3, l3);
                *(__nv_bfloat162*)(smem + AH_OFF + pr * AP_B + q0 * 2)       = __nv_bfloat162(h0, h1);
                *(__nv_bfloat162*)(smem + AL_OFF + pr * AP_B + q0 * 2)       = __nv_bfloat162(l0, l1);
                *(__nv_bfloat162*)(smem + AH_OFF + (pr + 8) * AP_B + q0 * 2) = __nv_bfloat162(h2, h3);
                *(__nv_bfloat162*)(smem + AL_OFF + (pr + 8) * AP_B + q0 * 2) = __nv_bfloat162(l2, l3);
            }
        }
    }
    __syncthreads();

    // ---- phase 3: out = alpha @ question; Q single-buffered in stage region ----
    {
        uint32_t aoff3[4];
#pragma unroll
        for (int mi = 0; mi < 4; ++mi)
            aoff3[mi] = (uint32_t)(AH_OFF + (wm * 64 + mi * 16 + (j & 1) * 8 + rj) * AP_B + (j >> 1) * 16);
        uint32_t boffq = (uint32_t)(((j & 1) * 8 + rj) * QP_B + wn * 32 + (j >> 1) * 16);
        const uint32_t dAL = AL_OFF - AH_OFF;

        for (int dc = 0; dc < 12; ++dc) {
            if (dc > 0) __syncthreads();
#pragma unroll
            for (int i = 0; i < 4; ++i) {
                int idx = tid + i * 256;
                int row = idx >> 3;
                int c   = idx & 7;
                uint32_t d = sb + (uint32_t)(row * QP_B + c * 16);
                size_t so = (size_t)row * DHID + dc * 64 + c * 8;
                cp16(d, Q_h + so);
                cp16(d + 18432, Q_l + so);
            }
            CP_COMMIT();
            CP_WAIT0();
            __syncthreads();

            float o3[4][2][4];
#pragma unroll
            for (int mi = 0; mi < 4; ++mi)
#pragma unroll
                for (int ni = 0; ni < 2; ++ni)
#pragma unroll
                    for (int r = 0; r < 4; ++r) o3[mi][ni][r] = 0.0f;

#pragma unroll
            for (int ks = 0; ks < 8; ++ks) {
                uint32_t ka = (uint32_t)ks * 32;
                uint32_t kq = (uint32_t)ks * 16 * QP_B;
                uint32_t ah[4][4], al[4][4];
#pragma unroll
                for (int mi = 0; mi < 4; ++mi)
                    ldsm4(ah[mi][0], ah[mi][1], ah[mi][2], ah[mi][3],
                          sb + aoff3[mi] + ka);
#pragma unroll
                for (int mi = 0; mi < 4; ++mi)
                    ldsm4(al[mi][0], al[mi][1], al[mi][2], al[mi][3],
                          sb + aoff3[mi] + dAL + ka);
                uint32_t bh[2][2], bl[2][2];
                {
                    uint32_t r0, r1, r2, r3;
                    ldsm4t(r0, r1, r2, r3, sb + boffq + kq);
                    bh[0][0] = r0; bh[0][1] = r1; bh[1][0] = r2; bh[1][1] = r3;
                    ldsm4t(r0, r1, r2, r3, sb + 18432 + boffq + kq);
                    bl[0][0] = r0; bl[0][1] = r1; bl[1][0] = r2; bl[1][1] = r3;
                }
#pragma unroll
                for (int mi = 0; mi < 4; ++mi)
#pragma unroll
                    for (int ni = 0; ni < 2; ++ni) {
                        mma16816(o3[mi][ni], ah[mi][0], ah[mi][1], ah[mi][2], ah[mi][3],
                                 bh[ni][0], bh[ni][1]);
                        mma16816(o3[mi][ni], al[mi][0], al[mi][1], al[mi][2], al[mi][3],
                                 bh[ni][0], bh[ni][1]);
                        mma16816(o3[mi][ni], ah[mi][0], ah[mi][1], ah[mi][2], ah[mi][3],
                                 bl[ni][0], bl[ni][1]);
                    }
            }

#pragma unroll
            for (int mi = 0; mi < 4; ++mi) {
                size_t gr = (size_t)b * NLP + pBase + wm * 64 + mi * 16 + rGrp;
#pragma unroll
                for (int ni = 0; ni < 2; ++ni) {
                    int d = dc * 64 + wn * 16 + ni * 8 + cGrp;
                    float2 v0 = {o3[mi][ni][0], o3[mi][ni][1]};
                    float2 v1 = {o3[mi][ni][2], o3[mi][ni][3]};
                    *(float2*)(out + gr * DHID + d)       = v0;
                    *(float2*)(out + (gr + 8) * DHID + d) = v1;
                }
            }
        }
    }
}

// ---------------------------------------------------------------------------
extern "C" void kernel_launch(void* const* d_in, const int* in_sizes, int n_in,
                              void* d_out, int out_size) {
    const float* passage  = (const float*)d_in[0];
    const float* question = (const float*)d_in[2];
    const unsigned char* qmask = (const unsigned char*)d_in[3];
    const float* Ww = (const float*)d_in[4];
    const float* Wb = (const float*)d_in[5];
    float* out = (float*)d_out;

    __nv_bfloat16 *qh, *ql, *wth, *wtl, *wph, *wpl, *wqh, *wql;
    cudaGetSymbolAddress((void**)&qh,  g_Qh);
    cudaGetSymbolAddress((void**)&ql,  g_Ql);
    cudaGetSymbolAddress((void**)&wth, g_Wth);
    cudaGetSymbolAddress((void**)&wtl, g_Wtl);
    cudaGetSymbolAddress((void**)&wph, g_Wph);
    cudaGetSymbolAddress((void**)&wpl, g_Wpl);
    cudaGetSymbolAddress((void**)&wqh, g_Wqh);
    cudaGetSymbolAddress((void**)&wql, g_Wql);

    mask_prep_kernel<<<1, 256>>>(qmask, NB * NLQ);

    int nq4 = NB * NLQ * DHID / 4;
    split_kernel<<<(nq4 + 255) / 256, 256>>>((const float4*)question,
                                             (__nv_bfloat162*)qh, (__nv_bfloat162*)ql, nq4);
    wsplit_kernel<<<dim3(DHID / 32, DHID / 32), dim3(32, 8)>>>(Ww, wth, wtl);

    cudaFuncSetAttribute(gemm_mma_kernel, cudaFuncAttributeMaxDynamicSharedMemorySize, GSMEM);
    gemm_mma_kernel<<<dim3(DHID / 128, YP + (NB * NLQ) / 128), 256, GSMEM>>>(
        passage, question, wth, wtl, Wb, wph, wpl, wqh, wql);

    cudaFuncSetAttribute(attn_tc_kernel, cudaFuncAttributeMaxDynamicSharedMemorySize, ASMEM);
    attn_tc_kernel<<<dim3(NLP / 128, NB), 256, ASMEM>>>(wph, wpl, wqh, wql, qh, ql, out);
}

// round 13
// speedup vs baseline: 2.9744x; 1.0091x over previous
#include <cuda_runtime.h>
#include <cuda_bf16.h>
#include <math.h>
#include <stdint.h>
#include <stddef.h>

#define DHID 768
#define NB   64
#define NLP  1024
#define NLQ  128

// ---------------- scratch (__device__ globals; allocation-free rule) --------
__device__ float g_qbias[NB * NLQ];
__device__ __align__(16) __nv_bfloat16 g_Qh[(size_t)NB * NLQ * DHID];
__device__ __align__(16) __nv_bfloat16 g_Ql[(size_t)NB * NLQ * DHID];
__device__ __align__(16) __nv_bfloat16 g_Wth[DHID * DHID];   // W^T hi [n][k]
__device__ __align__(16) __nv_bfloat16 g_Wtl[DHID * DHID];   // W^T lo [n][k]
__device__ __align__(16) __nv_bfloat16 g_Wph[(size_t)NB * NLP * DHID];
__device__ __align__(16) __nv_bfloat16 g_Wpl[(size_t)NB * NLP * DHID];
__device__ __align__(16) __nv_bfloat16 g_Wqh[(size_t)NB * NLQ * DHID];
__device__ __align__(16) __nv_bfloat16 g_Wql[(size_t)NB * NLQ * DHID];

// ---------------- small asm helpers ----------------------------------------
__device__ __forceinline__ uint32_t smem_u32(const void* p) {
    uint32_t a;
    asm("{ .reg .u64 t; cvta.to.shared.u64 t, %1; cvt.u32.u64 %0, t; }" : "=r"(a) : "l"(p));
    return a;
}
__device__ __forceinline__ void cp16(uint32_t dst, const void* src) {
    asm volatile("cp.async.cg.shared.global [%0], [%1], 16;" :: "r"(dst), "l"(src));
}
#define CP_COMMIT() asm volatile("cp.async.commit_group;" ::: "memory")
#define CP_WAIT0()  asm volatile("cp.async.wait_group 0;" ::: "memory")

__device__ __forceinline__ void ldsm4(uint32_t& r0, uint32_t& r1, uint32_t& r2,
                                      uint32_t& r3, uint32_t a) {
    asm volatile("ldmatrix.sync.aligned.m8n8.x4.shared.b16 {%0,%1,%2,%3}, [%4];"
                 : "=r"(r0), "=r"(r1), "=r"(r2), "=r"(r3) : "r"(a));
}
__device__ __forceinline__ void ldsm4t(uint32_t& r0, uint32_t& r1, uint32_t& r2,
                                       uint32_t& r3, uint32_t a) {
    asm volatile("ldmatrix.sync.aligned.m8n8.x4.trans.shared.b16 {%0,%1,%2,%3}, [%4];"
                 : "=r"(r0), "=r"(r1), "=r"(r2), "=r"(r3) : "r"(a));
}
__device__ __forceinline__ void mma16816(float* c, uint32_t a0, uint32_t a1,
                                         uint32_t a2, uint32_t a3,
                                         uint32_t b0, uint32_t b1) {
    asm volatile("mma.sync.aligned.m16n8k16.row.col.f32.bf16.bf16.f32 "
                 "{%0,%1,%2,%3}, {%4,%5,%6,%7}, {%8,%9}, {%0,%1,%2,%3};"
                 : "+f"(c[0]), "+f"(c[1]), "+f"(c[2]), "+f"(c[3])
                 : "r"(a0), "r"(a1), "r"(a2), "r"(a3), "r"(b0), "r"(b1));
}
__device__ __forceinline__ void split2(float v, __nv_bfloat16& h, __nv_bfloat16& l) {
    h = __float2bfloat16(v);
    l = __float2bfloat16(v - __bfloat162float(h));
}

// ---------------- mask prep (dtype-sniffing) --------------------------------
__global__ void mask_prep_kernel(const unsigned char* __restrict__ qm, int n) {
    __shared__ int mode;
    if (threadIdx.x == 0) mode = 0;
    __syncthreads();
    for (int i = threadIdx.x; i < n; i += blockDim.x) {
        int r = i & 3;
        unsigned char c = qm[i];
        if (r != 0 && c != 0) {
            if (r == 3 && c == 0x3F) atomicMax(&mode, 2);
            else                     atomicMax(&mode, 1);
        }
    }
    __syncthreads();
    int m = mode;
    for (int i = threadIdx.x; i < n; i += blockDim.x) {
        int v;
        if (m == 2)      v = (((const float*)(const void*)qm)[i] != 0.0f);
        else if (m == 1) v = (qm[i] != 0);
        else             v = (((const int*)(const void*)qm)[i] != 0);
        g_qbias[i] = v ? -1e30f : 0.0f;
    }
}

// ---------------- fp32 -> (hi,lo) bf16 split (question only, for attn) ------
__global__ void split_kernel(const float4* __restrict__ x,
                             __nv_bfloat162* __restrict__ h,
                             __nv_bfloat162* __restrict__ l, int n4) {
    int i = blockIdx.x * blockDim.x + threadIdx.x;
    if (i >= n4) return;
    float4 v = x[i];
    __nv_bfloat16 h0, h1, h2, h3, l0, l1, l2, l3;
    split2(v.x, h0, l0); split2(v.y, h1, l1);
    split2(v.z, h2, l2); split2(v.w, h3, l3);
    h[i * 2]     = __nv_bfloat162(h0, h1);
    h[i * 2 + 1] = __nv_bfloat162(h2, h3);
    l[i * 2]     = __nv_bfloat162(l0, l1);
    l[i * 2 + 1] = __nv_bfloat162(l2, l3);
}

// ---------------- W[k][n] -> W^T split (hi/lo) ------------------------------
__global__ void wsplit_kernel(const float* __restrict__ W,
                              __nv_bfloat16* __restrict__ Wth,
                              __nv_bfloat16* __restrict__ Wtl) {
    __shared__ float t[32][33];
    int bx = blockIdx.x * 32;  // k
    int by = blockIdx.y * 32;  // n
    for (int yy = threadIdx.y; yy < 32; yy += 8)
        t[yy][threadIdx.x] = W[(size_t)(bx + yy) * DHID + by + threadIdx.x];
    __syncthreads();
    for (int yy = threadIdx.y; yy < 32; yy += 8) {
        float v = t[threadIdx.x][yy];
        __nv_bfloat16 h, l;
        split2(v, h, l);
        size_t o = (size_t)(by + yy) * DHID + bx + threadIdx.x;
        Wth[o] = h;
        Wtl[o] = l;
    }
}

// ---------------- common tiling constants -----------------------------------
#define GP_B      80
#define ARR_B     (128 * GP_B)
#define O_AH      0
#define O_AL      (1 * ARR_B)
#define O_BH      (2 * ARR_B)
#define O_BL      (3 * ARR_B)
#define STAGE_B   (4 * ARR_B)         // 40960
#define NCHUNK    (DHID / 32)         // 24

// B hi/lo loader (cp.async) into the standard stage layout
__device__ __forceinline__ void load_stageB(uint32_t dst, int kc, int tid,
                                            const __nv_bfloat16* __restrict__ B_h,
                                            const __nv_bfloat16* __restrict__ B_l) {
#pragma unroll
    for (int i = 0; i < 2; ++i) {
        int idx = tid + i * 256;
        int row = idx >> 2;
        int c   = idx & 3;
        uint32_t d = dst + (uint32_t)(row * GP_B + c * 16);
        size_t so = (size_t)row * DHID + kc + c * 8;
        cp16(d + O_BH, B_h + so);
        cp16(d + O_BL, B_l + so);
    }
}

// full hi/lo loader (A+B) — used by the attention kernel
__device__ __forceinline__ void load_stage(uint32_t dst, int kc, int tid,
                                           const __nv_bfloat16* __restrict__ A_h,
                                           const __nv_bfloat16* __restrict__ A_l,
                                           const __nv_bfloat16* __restrict__ B_h,
                                           const __nv_bfloat16* __restrict__ B_l) {
#pragma unroll
    for (int i = 0; i < 2; ++i) {
        int idx = tid + i * 256;
        int row = idx >> 2;
        int c   = idx & 3;
        uint32_t d = dst + (uint32_t)(row * GP_B + c * 16);
        size_t so = (size_t)row * DHID + kc + c * 8;
        cp16(d + O_AH, A_h + so);
        cp16(d + O_AL, A_l + so);
        cp16(d + O_BH, B_h + so);
        cp16(d + O_BL, B_l + so);
    }
}

// 3-product split-bf16 mainloop chunk (2 k16 steps)
__device__ __forceinline__ void mma_chunk(uint32_t st, const uint32_t* aoff,
                                          const uint32_t* boff, float acc[4][4][4]) {
#pragma unroll
    for (int ks = 0; ks < 2; ++ks) {
        uint32_t k2 = (uint32_t)ks * 32;
        uint32_t ah[4][4], al[4][4], bh[4][2], bl[4][2];
#pragma unroll
        for (int mi = 0; mi < 4; ++mi)
            ldsm4(ah[mi][0], ah[mi][1], ah[mi][2], ah[mi][3], st + O_AH + aoff[mi] + k2);
#pragma unroll
        for (int mi = 0; mi < 4; ++mi)
            ldsm4(al[mi][0], al[mi][1], al[mi][2], al[mi][3], st + O_AL + aoff[mi] + k2);
#pragma unroll
        for (int p = 0; p < 2; ++p) {
            uint32_t r0, r1, r2, r3;
            ldsm4(r0, r1, r2, r3, st + O_BH + boff[p] + k2);
            bh[p * 2][0] = r0; bh[p * 2][1] = r1;
            bh[p * 2 + 1][0] = r2; bh[p * 2 + 1][1] = r3;
            ldsm4(r0, r1, r2, r3, st + O_BL + boff[p] + k2);
            bl[p * 2][0] = r0; bl[p * 2][1] = r1;
            bl[p * 2 + 1][0] = r2; bl[p * 2 + 1][1] = r3;
        }
#pragma unroll
        for (int mi = 0; mi < 4; ++mi)
#pragma unroll
            for (int ni = 0; ni < 4; ++ni) {
                mma16816(acc[mi][ni], ah[mi][0], ah[mi][1], ah[mi][2], ah[mi][3],
                         bh[ni][0], bh[ni][1]);
                mma16816(acc[mi][ni], al[mi][0], al[mi][1], al[mi][2], al[mi][3],
                         bh[ni][0], bh[ni][1]);
                mma16816(acc[mi][ni], ah[mi][0], ah[mi][1], ah[mi][2], ah[mi][3],
                         bl[ni][0], bl[ni][1]);
            }
    }
}

// ---------------- projection GEMM: fused A split, 2-stage, 2 CTAs/SM --------
#define F32_OFF   (2 * STAGE_B)       // 81920
#define F32_PITCH 144                 // 128B row + 16B pad (16B-aligned rows)
#define F32_SZ    (128 * F32_PITCH)   // 18432
#define BIAS_OFF  (F32_OFF + F32_SZ)  // 100352
#define GSMEM     (BIAS_OFF + 512)    // 100864
#define YP        ((NB * NLP) / 128)  // 512 P row-blocks

__device__ __forceinline__ void loadA32(uint32_t f32b, const float* __restrict__ Af,
                                        int kc, int tid) {
#pragma unroll
    for (int i = 0; i < 4; ++i) {
        int idx = tid + i * 256;          // 0..1023 16B units
        int row = idx >> 3;               // 0..127
        int c   = idx & 7;                // 8 units of 16B per 128B row
        cp16(f32b + (uint32_t)(row * F32_PITCH + c * 16),
             Af + (size_t)row * DHID + kc + c * 4);
    }
}

__device__ __forceinline__ void convertA(const char* f32s, char* stage, int tid) {
#pragma unroll
    for (int i = 0; i < 2; ++i) {
        int idx = tid + i * 256;          // 0..511 output 16B-hi units
        int row = idx >> 2;
        int c   = idx & 3;                // 32B fp32 -> 16B hi + 16B lo
        const float4* s = (const float4*)(f32s + row * F32_PITCH + c * 32);
        float4 v0 = s[0], v1 = s[1];
        float f[8] = {v0.x, v0.y, v0.z, v0.w, v1.x, v1.y, v1.z, v1.w};
        uint32_t H[4], L[4];
#pragma unroll
        for (int q = 0; q < 4; ++q) {
            __nv_bfloat16 h0, l0, h1, l1;
            split2(f[2 * q],     h0, l0);
            split2(f[2 * q + 1], h1, l1);
            __nv_bfloat162 ph(h0, h1), pl(l0, l1);
            H[q] = *reinterpret_cast<uint32_t*>(&ph);
            L[q] = *reinterpret_cast<uint32_t*>(&pl);
        }
        char* d = stage + row * GP_B + c * 16;
        *(uint4*)(d + O_AH) = make_uint4(H[0], H[1], H[2], H[3]);
        *(uint4*)(d + O_AL) = make_uint4(L[0], L[1], L[2], L[3]);
    }
}

__global__ __launch_bounds__(256, 2)
void gemm_mma_kernel(const float* __restrict__ Pf,
                     const float* __restrict__ Qf,
                     const __nv_bfloat16* __restrict__ Bh,
                     const __nv_bfloat16* __restrict__ Bl,
                     const float* __restrict__ bias,
                     __nv_bfloat16* __restrict__ Ph_out,
                     __nv_bfloat16* __restrict__ Pl_out,
                     __nv_bfloat16* __restrict__ Qh_out,
                     __nv_bfloat16* __restrict__ Ql_out) {
    extern __shared__ char smem[];
    uint32_t sb = smem_u32(smem);
    const uint32_t f32b = sb + F32_OFF;
    float* bias_s = (float*)(smem + BIAS_OFF);

    const int tid  = threadIdx.x;
    const int w    = tid >> 5;
    const int lane = tid & 31;
    const int wm   = w >> 2;
    const int wn   = w & 3;
    const int yb   = blockIdx.y;
    const bool isQ = (yb >= YP);
    const size_t mBase = (size_t)(isQ ? yb - YP : yb) * 128;
    const int    nBase = blockIdx.x * 128;

    if (tid < 128) bias_s[tid] = bias[nBase + tid];

    const float* Af = (isQ ? Qf : Pf) + mBase * DHID;
    const __nv_bfloat16* B_h = Bh + (size_t)nBase * DHID;
    const __nv_bfloat16* B_l = Bl + (size_t)nBase * DHID;
    __nv_bfloat16* Ch = isQ ? Qh_out : Ph_out;
    __nv_bfloat16* Cl = isQ ? Ql_out : Pl_out;

    const int j  = lane >> 3;
    const int rj = lane & 7;
    uint32_t aoff[4], boff[2];
#pragma unroll
    for (int mi = 0; mi < 4; ++mi)
        aoff[mi] = (uint32_t)((wm * 64 + mi * 16 + (j & 1) * 8 + rj) * GP_B + (j >> 1) * 16);
#pragma unroll
    for (int p = 0; p < 2; ++p)
        boff[p] = (uint32_t)((wn * 32 + p * 16 + (j >> 1) * 8 + rj) * GP_B + (j & 1) * 16);

    float acc[4][4][4];
#pragma unroll
    for (int mi = 0; mi < 4; ++mi)
#pragma unroll
        for (int ni = 0; ni < 4; ++ni)
#pragma unroll
            for (int r = 0; r < 4; ++r) acc[mi][ni][r] = 0.0f;

    // prologue: A32(0)+B(0) -> convert stage0 -> A32(1) staged
    loadA32(f32b, Af, 0, tid);
    load_stageB(sb + 0 * STAGE_B, 0, tid, B_h, B_l);
    CP_COMMIT();
    CP_WAIT0();
    __syncthreads();
    convertA(smem + F32_OFF, smem + 0 * STAGE_B, tid);
    __syncthreads();
    loadA32(f32b, Af, 32, tid);
    CP_COMMIT();
    CP_WAIT0();
    __syncthreads();
    // invariant entering t: stage[t&1] ready; f32buf holds A32(t+1), arrived.

    for (int t = 0; t < NCHUNK; ++t) {
        if (t + 1 < NCHUNK)
            convertA(smem + F32_OFF, smem + (size_t)((t + 1) & 1) * STAGE_B, tid);
        __syncthreads();               // convert visible; f32buf free
        if (t + 2 < NCHUNK) loadA32(f32b, Af, (t + 2) * 32, tid);
        if (t + 1 < NCHUNK) load_stageB(sb + (uint32_t)((t + 1) & 1) * STAGE_B,
                                        (t + 1) * 32, tid, B_h, B_l);
        CP_COMMIT();
        mma_chunk(sb + (uint32_t)(t & 1) * STAGE_B, aoff, boff, acc);
        CP_WAIT0();
        __syncthreads();
    }

    // epilogue: bias + relu, split hi/lo bf16 store
    const int rGrp = lane >> 2;
    const int cGrp = (lane & 3) * 2;
#pragma unroll
    for (int mi = 0; mi < 4; ++mi) {
        size_t gr = mBase + wm * 64 + mi * 16 + rGrp;
#pragma unroll
        for (int ni = 0; ni < 4; ++ni) {
            int lc = wn * 32 + ni * 8 + cGrp;
            float b0 = bias_s[lc], b1 = bias_s[lc + 1];
            float v0 = fmaxf(acc[mi][ni][0] + b0, 0.0f);
            float v1 = fmaxf(acc[mi][ni][1] + b1, 0.0f);
            float v2 = fmaxf(acc[mi][ni][2] + b0, 0.0f);
            float v3 = fmaxf(acc[mi][ni][3] + b1, 0.0f);
            __nv_bfloat16 h0, h1, h2, h3, l0, l1, l2, l3;
            split2(v0, h0, l0); split2(v1, h1, l1);
            split2(v2, h2, l2); split2(v3, h3, l3);
            size_t o0 = gr * DHID + nBase + lc;
            size_t o1 = (gr + 8) * DHID + nBase + lc;
            *(__nv_bfloat162*)(Ch + o0) = __nv_bfloat162(h0, h1);
            *(__nv_bfloat162*)(Cl + o0) = __nv_bfloat162(l0, l1);
            *(__nv_bfloat162*)(Ch + o1) = __nv_bfloat162(h2, h3);
            *(__nv_bfloat162*)(Cl + o1) = __nv_bfloat162(l2, l3);
        }
    }
}

// ---------------- tensor-core fused attention: 2 CTAs/SM ---------------------
// phase 1 is double-buffered: stage0 at offset 0, stage1 ALIASES the alpha
// region (dead during phase 1). Alpha writes happen only after phase-2 syncs.
#define AH_OFF   40960
#define AL_OFF   75776
#define AP_B     272
#define QB_OFF   110592
#define RED_OFF  111104
#define ASMEM    113152
#define QP_B     144

__global__ __launch_bounds__(256, 2)
void attn_tc_kernel(const __nv_bfloat16* __restrict__ Wph,
                    const __nv_bfloat16* __restrict__ Wpl,
                    const __nv_bfloat16* __restrict__ Wqh,
                    const __nv_bfloat16* __restrict__ Wql,
                    const __nv_bfloat16* __restrict__ Qh,
                    const __nv_bfloat16* __restrict__ Ql,
                    float* __restrict__ out) {
    extern __shared__ char smem[];
    uint32_t sb = smem_u32(smem);
    float* qb  = (float*)(smem + QB_OFF);
    float* red = (float*)(smem + RED_OFF);

    const int tid  = threadIdx.x;
    const int w    = tid >> 5;
    const int lane = tid & 31;
    const int wm   = w >> 2;
    const int wn   = w & 3;
    const int b    = blockIdx.y;
    const int pBase = blockIdx.x * 128;

    if (tid < 128) qb[tid] = g_qbias[b * NLQ + tid];

    const __nv_bfloat16* A_h = Wph + ((size_t)b * NLP + pBase) * DHID;
    const __nv_bfloat16* A_l = Wpl + ((size_t)b * NLP + pBase) * DHID;
    const __nv_bfloat16* B_h = Wqh + (size_t)b * NLQ * DHID;
    const __nv_bfloat16* B_l = Wql + (size_t)b * NLQ * DHID;
    const __nv_bfloat16* Q_h = Qh + (size_t)b * NLQ * DHID;
    const __nv_bfloat16* Q_l = Ql + (size_t)b * NLQ * DHID;

    const int j  = lane >> 3;
    const int rj = lane & 7;
    const int rGrp = lane >> 2;
    const int cGrp = (lane & 3) * 2;

    // ---- phase 1: scores = Wp @ Wq^T, 2-stage (stage1 aliases alpha region) ----
    float acc[4][4][4];
#pragma unroll
    for (int mi = 0; mi < 4; ++mi)
#pragma unroll
        for (int ni = 0; ni < 4; ++ni)
#pragma unroll
            for (int r = 0; r < 4; ++r) acc[mi][ni][r] = 0.0f;
    {
        uint32_t aoff[4], boff[2];
#pragma unroll
        for (int mi = 0; mi < 4; ++mi)
            aoff[mi] = (uint32_t)((wm * 64 + mi * 16 + (j & 1) * 8 + rj) * GP_B + (j >> 1) * 16);
#pragma unroll
        for (int p = 0; p < 2; ++p)
            boff[p] = (uint32_t)((wn * 32 + p * 16 + (j >> 1) * 8 + rj) * GP_B + (j & 1) * 16);

        load_stage(sb, 0, tid, A_h, A_l, B_h, B_l);
        CP_COMMIT();
        for (int t = 0; t < NCHUNK; ++t) {
            CP_WAIT0();
            __syncthreads();
            if (t + 1 < NCHUNK) {
                load_stage(sb + (uint32_t)(((t + 1) & 1) ? AH_OFF : 0),
                           (t + 1) * 32, tid, A_h, A_l, B_h, B_l);
                CP_COMMIT();
            }
            mma_chunk(sb + (uint32_t)((t & 1) ? AH_OFF : 0), aoff, boff, acc);
        }
    }

    // ---- phase 2: mask bias + softmax in registers ----
    {
#pragma unroll
        for (int mi = 0; mi < 4; ++mi)
#pragma unroll
            for (int ni = 0; ni < 4; ++ni) {
                int q0 = wn * 32 + ni * 8 + cGrp;
                float b0 = qb[q0], b1 = qb[q0 + 1];
                acc[mi][ni][0] += b0; acc[mi][ni][1] += b1;
                acc[mi][ni][2] += b0; acc[mi][ni][3] += b1;
            }

        float mrow[4][2];
#pragma unroll
        for (int mi = 0; mi < 4; ++mi) {
            mrow[mi][0] = -INFINITY; mrow[mi][1] = -INFINITY;
#pragma unroll
            for (int ni = 0; ni < 4; ++ni) {
                mrow[mi][0] = fmaxf(mrow[mi][0], fmaxf(acc[mi][ni][0], acc[mi][ni][1]));
                mrow[mi][1] = fmaxf(mrow[mi][1], fmaxf(acc[mi][ni][2], acc[mi][ni][3]));
            }
        }
#pragma unroll
        for (int o = 1; o <= 2; o <<= 1)
#pragma unroll
            for (int mi = 0; mi < 4; ++mi) {
                mrow[mi][0] = fmaxf(mrow[mi][0], __shfl_xor_sync(0xFFFFFFFFu, mrow[mi][0], o));
                mrow[mi][1] = fmaxf(mrow[mi][1], __shfl_xor_sync(0xFFFFFFFFu, mrow[mi][1], o));
            }
        if ((lane & 3) == 0)
#pragma unroll
            for (int mi = 0; mi < 4; ++mi) {
                red[(wm * 64 + mi * 16 + rGrp) * 4 + wn]     = mrow[mi][0];
                red[(wm * 64 + mi * 16 + rGrp + 8) * 4 + wn] = mrow[mi][1];
            }
        __syncthreads();
        float M[4][2];
#pragma unroll
        for (int mi = 0; mi < 4; ++mi)
#pragma unroll
            for (int h = 0; h < 2; ++h) {
                const float* rr = &red[(wm * 64 + mi * 16 + rGrp + h * 8) * 4];
                M[mi][h] = fmaxf(fmaxf(rr[0], rr[1]), fmaxf(rr[2], rr[3]));
            }
        __syncthreads();

        float srow[4][2];
#pragma unroll
        for (int mi = 0; mi < 4; ++mi) { srow[mi][0] = 0.0f; srow[mi][1] = 0.0f; }
#pragma unroll
        for (int mi = 0; mi < 4; ++mi)
#pragma unroll
            for (int ni = 0; ni < 4; ++ni) {
                float e0 = __expf(acc[mi][ni][0] - M[mi][0]);
                float e1 = __expf(acc[mi][ni][1] - M[mi][0]);
                float e2 = __expf(acc[mi][ni][2] - M[mi][1]);
                float e3 = __expf(acc[mi][ni][3] - M[mi][1]);
                acc[mi][ni][0] = e0; acc[mi][ni][1] = e1;
                acc[mi][ni][2] = e2; acc[mi][ni][3] = e3;
                srow[mi][0] += e0 + e1;
                srow[mi][1] += e2 + e3;
            }
#pragma unroll
        for (int o = 1; o <= 2; o <<= 1)
#pragma unroll
            for (int mi = 0; mi < 4; ++mi) {
                srow[mi][0] += __shfl_xor_sync(0xFFFFFFFFu, srow[mi][0], o);
                srow[mi][1] += __shfl_xor_sync(0xFFFFFFFFu, srow[mi][1], o);
            }
        if ((lane & 3) == 0)
#pragma unroll
            for (int mi = 0; mi < 4; ++mi) {
                red[(wm * 64 + mi * 16 + rGrp) * 4 + wn]     = srow[mi][0];
                red[(wm * 64 + mi * 16 + rGrp + 8) * 4 + wn] = srow[mi][1];
            }
        __syncthreads();
        float INV[4][2];
#pragma unroll
        for (int mi = 0; mi < 4; ++mi)
#pragma unroll
            for (int h = 0; h < 2; ++h) {
                const float* rr = &red[(wm * 64 + mi * 16 + rGrp + h * 8) * 4];
                INV[mi][h] = 1.0f / (rr[0] + rr[1] + rr[2] + rr[3]);
            }

#pragma unroll
        for (int mi = 0; mi < 4; ++mi) {
            int pr = wm * 64 + mi * 16 + rGrp;
#pragma unroll
            for (int ni = 0; ni < 4; ++ni) {
                int q0 = wn * 32 + ni * 8 + cGrp;
                float a0 = acc[mi][ni][0] * INV[mi][0];
                float a1 = acc[mi][ni][1] * INV[mi][0];
                float a2 = acc[mi][ni][2] * INV[mi][1];
                float a3 = acc[mi][ni][3] * INV[mi][1];
                __nv_bfloat16 h0, h1, h2, h3, l0, l1, l2, l3;
                split2(a0, h0, l0); split2(a1, h1, l1);
                split2(a2, h2, l2); split2(a3, h3, l3);
                *(__nv_bfloat162*)(smem + AH_OFF + pr * AP_B + q0 * 2)       = __nv_bfloat162(h0, h1);
                *(__nv_bfloat162*)(smem + AL_OFF + pr * AP_B + q0 * 2)       = __nv_bfloat162(l0, l1);
                *(__nv_bfloat162*)(smem + AH_OFF + (pr + 8) * AP_B + q0 * 2) = __nv_bfloat162(h2, h3);
                *(__nv_bfloat162*)(smem + AL_OFF + (pr + 8) * AP_B + q0 * 2) = __nv_bfloat162(l2, l3);
            }
        }
    }
    __syncthreads();

    // ---- phase 3: out = alpha @ question; Q single-buffered in stage0 region ----
    {
        uint32_t aoff3[4];
#pragma unroll
        for (int mi = 0; mi < 4; ++mi)
            aoff3[mi] = (uint32_t)(AH_OFF + (wm * 64 + mi * 16 + (j & 1) * 8 + rj) * AP_B + (j >> 1) * 16);
        uint32_t boffq = (uint32_t)(((j & 1) * 8 + rj) * QP_B + wn * 32 + (j >> 1) * 16);
        const uint32_t dAL = AL_OFF - AH_OFF;

        for (int dc = 0; dc < 12; ++dc) {
            if (dc > 0) __syncthreads();
#pragma unroll
            for (int i = 0; i < 4; ++i) {
                int idx = tid + i * 256;
                int row = idx >> 3;
                int c   = idx & 7;
                uint32_t d = sb + (uint32_t)(row * QP_B + c * 16);
                size_t so = (size_t)row * DHID + dc * 64 + c * 8;
                cp16(d, Q_h + so);
                cp16(d + 18432, Q_l + so);
            }
            CP_COMMIT();
            CP_WAIT0();
            __syncthreads();

            float o3[4][2][4];
#pragma unroll
            for (int mi = 0; mi < 4; ++mi)
#pragma unroll
                for (int ni = 0; ni < 2; ++ni)
#pragma unroll
                    for (int r = 0; r < 4; ++r) o3[mi][ni][r] = 0.0f;

#pragma unroll
            for (int ks = 0; ks < 8; ++ks) {
                uint32_t ka = (uint32_t)ks * 32;
                uint32_t kq = (uint32_t)ks * 16 * QP_B;
                uint32_t ah[4][4], al[4][4];
#pragma unroll
                for (int mi = 0; mi < 4; ++mi)
                    ldsm4(ah[mi][0], ah[mi][1], ah[mi][2], ah[mi][3],
                          sb + aoff3[mi] + ka);
#pragma unroll
                for (int mi = 0; mi < 4; ++mi)
                    ldsm4(al[mi][0], al[mi][1], al[mi][2], al[mi][3],
                          sb + aoff3[mi] + dAL + ka);
                uint32_t bh[2][2], bl[2][2];
                {
                    uint32_t r0, r1, r2, r3;
                    ldsm4t(r0, r1, r2, r3, sb + boffq + kq);
                    bh[0][0] = r0; bh[0][1] = r1; bh[1][0] = r2; bh[1][1] = r3;
                    ldsm4t(r0, r1, r2, r3, sb + 18432 + boffq + kq);
                    bl[0][0] = r0; bl[0][1] = r1; bl[1][0] = r2; bl[1][1] = r3;
                }
#pragma unroll
                for (int mi = 0; mi < 4; ++mi)
#pragma unroll
                    for (int ni = 0; ni < 2; ++ni) {
                        mma16816(o3[mi][ni], ah[mi][0], ah[mi][1], ah[mi][2], ah[mi][3],
                                 bh[ni][0], bh[ni][1]);
                        mma16816(o3[mi][ni], al[mi][0], al[mi][1], al[mi][2], al[mi][3],
                                 bh[ni][0], bh[ni][1]);
                        mma16816(o3[mi][ni], ah[mi][0], ah[mi][1], ah[mi][2], ah[mi][3],
                                 bl[ni][0], bl[ni][1]);
                    }
            }

#pragma unroll
            for (int mi = 0; mi < 4; ++mi) {
                size_t gr = (size_t)b * NLP + pBase + wm * 64 + mi * 16 + rGrp;
#pragma unroll
                for (int ni = 0; ni < 2; ++ni) {
                    int d = dc * 64 + wn * 16 + ni * 8 + cGrp;
                    float2 v0 = {o3[mi][ni][0], o3[mi][ni][1]};
                    float2 v1 = {o3[mi][ni][2], o3[mi][ni][3]};
                    *(float2*)(out + gr * DHID + d)       = v0;
                    *(float2*)(out + (gr + 8) * DHID + d) = v1;
                }
            }
        }
    }
}

// ---------------------------------------------------------------------------
extern "C" void kernel_launch(void* const* d_in, const int* in_sizes, int n_in,
                              void* d_out, int out_size) {
    const float* passage  = (const float*)d_in[0];
    const float* question = (const float*)d_in[2];
    const unsigned char* qmask = (const unsigned char*)d_in[3];
    const float* Ww = (const float*)d_in[4];
    const float* Wb = (const float*)d_in[5];
    float* out = (float*)d_out;

    __nv_bfloat16 *qh, *ql, *wth, *wtl, *wph, *wpl, *wqh, *wql;
    cudaGetSymbolAddress((void**)&qh,  g_Qh);
    cudaGetSymbolAddress((void**)&ql,  g_Ql);
    cudaGetSymbolAddress((void**)&wth, g_Wth);
    cudaGetSymbolAddress((void**)&wtl, g_Wtl);
    cudaGetSymbolAddress((void**)&wph, g_Wph);
    cudaGetSymbolAddress((void**)&wpl, g_Wpl);
    cudaGetSymbolAddress((void**)&wqh, g_Wqh);
    cudaGetSymbolAddress((void**)&wql, g_Wql);

    mask_prep_kernel<<<1, 256>>>(qmask, NB * NLQ);

    int nq4 = NB * NLQ * DHID / 4;
    split_kernel<<<(nq4 + 255) / 256, 256>>>((const float4*)question,
                                             (__nv_bfloat162*)qh, (__nv_bfloat162*)ql, nq4);
    wsplit_kernel<<<dim3(DHID / 32, DHID / 32), dim3(32, 8)>>>(Ww, wth, wtl);

    cudaFuncSetAttribute(gemm_mma_kernel, cudaFuncAttributeMaxDynamicSharedMemorySize, GSMEM);
    gemm_mma_kernel<<<dim3(DHID / 128, YP + (NB * NLQ) / 128), 256, GSMEM>>>(
        passage, question, wth, wtl, Wb, wph, wpl, wqh, wql);

    cudaFuncSetAttribute(attn_tc_kernel, cudaFuncAttributeMaxDynamicSharedMemorySize, ASMEM);
    attn_tc_kernel<<<dim3(NLP / 128, NB), 256, ASMEM>>>(wph, wpl, wqh, wql, qh, ql, out);
}

// round 14
// speedup vs baseline: 3.0611x; 1.0291x over previous
#include <cuda_runtime.h>
#include <cuda_bf16.h>
#include <math.h>
#include <stdint.h>
#include <stddef.h>

#define DHID 768
#define NB   64
#define NLP  1024
#define NLQ  128

// ---------------- scratch (__device__ globals; allocation-free rule) --------
__device__ float g_qbias[NB * NLQ];
__device__ __align__(16) __nv_bfloat16 g_Qh[(size_t)NB * NLQ * DHID];
__device__ __align__(16) __nv_bfloat16 g_Ql[(size_t)NB * NLQ * DHID];
__device__ __align__(16) __nv_bfloat16 g_Wth[DHID * DHID];   // W^T hi [n][k]
__device__ __align__(16) __nv_bfloat16 g_Wtl[DHID * DHID];   // W^T lo [n][k]
__device__ __align__(16) __nv_bfloat16 g_Wph[(size_t)NB * NLP * DHID];
__device__ __align__(16) __nv_bfloat16 g_Wpl[(size_t)NB * NLP * DHID];
__device__ __align__(16) __nv_bfloat16 g_Wqh[(size_t)NB * NLQ * DHID];
__device__ __align__(16) __nv_bfloat16 g_Wql[(size_t)NB * NLQ * DHID];

// ---------------- small asm helpers ----------------------------------------
__device__ __forceinline__ uint32_t smem_u32(const void* p) {
    uint32_t a;
    asm("{ .reg .u64 t; cvta.to.shared.u64 t, %1; cvt.u32.u64 %0, t; }" : "=r"(a) : "l"(p));
    return a;
}
__device__ __forceinline__ void cp16(uint32_t dst, const void* src) {
    asm volatile("cp.async.cg.shared.global [%0], [%1], 16;" :: "r"(dst), "l"(src));
}
#define CP_COMMIT() asm volatile("cp.async.commit_group;" ::: "memory")
#define CP_WAIT0()  asm volatile("cp.async.wait_group 0;" ::: "memory")

__device__ __forceinline__ void ldsm4(uint32_t& r0, uint32_t& r1, uint32_t& r2,
                                      uint32_t& r3, uint32_t a) {
    asm volatile("ldmatrix.sync.aligned.m8n8.x4.shared.b16 {%0,%1,%2,%3}, [%4];"
                 : "=r"(r0), "=r"(r1), "=r"(r2), "=r"(r3) : "r"(a));
}
__device__ __forceinline__ void ldsm4t(uint32_t& r0, uint32_t& r1, uint32_t& r2,
                                       uint32_t& r3, uint32_t a) {
    asm volatile("ldmatrix.sync.aligned.m8n8.x4.trans.shared.b16 {%0,%1,%2,%3}, [%4];"
                 : "=r"(r0), "=r"(r1), "=r"(r2), "=r"(r3) : "r"(a));
}
__device__ __forceinline__ void mma16816(float* c, uint32_t a0, uint32_t a1,
                                         uint32_t a2, uint32_t a3,
                                         uint32_t b0, uint32_t b1) {
    asm volatile("mma.sync.aligned.m16n8k16.row.col.f32.bf16.bf16.f32 "
                 "{%0,%1,%2,%3}, {%4,%5,%6,%7}, {%8,%9}, {%0,%1,%2,%3};"
                 : "+f"(c[0]), "+f"(c[1]), "+f"(c[2]), "+f"(c[3])
                 : "r"(a0), "r"(a1), "r"(a2), "r"(a3), "r"(b0), "r"(b1));
}
__device__ __forceinline__ void split2(float v, __nv_bfloat16& h, __nv_bfloat16& l) {
    h = __float2bfloat16(v);
    l = __float2bfloat16(v - __bfloat162float(h));
}

// ---------------- mask prep (dtype-sniffing) --------------------------------
__global__ void mask_prep_kernel(const unsigned char* __restrict__ qm, int n) {
    __shared__ int mode;
    if (threadIdx.x == 0) mode = 0;
    __syncthreads();
    for (int i = threadIdx.x; i < n; i += blockDim.x) {
        int r = i & 3;
        unsigned char c = qm[i];
        if (r != 0 && c != 0) {
            if (r == 3 && c == 0x3F) atomicMax(&mode, 2);
            else                     atomicMax(&mode, 1);
        }
    }
    __syncthreads();
    int m = mode;
    for (int i = threadIdx.x; i < n; i += blockDim.x) {
        int v;
        if (m == 2)      v = (((const float*)(const void*)qm)[i] != 0.0f);
        else if (m == 1) v = (qm[i] != 0);
        else             v = (((const int*)(const void*)qm)[i] != 0);
        g_qbias[i] = v ? -1e30f : 0.0f;
    }
}

// ---------------- fp32 -> (hi,lo) bf16 split (question only, for attn) ------
__global__ void split_kernel(const float4* __restrict__ x,
                             __nv_bfloat162* __restrict__ h,
                             __nv_bfloat162* __restrict__ l, int n4) {
    int i = blockIdx.x * blockDim.x + threadIdx.x;
    if (i >= n4) return;
    float4 v = x[i];
    __nv_bfloat16 h0, h1, h2, h3, l0, l1, l2, l3;
    split2(v.x, h0, l0); split2(v.y, h1, l1);
    split2(v.z, h2, l2); split2(v.w, h3, l3);
    h[i * 2]     = __nv_bfloat162(h0, h1);
    h[i * 2 + 1] = __nv_bfloat162(h2, h3);
    l[i * 2]     = __nv_bfloat162(l0, l1);
    l[i * 2 + 1] = __nv_bfloat162(l2, l3);
}

// ---------------- W[k][n] -> W^T split (hi/lo) ------------------------------
__global__ void wsplit_kernel(const float* __restrict__ W,
                              __nv_bfloat16* __restrict__ Wth,
                              __nv_bfloat16* __restrict__ Wtl) {
    __shared__ float t[32][33];
    int bx = blockIdx.x * 32;  // k
    int by = blockIdx.y * 32;  // n
    for (int yy = threadIdx.y; yy < 32; yy += 8)
        t[yy][threadIdx.x] = W[(size_t)(bx + yy) * DHID + by + threadIdx.x];
    __syncthreads();
    for (int yy = threadIdx.y; yy < 32; yy += 8) {
        float v = t[threadIdx.x][yy];
        __nv_bfloat16 h, l;
        split2(v, h, l);
        size_t o = (size_t)(by + yy) * DHID + bx + threadIdx.x;
        Wth[o] = h;
        Wtl[o] = l;
    }
}

// ---------------- common tiling constants -----------------------------------
#define GP_B      80
#define ARR_B     (128 * GP_B)
#define O_AH      0
#define O_AL      (1 * ARR_B)
#define O_BH      (2 * ARR_B)
#define O_BL      (3 * ARR_B)
#define STAGE_B   (4 * ARR_B)         // 40960
#define NCHUNK    (DHID / 32)         // 24

// B hi/lo loader (cp.async) into the standard stage layout
__device__ __forceinline__ void load_stageB(uint32_t dst, int kc, int tid,
                                            const __nv_bfloat16* __restrict__ B_h,
                                            const __nv_bfloat16* __restrict__ B_l) {
#pragma unroll
    for (int i = 0; i < 2; ++i) {
        int idx = tid + i * 256;
        int row = idx >> 2;
        int c   = idx & 3;
        uint32_t d = dst + (uint32_t)(row * GP_B + c * 16);
        size_t so = (size_t)row * DHID + kc + c * 8;
        cp16(d + O_BH, B_h + so);
        cp16(d + O_BL, B_l + so);
    }
}

// full hi/lo loader (A+B) — used by the attention kernel
__device__ __forceinline__ void load_stage(uint32_t dst, int kc, int tid,
                                           const __nv_bfloat16* __restrict__ A_h,
                                           const __nv_bfloat16* __restrict__ A_l,
                                           const __nv_bfloat16* __restrict__ B_h,
                                           const __nv_bfloat16* __restrict__ B_l) {
#pragma unroll
    for (int i = 0; i < 2; ++i) {
        int idx = tid + i * 256;
        int row = idx >> 2;
        int c   = idx & 3;
        uint32_t d = dst + (uint32_t)(row * GP_B + c * 16);
        size_t so = (size_t)row * DHID + kc + c * 8;
        cp16(d + O_AH, A_h + so);
        cp16(d + O_AL, A_l + so);
        cp16(d + O_BH, B_h + so);
        cp16(d + O_BL, B_l + so);
    }
}

// 3-product split-bf16 mainloop chunk (2 k16 steps)
__device__ __forceinline__ void mma_chunk(uint32_t st, const uint32_t* aoff,
                                          const uint32_t* boff, float acc[4][4][4]) {
#pragma unroll
    for (int ks = 0; ks < 2; ++ks) {
        uint32_t k2 = (uint32_t)ks * 32;
        uint32_t ah[4][4], al[4][4], bh[4][2], bl[4][2];
#pragma unroll
        for (int mi = 0; mi < 4; ++mi)
            ldsm4(ah[mi][0], ah[mi][1], ah[mi][2], ah[mi][3], st + O_AH + aoff[mi] + k2);
#pragma unroll
        for (int mi = 0; mi < 4; ++mi)
            ldsm4(al[mi][0], al[mi][1], al[mi][2], al[mi][3], st + O_AL + aoff[mi] + k2);
#pragma unroll
        for (int p = 0; p < 2; ++p) {
            uint32_t r0, r1, r2, r3;
            ldsm4(r0, r1, r2, r3, st + O_BH + boff[p] + k2);
            bh[p * 2][0] = r0; bh[p * 2][1] = r1;
            bh[p * 2 + 1][0] = r2; bh[p * 2 + 1][1] = r3;
            ldsm4(r0, r1, r2, r3, st + O_BL + boff[p] + k2);
            bl[p * 2][0] = r0; bl[p * 2][1] = r1;
            bl[p * 2 + 1][0] = r2; bl[p * 2 + 1][1] = r3;
        }
#pragma unroll
        for (int mi = 0; mi < 4; ++mi)
#pragma unroll
            for (int ni = 0; ni < 4; ++ni) {
                mma16816(acc[mi][ni], ah[mi][0], ah[mi][1], ah[mi][2], ah[mi][3],
                         bh[ni][0], bh[ni][1]);
                mma16816(acc[mi][ni], al[mi][0], al[mi][1], al[mi][2], al[mi][3],
                         bh[ni][0], bh[ni][1]);
                mma16816(acc[mi][ni], ah[mi][0], ah[mi][1], ah[mi][2], ah[mi][3],
                         bl[ni][0], bl[ni][1]);
            }
    }
}

// ---------------- projection GEMM: direct-LDG A split, 2-stage, 2 CTAs/SM ---
// A (passage/question fp32) read via LDG.128 (L2-resident), converted in
// registers, STS'd into the hi/lo stage layout. One __syncthreads per chunk.
#define BIAS_OFF  (2 * STAGE_B)       // 81920
#define GSMEM     (BIAS_OFF + 512)    // 82432
#define YP        ((NB * NLP) / 128)  // 512 P row-blocks

__device__ __forceinline__ void convertA_g(const float* __restrict__ Af, int kc,
                                           char* stage, int tid) {
#pragma unroll
    for (int i = 0; i < 2; ++i) {
        int idx = tid + i * 256;          // 0..511 output 16B-hi units
        int row = idx >> 2;
        int c   = idx & 3;                // 32B fp32 -> 16B hi + 16B lo
        const float4* s = (const float4*)(Af + (size_t)row * DHID + kc + c * 8);
        float4 v0 = s[0], v1 = s[1];
        float f[8] = {v0.x, v0.y, v0.z, v0.w, v1.x, v1.y, v1.z, v1.w};
        uint32_t H[4], L[4];
#pragma unroll
        for (int q = 0; q < 4; ++q) {
            __nv_bfloat16 h0, l0, h1, l1;
            split2(f[2 * q],     h0, l0);
            split2(f[2 * q + 1], h1, l1);
            __nv_bfloat162 ph(h0, h1), pl(l0, l1);
            H[q] = *reinterpret_cast<uint32_t*>(&ph);
            L[q] = *reinterpret_cast<uint32_t*>(&pl);
        }
        char* d = stage + row * GP_B + c * 16;
        *(uint4*)(d + O_AH) = make_uint4(H[0], H[1], H[2], H[3]);
        *(uint4*)(d + O_AL) = make_uint4(L[0], L[1], L[2], L[3]);
    }
}

__global__ __launch_bounds__(256, 2)
void gemm_mma_kernel(const float* __restrict__ Pf,
                     const float* __restrict__ Qf,
                     const __nv_bfloat16* __restrict__ Bh,
                     const __nv_bfloat16* __restrict__ Bl,
                     const float* __restrict__ bias,
                     __nv_bfloat16* __restrict__ Ph_out,
                     __nv_bfloat16* __restrict__ Pl_out,
                     __nv_bfloat16* __restrict__ Qh_out,
                     __nv_bfloat16* __restrict__ Ql_out) {
    extern __shared__ char smem[];
    uint32_t sb = smem_u32(smem);
    float* bias_s = (float*)(smem + BIAS_OFF);

    const int tid  = threadIdx.x;
    const int w    = tid >> 5;
    const int lane = tid & 31;
    const int wm   = w >> 2;
    const int wn   = w & 3;
    const int yb   = blockIdx.y;
    const bool isQ = (yb >= YP);
    const size_t mBase = (size_t)(isQ ? yb - YP : yb) * 128;
    const int    nBase = blockIdx.x * 128;

    if (tid < 128) bias_s[tid] = bias[nBase + tid];

    const float* Af = (isQ ? Qf : Pf) + mBase * DHID;
    const __nv_bfloat16* B_h = Bh + (size_t)nBase * DHID;
    const __nv_bfloat16* B_l = Bl + (size_t)nBase * DHID;
    __nv_bfloat16* Ch = isQ ? Qh_out : Ph_out;
    __nv_bfloat16* Cl = isQ ? Ql_out : Pl_out;

    const int j  = lane >> 3;
    const int rj = lane & 7;
    uint32_t aoff[4], boff[2];
#pragma unroll
    for (int mi = 0; mi < 4; ++mi)
        aoff[mi] = (uint32_t)((wm * 64 + mi * 16 + (j & 1) * 8 + rj) * GP_B + (j >> 1) * 16);
#pragma unroll
    for (int p = 0; p < 2; ++p)
        boff[p] = (uint32_t)((wn * 32 + p * 16 + (j >> 1) * 8 + rj) * GP_B + (j & 1) * 16);

    float acc[4][4][4];
#pragma unroll
    for (int mi = 0; mi < 4; ++mi)
#pragma unroll
        for (int ni = 0; ni < 4; ++ni)
#pragma unroll
            for (int r = 0; r < 4; ++r) acc[mi][ni][r] = 0.0f;

    // prologue: B(0) async + A(0) direct-convert into stage0
    load_stageB(sb + 0 * STAGE_B, 0, tid, B_h, B_l);
    CP_COMMIT();
    convertA_g(Af, 0, smem + 0 * STAGE_B, tid);
    CP_WAIT0();
    __syncthreads();
    // invariant entering t: stage[t&1] fully ready (A converted, B arrived).

    for (int t = 0; t < NCHUNK; ++t) {
        if (t + 1 < NCHUNK) {
            load_stageB(sb + (uint32_t)((t + 1) & 1) * STAGE_B, (t + 1) * 32, tid,
                        B_h, B_l);
            CP_COMMIT();
            convertA_g(Af, (t + 1) * 32,
                       smem + (size_t)((t + 1) & 1) * STAGE_B, tid);
        }
        mma_chunk(sb + (uint32_t)(t & 1) * STAGE_B, aoff, boff, acc);
        CP_WAIT0();
        __syncthreads();
    }

    // epilogue: bias + relu, split hi/lo bf16 store
    const int rGrp = lane >> 2;
    const int cGrp = (lane & 3) * 2;
#pragma unroll
    for (int mi = 0; mi < 4; ++mi) {
        size_t gr = mBase + wm * 64 + mi * 16 + rGrp;
#pragma unroll
        for (int ni = 0; ni < 4; ++ni) {
            int lc = wn * 32 + ni * 8 + cGrp;
            float b0 = bias_s[lc], b1 = bias_s[lc + 1];
            float v0 = fmaxf(acc[mi][ni][0] + b0, 0.0f);
            float v1 = fmaxf(acc[mi][ni][1] + b1, 0.0f);
            float v2 = fmaxf(acc[mi][ni][2] + b0, 0.0f);
            float v3 = fmaxf(acc[mi][ni][3] + b1, 0.0f);
            __nv_bfloat16 h0, h1, h2, h3, l0, l1, l2, l3;
            split2(v0, h0, l0); split2(v1, h1, l1);
            split2(v2, h2, l2); split2(v3, h3, l3);
            size_t o0 = gr * DHID + nBase + lc;
            size_t o1 = (gr + 8) * DHID + nBase + lc;
            *(__nv_bfloat162*)(Ch + o0) = __nv_bfloat162(h0, h1);
            *(__nv_bfloat162*)(Cl + o0) = __nv_bfloat162(l0, l1);
            *(__nv_bfloat162*)(Ch + o1) = __nv_bfloat162(h2, h3);
            *(__nv_bfloat162*)(Cl + o1) = __nv_bfloat162(l2, l3);
        }
    }
}

// ---------------- tensor-core fused attention: 2 CTAs/SM ---------------------
// phase 1 double-buffered: stage0 at offset 0, stage1 aliases the alpha region
// (dead during phase 1; alpha writes only after phase-2 syncs).
#define AH_OFF   40960
#define AL_OFF   75776
#define AP_B     272
#define QB_OFF   110592
#define RED_OFF  111104
#define ASMEM    113152
#define QP_B     144

__global__ __launch_bounds__(256, 2)
void attn_tc_kernel(const __nv_bfloat16* __restrict__ Wph,
                    const __nv_bfloat16* __restrict__ Wpl,
                    const __nv_bfloat16* __restrict__ Wqh,
                    const __nv_bfloat16* __restrict__ Wql,
                    const __nv_bfloat16* __restrict__ Qh,
                    const __nv_bfloat16* __restrict__ Ql,
                    float* __restrict__ out) {
    extern __shared__ char smem[];
    uint32_t sb = smem_u32(smem);
    float* qb  = (float*)(smem + QB_OFF);
    float* red = (float*)(smem + RED_OFF);

    const int tid  = threadIdx.x;
    const int w    = tid >> 5;
    const int lane = tid & 31;
    const int wm   = w >> 2;
    const int wn   = w & 3;
    const int b    = blockIdx.y;
    const int pBase = blockIdx.x * 128;

    if (tid < 128) qb[tid] = g_qbias[b * NLQ + tid];

    const __nv_bfloat16* A_h = Wph + ((size_t)b * NLP + pBase) * DHID;
    const __nv_bfloat16* A_l = Wpl + ((size_t)b * NLP + pBase) * DHID;
    const __nv_bfloat16* B_h = Wqh + (size_t)b * NLQ * DHID;
    const __nv_bfloat16* B_l = Wql + (size_t)b * NLQ * DHID;
    const __nv_bfloat16* Q_h = Qh + (size_t)b * NLQ * DHID;
    const __nv_bfloat16* Q_l = Ql + (size_t)b * NLQ * DHID;

    const int j  = lane >> 3;
    const int rj = lane & 7;
    const int rGrp = lane >> 2;
    const int cGrp = (lane & 3) * 2;

    // ---- phase 1: scores = Wp @ Wq^T, 2-stage (stage1 aliases alpha region) ----
    float acc[4][4][4];
#pragma unroll
    for (int mi = 0; mi < 4; ++mi)
#pragma unroll
        for (int ni = 0; ni < 4; ++ni)
#pragma unroll
            for (int r = 0; r < 4; ++r) acc[mi][ni][r] = 0.0f;
    {
        uint32_t aoff[4], boff[2];
#pragma unroll
        for (int mi = 0; mi < 4; ++mi)
            aoff[mi] = (uint32_t)((wm * 64 + mi * 16 + (j & 1) * 8 + rj) * GP_B + (j >> 1) * 16);
#pragma unroll
        for (int p = 0; p < 2; ++p)
            boff[p] = (uint32_t)((wn * 32 + p * 16 + (j >> 1) * 8 + rj) * GP_B + (j & 1) * 16);

        load_stage(sb, 0, tid, A_h, A_l, B_h, B_l);
        CP_COMMIT();
        for (int t = 0; t < NCHUNK; ++t) {
            CP_WAIT0();
            __syncthreads();
            if (t + 1 < NCHUNK) {
                load_stage(sb + (uint32_t)(((t + 1) & 1) ? AH_OFF : 0),
                           (t + 1) * 32, tid, A_h, A_l, B_h, B_l);
                CP_COMMIT();
            }
            mma_chunk(sb + (uint32_t)((t & 1) ? AH_OFF : 0), aoff, boff, acc);
        }
    }

    // ---- phase 2: mask bias + softmax in registers ----
    {
#pragma unroll
        for (int mi = 0; mi < 4; ++mi)
#pragma unroll
            for (int ni = 0; ni < 4; ++ni) {
                int q0 = wn * 32 + ni * 8 + cGrp;
                float b0 = qb[q0], b1 = qb[q0 + 1];
                acc[mi][ni][0] += b0; acc[mi][ni][1] += b1;
                acc[mi][ni][2] += b0; acc[mi][ni][3] += b1;
            }

        float mrow[4][2];
#pragma unroll
        for (int mi = 0; mi < 4; ++mi) {
            mrow[mi][0] = -INFINITY; mrow[mi][1] = -INFINITY;
#pragma unroll
            for (int ni = 0; ni < 4; ++ni) {
                mrow[mi][0] = fmaxf(mrow[mi][0], fmaxf(acc[mi][ni][0], acc[mi][ni][1]));
                mrow[mi][1] = fmaxf(mrow[mi][1], fmaxf(acc[mi][ni][2], acc[mi][ni][3]));
            }
        }
#pragma unroll
        for (int o = 1; o <= 2; o <<= 1)
#pragma unroll
            for (int mi = 0; mi < 4; ++mi) {
                mrow[mi][0] = fmaxf(mrow[mi][0], __shfl_xor_sync(0xFFFFFFFFu, mrow[mi][0], o));
                mrow[mi][1] = fmaxf(mrow[mi][1], __shfl_xor_sync(0xFFFFFFFFu, mrow[mi][1], o));
            }
        if ((lane & 3) == 0)
#pragma unroll
            for (int mi = 0; mi < 4; ++mi) {
                red[(wm * 64 + mi * 16 + rGrp) * 4 + wn]     = mrow[mi][0];
                red[(wm * 64 + mi * 16 + rGrp + 8) * 4 + wn] = mrow[mi][1];
            }
        __syncthreads();
        float M[4][2];
#pragma unroll
        for (int mi = 0; mi < 4; ++mi)
#pragma unroll
            for (int h = 0; h < 2; ++h) {
                const float* rr = &red[(wm * 64 + mi * 16 + rGrp + h * 8) * 4];
                M[mi][h] = fmaxf(fmaxf(rr[0], rr[1]), fmaxf(rr[2], rr[3]));
            }
        __syncthreads();

        float srow[4][2];
#pragma unroll
        for (int mi = 0; mi < 4; ++mi) { srow[mi][0] = 0.0f; srow[mi][1] = 0.0f; }
#pragma unroll
        for (int mi = 0; mi < 4; ++mi)
#pragma unroll
            for (int ni = 0; ni < 4; ++ni) {
                float e0 = __expf(acc[mi][ni][0] - M[mi][0]);
                float e1 = __expf(acc[mi][ni][1] - M[mi][0]);
                float e2 = __expf(acc[mi][ni][2] - M[mi][1]);
                float e3 = __expf(acc[mi][ni][3] - M[mi][1]);
                acc[mi][ni][0] = e0; acc[mi][ni][1] = e1;
                acc[mi][ni][2] = e2; acc[mi][ni][3] = e3;
                srow[mi][0] += e0 + e1;
                srow[mi][1] += e2 + e3;
            }
#pragma unroll
        for (int o = 1; o <= 2; o <<= 1)
#pragma unroll
            for (int mi = 0; mi < 4; ++mi) {
                srow[mi][0] += __shfl_xor_sync(0xFFFFFFFFu, srow[mi][0], o);
                srow[mi][1] += __shfl_xor_sync(0xFFFFFFFFu, srow[mi][1], o);
            }
        if ((lane & 3) == 0)
#pragma unroll
            for (int mi = 0; mi < 4; ++mi) {
                red[(wm * 64 + mi * 16 + rGrp) * 4 + wn]     = srow[mi][0];
                red[(wm * 64 + mi * 16 + rGrp + 8) * 4 + wn] = srow[mi][1];
            }
        __syncthreads();
        float INV[4][2];
#pragma unroll
        for (int mi = 0; mi < 4; ++mi)
#pragma unroll
            for (int h = 0; h < 2; ++h) {
                const float* rr = &red[(wm * 64 + mi * 16 + rGrp + h * 8) * 4];
                INV[mi][h] = 1.0f / (rr[0] + rr[1] + rr[2] + rr[3]);
            }

#pragma unroll
        for (int mi = 0; mi < 4; ++mi) {
            int pr = wm * 64 + mi * 16 + rGrp;
#pragma unroll
            for (int ni = 0; ni < 4; ++ni) {
                int q0 = wn * 32 + ni * 8 + cGrp;
                float a0 = acc[mi][ni][0] * INV[mi][0];
                float a1 = acc[mi][ni][1] * INV[mi][0];
                float a2 = acc[mi][ni][2] * INV[mi][1];
                float a3 = acc[mi][ni][3] * INV[mi][1];
                __nv_bfloat16 h0, h1, h2, h3, l0, l1, l2, l3;
                split2(a0, h0, l0); split2(a1, h1, l1);
                split2(a2, h2, l2); split2(a3, h3, l3);
                *(__nv_bfloat162*)(smem + AH_OFF + pr * AP_B + q0 * 2)       = __nv_bfloat162(h0, h1);
                *(__nv_bfloat162*)(smem + AL_OFF + pr * AP_B + q0 * 2)       = __nv_bfloat162(l0, l1);
                *(__nv_bfloat162*)(smem + AH_OFF + (pr + 8) * AP_B + q0 * 2) = __nv_bfloat162(h2, h3);
                *(__nv_bfloat162*)(smem + AL_OFF + (pr + 8) * AP_B + q0 * 2) = __nv_bfloat162(l2, l3);
            }
        }
    }
    __syncthreads();

    // ---- phase 3: out = alpha @ question; Q single-buffered in stage0 region ----
    {
        uint32_t aoff3[4];
#pragma unroll
        for (int mi = 0; mi < 4; ++mi)
            aoff3[mi] = (uint32_t)(AH_OFF + (wm * 64 + mi * 16 + (j & 1) * 8 + rj) * AP_B + (j >> 1) * 16);
        uint32_t boffq = (uint32_t)(((j & 1) * 8 + rj) * QP_B + wn * 32 + (j >> 1) * 16);
        const uint32_t dAL = AL_OFF - AH_OFF;

        for (int dc = 0; dc < 12; ++dc) {
            if (dc > 0) __syncthreads();
#pragma unroll
            for (int i = 0; i < 4; ++i) {
                int idx = tid + i * 256;
                int row = idx >> 3;
                int c   = idx & 7;
                uint32_t d = sb + (uint32_t)(row * QP_B + c * 16);
                size_t so = (size_t)row * DHID + dc * 64 + c * 8;
                cp16(d, Q_h + so);
                cp16(d + 18432, Q_l + so);
            }
            CP_COMMIT();
            CP_WAIT0();
            __syncthreads();

            float o3[4][2][4];
#pragma unroll
            for (int mi = 0; mi < 4; ++mi)
#pragma unroll
                for (int ni = 0; ni < 2; ++ni)
#pragma unroll
                    for (int r = 0; r < 4; ++r) o3[mi][ni][r] = 0.0f;

#pragma unroll
            for (int ks = 0; ks < 8; ++ks) {
                uint32_t ka = (uint32_t)ks * 32;
                uint32_t kq = (uint32_t)ks * 16 * QP_B;
                uint32_t ah[4][4], al[4][4];
#pragma unroll
                for (int mi = 0; mi < 4; ++mi)
                    ldsm4(ah[mi][0], ah[mi][1], ah[mi][2], ah[mi][3],
                          sb + aoff3[mi] + ka);
#pragma unroll
                for (int mi = 0; mi < 4; ++mi)
                    ldsm4(al[mi][0], al[mi][1], al[mi][2], al[mi][3],
                          sb + aoff3[mi] + dAL + ka);
                uint32_t bh[2][2], bl[2][2];
                {
                    uint32_t r0, r1, r2, r3;
                    ldsm4t(r0, r1, r2, r3, sb + boffq + kq);
                    bh[0][0] = r0; bh[0][1] = r1; bh[1][0] = r2; bh[1][1] = r3;
                    ldsm4t(r0, r1, r2, r3, sb + 18432 + boffq + kq);
                    bl[0][0] = r0; bl[0][1] = r1; bl[1][0] = r2; bl[1][1] = r3;
                }
#pragma unroll
                for (int mi = 0; mi < 4; ++mi)
#pragma unroll
                    for (int ni = 0; ni < 2; ++ni) {
                        mma16816(o3[mi][ni], ah[mi][0], ah[mi][1], ah[mi][2], ah[mi][3],
                                 bh[ni][0], bh[ni][1]);
                        mma16816(o3[mi][ni], al[mi][0], al[mi][1], al[mi][2], al[mi][3],
                                 bh[ni][0], bh[ni][1]);
                        mma16816(o3[mi][ni], ah[mi][0], ah[mi][1], ah[mi][2], ah[mi][3],
                                 bl[ni][0], bl[ni][1]);
                    }
            }

#pragma unroll
            for (int mi = 0; mi < 4; ++mi) {
                size_t gr = (size_t)b * NLP + pBase + wm * 64 + mi * 16 + rGrp;
#pragma unroll
                for (int ni = 0; ni < 2; ++ni) {
                    int d = dc * 64 + wn * 16 + ni * 8 + cGrp;
                    float2 v0 = {o3[mi][ni][0], o3[mi][ni][1]};
                    float2 v1 = {o3[mi][ni][2], o3[mi][ni][3]};
                    *(float2*)(out + gr * DHID + d)       = v0;
                    *(float2*)(out + (gr + 8) * DHID + d) = v1;
                }
            }
        }
    }
}

// ---------------------------------------------------------------------------
extern "C" void kernel_launch(void* const* d_in, const int* in_sizes, int n_in,
                              void* d_out, int out_size) {
    const float* passage  = (const float*)d_in[0];
    const float* question = (const float*)d_in[2];
    const unsigned char* qmask = (const unsigned char*)d_in[3];
    const float* Ww = (const float*)d_in[4];
    const float* Wb = (const float*)d_in[5];
    float* out = (float*)d_out;

    __nv_bfloat16 *qh, *ql, *wth, *wtl, *wph, *wpl, *wqh, *wql;
    cudaGetSymbolAddress((void**)&qh,  g_Qh);
    cudaGetSymbolAddress((void**)&ql,  g_Ql);
    cudaGetSymbolAddress((void**)&wth, g_Wth);
    cudaGetSymbolAddress((void**)&wtl, g_Wtl);
    cudaGetSymbolAddress((void**)&wph, g_Wph);
    cudaGetSymbolAddress((void**)&wpl, g_Wpl);
    cudaGetSymbolAddress((void**)&wqh, g_Wqh);
    cudaGetSymbolAddress((void**)&wql, g_Wql);

    mask_prep_kernel<<<1, 256>>>(qmask, NB * NLQ);

    int nq4 = NB * NLQ * DHID / 4;
    split_kernel<<<(nq4 + 255) / 256, 256>>>((const float4*)question,
                                             (__nv_bfloat162*)qh, (__nv_bfloat162*)ql, nq4);
    wsplit_kernel<<<dim3(DHID / 32, DHID / 32), dim3(32, 8)>>>(Ww, wth, wtl);

    cudaFuncSetAttribute(gemm_mma_kernel, cudaFuncAttributeMaxDynamicSharedMemorySize, GSMEM);
    gemm_mma_kernel<<<dim3(DHID / 128, YP + (NB * NLQ) / 128), 256, GSMEM>>>(
        passage, question, wth, wtl, Wb, wph, wpl, wqh, wql);

    cudaFuncSetAttribute(attn_tc_kernel, cudaFuncAttributeMaxDynamicSharedMemorySize, ASMEM);
    attn_tc_kernel<<<dim3(NLP / 128, NB), 256, ASMEM>>>(wph, wpl, wqh, wql, qh, ql, out);
}